// round 1
// baseline (speedup 1.0000x reference)
#include <cuda_runtime.h>
#include <cuda_bf16.h>

// Problem constants
#define BDIM 2      // batch
#define CH   512    // channels
#define CQ   64     // C/8 (q,k dim)
#define NN   4096   // h*w

// ---------------------------------------------------------------------------
// Scratch (allocation-free: __device__ globals)
// ---------------------------------------------------------------------------
__device__ float g_q   [BDIM * CQ * NN];            // 2 MB
__device__ float g_k   [BDIM * CQ * NN];            // 2 MB
__device__ float g_v   [BDIM * CH * NN];            // 16 MB
__device__ float g_att [(size_t)BDIM * NN * NN];    // 134 MB
__device__ float g_pos [BDIM * CH * NN];            // 16 MB
__device__ float g_gram[BDIM * CH * CH];            // 2 MB

// ---------------------------------------------------------------------------
// Generic tiled SGEMM: C = op(A) * op(B) [+ bias] [combine epilogue]
//   op(A)[m,k] = TA ? A[k*M + m] : A[m*K + k]
//   op(B)[k,n] = TB ? B[n*K + k] : B[k*N + n]
// BM=BN=128, BK=16, 256 threads, 8x8 per-thread micro-tile.
// COMBINE epilogue: C = c1*P + c2*acc + c3*X  (c1=alpha*gpos, c2=beta*gchan,
// c3=alpha+beta+1), scalars read from device pointers.
// ---------------------------------------------------------------------------
template <bool TA, bool TB, bool HAS_BIAS, bool COMBINE>
__global__ __launch_bounds__(256, 2)
void gemm_k(const float* __restrict__ A, const float* __restrict__ B,
            float* __restrict__ C, const float* __restrict__ bias,
            int M, int N, int K,
            long long sA, long long sB, long long sC,
            const float* __restrict__ P, const float* __restrict__ X,
            long long sPX,
            const float* __restrict__ s_alpha, const float* __restrict__ s_beta,
            const float* __restrict__ s_gpos, const float* __restrict__ s_gchan)
{
    constexpr int BM = 128, BN = 128, BK = 16;
    __shared__ float As[BK][BM];
    __shared__ float Bs[BK][BN];

    const int z = blockIdx.z;
    A += (long long)z * sA;
    B += (long long)z * sB;
    C += (long long)z * sC;

    const int m0 = blockIdx.y * BM;
    const int n0 = blockIdx.x * BN;
    const int tid = threadIdx.x;
    const int tx = tid & 15;        // 0..15 -> 8 output cols each
    const int ty = tid >> 4;        // 0..15 -> 8 output rows each

    float acc[8][8];
#pragma unroll
    for (int i = 0; i < 8; i++)
#pragma unroll
        for (int j = 0; j < 8; j++) acc[i][j] = 0.f;

    for (int k0 = 0; k0 < K; k0 += BK) {
        // ---- load A tile into As[kk][m] ----
#pragma unroll
        for (int r = 0; r < (BM * BK) / 256; r++) {
            int t = tid + r * 256;
            int m, kk;
            if (!TA) { kk = t & (BK - 1); m = t >> 4; }   // consecutive tid -> kk
            else     { m = t & (BM - 1); kk = t >> 7; }   // consecutive tid -> m (coalesced)
            int gm = m0 + m, gk = k0 + kk;
            float val = 0.f;
            if (gm < M && gk < K)
                val = TA ? A[(long long)gk * M + gm]
                         : A[(long long)gm * K + gk];
            As[kk][m] = val;
        }
        // ---- load B tile into Bs[kk][n] ----
#pragma unroll
        for (int r = 0; r < (BK * BN) / 256; r++) {
            int t = tid + r * 256;
            int n, kk;
            if (!TB) { n = t & (BN - 1); kk = t >> 7; }   // consecutive tid -> n (coalesced)
            else     { kk = t & (BK - 1); n = t >> 4; }   // consecutive tid -> kk
            int gn = n0 + n, gk = k0 + kk;
            float val = 0.f;
            if (gn < N && gk < K)
                val = TB ? B[(long long)gn * K + gk]
                         : B[(long long)gk * N + gn];
            Bs[kk][n] = val;
        }
        __syncthreads();

#pragma unroll
        for (int kk = 0; kk < BK; kk++) {
            float a[8], b[8];
            *(float4*)&a[0] = *(const float4*)&As[kk][ty * 8];
            *(float4*)&a[4] = *(const float4*)&As[kk][ty * 8 + 4];
            *(float4*)&b[0] = *(const float4*)&Bs[kk][tx * 8];
            *(float4*)&b[4] = *(const float4*)&Bs[kk][tx * 8 + 4];
#pragma unroll
            for (int i = 0; i < 8; i++)
#pragma unroll
                for (int j = 0; j < 8; j++)
                    acc[i][j] += a[i] * b[j];
        }
        __syncthreads();
    }

    float c1 = 0.f, c2 = 1.f, c3 = 0.f;
    if (COMBINE) {
        float al = *s_alpha, be = *s_beta;
        c1 = al * (*s_gpos);
        c2 = be * (*s_gchan);
        c3 = al + be + 1.f;
        P += (long long)z * sPX;
        X += (long long)z * sPX;
    }

#pragma unroll
    for (int i = 0; i < 8; i++) {
        int gm = m0 + ty * 8 + i;
        if (gm >= M) continue;
        float bval = HAS_BIAS ? bias[gm] : 0.f;
#pragma unroll
        for (int j = 0; j < 8; j++) {
            int gn = n0 + tx * 8 + j;
            if (gn >= N) continue;
            long long idx = (long long)gm * N + gn;
            float r = acc[i][j] + bval;
            if (COMBINE) r = c1 * P[idx] + c2 * r + c3 * X[idx];
            C[idx] = r;
        }
    }
}

// ---------------------------------------------------------------------------
// Row softmax over 4096-wide rows (position attention), in place.
// grid (NN, BDIM), 256 threads, 16 elems/thread.
// ---------------------------------------------------------------------------
__global__ __launch_bounds__(256)
void softmax_pos(float* __restrict__ att)
{
    float* p = att + ((long long)blockIdx.y * NN + blockIdx.x) * NN;
    const int tid = threadIdx.x;
    __shared__ float red[8];

    float v[16];
    float mx = -1e30f;
#pragma unroll
    for (int i = 0; i < 16; i++) {
        v[i] = p[tid + i * 256];
        mx = fmaxf(mx, v[i]);
    }
#pragma unroll
    for (int o = 16; o; o >>= 1) mx = fmaxf(mx, __shfl_xor_sync(0xffffffffu, mx, o));
    if ((tid & 31) == 0) red[tid >> 5] = mx;
    __syncthreads();
    mx = red[0];
#pragma unroll
    for (int i = 1; i < 8; i++) mx = fmaxf(mx, red[i]);

    float s = 0.f;
#pragma unroll
    for (int i = 0; i < 16; i++) {
        v[i] = expf(v[i] - mx);
        s += v[i];
    }
#pragma unroll
    for (int o = 16; o; o >>= 1) s += __shfl_xor_sync(0xffffffffu, s, o);
    __syncthreads();                 // red reuse
    if ((tid & 31) == 0) red[tid >> 5] = s;
    __syncthreads();
    s = 0.f;
#pragma unroll
    for (int i = 0; i < 8; i++) s += red[i];
    float inv = 1.f / s;
#pragma unroll
    for (int i = 0; i < 16; i++) p[tid + i * 256] = v[i] * inv;
}

// ---------------------------------------------------------------------------
// Channel softmax: att_c[i,j] = softmax_j( rowmax(G) - G[i,j] )
//                             = exp(rowmin(G) - G[i,j]) / sum_j exp(...)
// Row length 512, in place on gram. grid (CH, BDIM), 128 threads.
// ---------------------------------------------------------------------------
__global__ __launch_bounds__(128)
void softmax_chan(float* __restrict__ gram)
{
    float* p = gram + ((long long)blockIdx.y * CH + blockIdx.x) * CH;
    const int tid = threadIdx.x;
    __shared__ float red[4];

    float v[4];
    float mn = 1e30f;
#pragma unroll
    for (int i = 0; i < 4; i++) {
        v[i] = p[tid + i * 128];
        mn = fminf(mn, v[i]);
    }
#pragma unroll
    for (int o = 16; o; o >>= 1) mn = fminf(mn, __shfl_xor_sync(0xffffffffu, mn, o));
    if ((tid & 31) == 0) red[tid >> 5] = mn;
    __syncthreads();
    mn = fminf(fminf(red[0], red[1]), fminf(red[2], red[3]));

    float s = 0.f;
#pragma unroll
    for (int i = 0; i < 4; i++) {
        v[i] = expf(mn - v[i]);
        s += v[i];
    }
#pragma unroll
    for (int o = 16; o; o >>= 1) s += __shfl_xor_sync(0xffffffffu, s, o);
    __syncthreads();
    if ((tid & 31) == 0) red[tid >> 5] = s;
    __syncthreads();
    s = red[0] + red[1] + red[2] + red[3];
    float inv = 1.f / s;
#pragma unroll
    for (int i = 0; i < 4; i++) p[tid + i * 128] = v[i] * inv;
}

// ---------------------------------------------------------------------------
// Launcher
// ---------------------------------------------------------------------------
extern "C" void kernel_launch(void* const* d_in, const int* in_sizes, int n_in,
                              void* d_out, int out_size)
{
    const float* x  = (const float*)d_in[0];   // (2,512,64,64)
    const float* wq = (const float*)d_in[1];   // (64,512)
    const float* bq = (const float*)d_in[2];   // (64,)
    const float* wk = (const float*)d_in[3];
    const float* bk = (const float*)d_in[4];
    const float* wv = (const float*)d_in[5];   // (512,512)
    const float* bv = (const float*)d_in[6];
    const float* gp = (const float*)d_in[7];   // gamma_pos
    const float* gc = (const float*)d_in[8];   // gamma_chan
    const float* al = (const float*)d_in[9];   // alpha
    const float* be = (const float*)d_in[10];  // beta
    float* out = (float*)d_out;

    float *q, *k, *v, *att, *pos, *gram;
    cudaGetSymbolAddress((void**)&q,    g_q);
    cudaGetSymbolAddress((void**)&k,    g_k);
    cudaGetSymbolAddress((void**)&v,    g_v);
    cudaGetSymbolAddress((void**)&att,  g_att);
    cudaGetSymbolAddress((void**)&pos,  g_pos);
    cudaGetSymbolAddress((void**)&gram, g_gram);

    const long long sX   = (long long)CH * NN;      // batch stride of x / v / pos / out
    const long long sQK  = (long long)CQ * NN;
    const long long sAtt = (long long)NN * NN;
    const long long sGr  = (long long)CH * CH;

    dim3 blk(256);

    // q = wq @ x + bq   (64 x 4096, K=512)
    gemm_k<false, false, true, false><<<dim3(NN / 128, 1, BDIM), blk>>>(
        wq, x, q, bq, CQ, NN, CH, 0, sX, sQK,
        nullptr, nullptr, 0, nullptr, nullptr, nullptr, nullptr);
    // k = wk @ x + bk
    gemm_k<false, false, true, false><<<dim3(NN / 128, 1, BDIM), blk>>>(
        wk, x, k, bk, CQ, NN, CH, 0, sX, sQK,
        nullptr, nullptr, 0, nullptr, nullptr, nullptr, nullptr);
    // v = wv @ x + bv   (512 x 4096, K=512)
    gemm_k<false, false, true, false><<<dim3(NN / 128, CH / 128, BDIM), blk>>>(
        wv, x, v, bv, CH, NN, CH, 0, sX, sX,
        nullptr, nullptr, 0, nullptr, nullptr, nullptr, nullptr);

    // energy[i,j] = sum_d q[d,i] k[d,j]   (4096 x 4096, K=64; A transposed)
    gemm_k<true, false, false, false><<<dim3(NN / 128, NN / 128, BDIM), blk>>>(
        q, k, att, nullptr, NN, NN, CQ, sQK, sQK, sAtt,
        nullptr, nullptr, 0, nullptr, nullptr, nullptr, nullptr);

    // row softmax -> att
    softmax_pos<<<dim3(NN, BDIM), 256>>>(att);

    // pos[c,i] = sum_j v[c,j] att[i,j]   (512 x 4096, K=4096; B transposed)
    gemm_k<false, true, false, false><<<dim3(NN / 128, CH / 128, BDIM), blk>>>(
        v, att, pos, nullptr, CH, NN, NN, sX, sAtt, sX,
        nullptr, nullptr, 0, nullptr, nullptr, nullptr, nullptr);

    // gram[i,j] = sum_n x[i,n] x[j,n]   (512 x 512, K=4096; B transposed)
    gemm_k<false, true, false, false><<<dim3(CH / 128, CH / 128, BDIM), blk>>>(
        x, x, gram, nullptr, CH, CH, NN, sX, sX, sGr,
        nullptr, nullptr, 0, nullptr, nullptr, nullptr, nullptr);

    // channel softmax (max-trick) in place -> att_c
    softmax_chan<<<dim3(CH, BDIM), 128>>>(gram);

    // out = alpha*gp*pos + beta*gc*(att_c @ x) + (alpha+beta+1)*x
    gemm_k<false, false, false, true><<<dim3(NN / 128, CH / 128, BDIM), blk>>>(
        gram, x, out, nullptr, CH, NN, CH, sGr, sX, sX,
        pos, x, sX, al, be, gp, gc);
}

// round 6
// speedup vs baseline: 4.5184x; 4.5184x over previous
#include <cuda_runtime.h>
#include <cuda_bf16.h>
#include <cstdint>

// Problem constants
#define BDIM 2
#define CH   512
#define CQ   64
#define NN   4096

// ---------------------------------------------------------------------------
// Scratch (allocation-free __device__ globals), all fp32 (tf32-rounded where
// used as MMA operands). 256B-aligned for 16B cp.async chunks.
// Position softmax runs IN PLACE on g_energy (no separate att buffer).
// ---------------------------------------------------------------------------
__device__ __align__(256) float g_energy[(size_t)BDIM * NN * NN];   // 134 MB
__device__ __align__(256) float g_xb    [(size_t)BDIM * CH * NN];   // rounded, c-major
__device__ __align__(256) float g_xbt   [(size_t)BDIM * NN * CH];   // rounded, n-major
__device__ __align__(256) float g_vb    [(size_t)BDIM * CH * NN];
__device__ __align__(256) float g_qt    [(size_t)BDIM * NN * CQ];
__device__ __align__(256) float g_kt    [(size_t)BDIM * NN * CQ];
__device__ __align__(256) float g_pos   [(size_t)BDIM * CH * NN];
__device__ __align__(256) float g_gram  [(size_t)BDIM * CH * CH];
__device__ __align__(256) float g_wqr[CQ * CH];
__device__ __align__(256) float g_wkr[CQ * CH];
__device__ __align__(256) float g_wvr[CH * CH];

// ---------------------------------------------------------------------------
// PTX helpers (sm_80+ path: cp.async + mma.sync m16n8k8 tf32)
// ---------------------------------------------------------------------------
__device__ __forceinline__ uint32_t smem_u32(const void* p) {
    uint32_t a;
    asm("{ .reg .u64 t; cvta.to.shared.u64 t, %1; cvt.u32.u64 %0, t; }"
        : "=r"(a) : "l"(p));
    return a;
}

__device__ __forceinline__ float tf32r(float x) {
    uint32_t u;
    asm("cvt.rna.tf32.f32 %0, %1;" : "=r"(u) : "f"(x));
    return __uint_as_float(u);
}

#define CP_ASYNC16(dst, src, sz) \
    asm volatile("cp.async.cg.shared.global [%0], [%1], 16, %2;" \
                 :: "r"(dst), "l"(src), "r"(sz))
#define CP_COMMIT() asm volatile("cp.async.commit_group;")
#define CP_WAIT(N)  asm volatile("cp.async.wait_group %0;" :: "n"(N))

#define MMA1688(d, a, b) \
    asm volatile("mma.sync.aligned.m16n8k8.row.col.f32.tf32.tf32.f32 " \
                 "{%0,%1,%2,%3}, {%4,%5,%6,%7}, {%8,%9}, {%0,%1,%2,%3};" \
                 : "+f"((d)[0]), "+f"((d)[1]), "+f"((d)[2]), "+f"((d)[3]) \
                 : "r"((a)[0]), "r"((a)[1]), "r"((a)[2]), "r"((a)[3]), \
                   "r"((b)[0]), "r"((b)[1]))

// 16B-chunk swizzle within a 64B row (4 chunks).
__device__ __forceinline__ int swzc(int r, int c) {
    return (c ^ (r & 3) ^ ((r >> 2) & 1)) & 3;
}

// ---------------------------------------------------------------------------
// tf32 tensor-core GEMM: D[m,n] = sum_k A[m,k]*B[n,k], A: M x K, B: N x K,
// both K-major fp32 (tf32-rounded), K % 16 == 0. Tile 128x128x16, 8 warps
// (2x4), double-buffered cp.async, mma.sync m16n8k8 tf32 -> f32.
// OM: 0 = f32 raw, 1 = f32 tf32-rounded, 2 = tf32-rounded transposed
//     (C[n*M+m]), 3 = f32 with combine epilogue (c1*P + c2*acc + c3*X)
// ---------------------------------------------------------------------------
template <int OM, bool HAS_BIAS>
__global__ __launch_bounds__(256)
void mma_gemm(const float* __restrict__ A, const float* __restrict__ B,
              float* __restrict__ Cout, const float* __restrict__ bias,
              int Mrows, int Nrows, int K,
              long long sA, long long sB, long long sC,
              const float* __restrict__ P, const float* __restrict__ X,
              long long sPX,
              const float* __restrict__ s_alpha, const float* __restrict__ s_beta,
              const float* __restrict__ s_gp, const float* __restrict__ s_gc)
{
    // smem: [bufA0 8K][bufB0 8K][bufA1 8K][bufB1 8K] = 32 KB
    __shared__ __align__(128) uint8_t smem[32768];

    const int tid  = threadIdx.x;
    const int lane = tid & 31;
    const int warp = tid >> 5;
    const int mw   = warp >> 2;     // 0..1
    const int nw   = warp & 3;      // 0..3
    const int z    = blockIdx.z;
    const int m0   = blockIdx.y * 128;
    const int n0   = blockIdx.x * 128;

    A += (long long)z * sA;
    B += (long long)z * sB;

    const uint32_t sbase = smem_u32(smem);
    const int KI = K >> 4;          // K / 16

    // tile = 128 rows x 16 fp32 = 64B/row; 512 16B chunks per operand
    auto load_tile = [&](int it, int buf) {
        const int k0 = it << 4;
#pragma unroll
        for (int i = 0; i < 2; ++i) {
            int idx = tid + i * 256;           // 0..511
            int r = idx >> 2, c = idx & 3;
            {   // A side
                int grow = m0 + r;
                int ok = (grow < Mrows);
                const float* src = A + (long long)(ok ? grow : 0) * K + k0 + c * 4;
                uint32_t dst = sbase + buf * 16384 + r * 64 + swzc(r, c) * 16;
                CP_ASYNC16(dst, src, ok ? 16 : 0);
            }
            {   // B side
                int grow = n0 + r;
                int ok = (grow < Nrows);
                const float* src = B + (long long)(ok ? grow : 0) * K + k0 + c * 4;
                uint32_t dst = sbase + buf * 16384 + 8192 + r * 64 + swzc(r, c) * 16;
                CP_ASYNC16(dst, src, ok ? 16 : 0);
            }
        }
    };

    float acc[4][4][4];
#pragma unroll
    for (int i = 0; i < 4; ++i)
#pragma unroll
        for (int j = 0; j < 4; ++j)
#pragma unroll
            for (int r = 0; r < 4; ++r) acc[i][j][r] = 0.f;

    load_tile(0, 0);
    CP_COMMIT();

    const int g  = lane >> 2;       // 0..7
    const int tq = lane & 3;        // 0..3

    for (int it = 0; it < KI; ++it) {
        const int buf = it & 1;
        if (it + 1 < KI) {
            load_tile(it + 1, buf ^ 1);
            CP_COMMIT();
            CP_WAIT(1);
        } else {
            CP_WAIT(0);
        }
        __syncthreads();

        const uint8_t* aP = smem + buf * 16384;
        const uint8_t* bP = aP + 8192;
        auto LD = [&](const uint8_t* base, int r, int k) -> uint32_t {
            int off = r * 64 + swzc(r, k >> 2) * 16 + (k & 3) * 4;
            return *(const uint32_t*)(base + off);
        };

#pragma unroll
        for (int ks = 0; ks < 2; ++ks) {        // two k8 steps per BK=16
            const int kb = ks * 8;
            uint32_t a[4][4];
#pragma unroll
            for (int mi = 0; mi < 4; ++mi) {
                int r0 = mw * 64 + mi * 16 + g;
                a[mi][0] = LD(aP, r0,     kb + tq);
                a[mi][1] = LD(aP, r0 + 8, kb + tq);
                a[mi][2] = LD(aP, r0,     kb + tq + 4);
                a[mi][3] = LD(aP, r0 + 8, kb + tq + 4);
            }
            uint32_t b[4][2];
#pragma unroll
            for (int ni = 0; ni < 4; ++ni) {
                int rn = nw * 32 + ni * 8 + g;
                b[ni][0] = LD(bP, rn, kb + tq);
                b[ni][1] = LD(bP, rn, kb + tq + 4);
            }
#pragma unroll
            for (int mi = 0; mi < 4; ++mi)
#pragma unroll
                for (int ni = 0; ni < 4; ++ni)
                    MMA1688(acc[mi][ni], a[mi], b[ni]);
        }
        __syncthreads();
    }

    // ---- epilogue ----
    float c1 = 0.f, c2 = 1.f, c3 = 0.f;
    if (OM == 3) {
        float al = *s_alpha, be = *s_beta;
        c1 = al * (*s_gp);
        c2 = be * (*s_gc);
        c3 = al + be + 1.f;
        P += (long long)z * sPX;
        X += (long long)z * sPX;
    }
    float* C = Cout + (long long)z * sC;

#pragma unroll
    for (int mi = 0; mi < 4; ++mi) {
#pragma unroll
        for (int half = 0; half < 2; ++half) {
            int m = m0 + mw * 64 + mi * 16 + g + half * 8;
            if (m >= Mrows) continue;
            float bv = HAS_BIAS ? bias[m] : 0.f;
#pragma unroll
            for (int ni = 0; ni < 4; ++ni) {
                int n = n0 + nw * 32 + ni * 8 + tq * 2;
                float v0 = acc[mi][ni][half * 2 + 0] + bv;
                float v1 = acc[mi][ni][half * 2 + 1] + bv;
                if (OM == 2) {
                    if (n < Nrows)     C[(long long)n * Mrows + m]       = tf32r(v0);
                    if (n + 1 < Nrows) C[(long long)(n + 1) * Mrows + m] = tf32r(v1);
                } else {
                    if (n + 1 < Nrows) {
                        long long idx = (long long)m * Nrows + n;
                        if (OM == 0) {
                            *(float2*)&C[idx] = make_float2(v0, v1);
                        } else if (OM == 1) {
                            *(float2*)&C[idx] = make_float2(tf32r(v0), tf32r(v1));
                        } else { // OM == 3
                            C[idx]     = c1 * P[idx]     + c2 * v0 + c3 * X[idx];
                            C[idx + 1] = c1 * P[idx + 1] + c2 * v1 + c3 * X[idx + 1];
                        }
                    } else if (n < Nrows) {
                        long long idx = (long long)m * Nrows + n;
                        if (OM == 0)      C[idx] = v0;
                        else if (OM == 1) C[idx] = tf32r(v0);
                        else              C[idx] = c1 * P[idx] + c2 * v0 + c3 * X[idx];
                    }
                }
            }
        }
    }
}

// ---------------------------------------------------------------------------
// x (b,c,n) fp32 -> tf32-rounded xb (c-major) and xbt (n-major transposed)
// ---------------------------------------------------------------------------
__global__ __launch_bounds__(256)
void convert_x_k(const float* __restrict__ x, float* __restrict__ xb,
                 float* __restrict__ xbt)
{
    __shared__ float t[32][33];
    const int z = blockIdx.z;
    const float* xp = x + (size_t)z * CH * NN;
    float* xbp = xb + (size_t)z * CH * NN;
    float* xtp = xbt + (size_t)z * NN * CH;
    const int n0 = blockIdx.x * 32, c0 = blockIdx.y * 32;
    const int tx = threadIdx.x, ty = threadIdx.y;
#pragma unroll
    for (int k = 0; k < 4; ++k) {
        int c = ty + k * 8;
        float v = tf32r(xp[(size_t)(c0 + c) * NN + n0 + tx]);
        t[c][tx] = v;
        xbp[(size_t)(c0 + c) * NN + n0 + tx] = v;
    }
    __syncthreads();
#pragma unroll
    for (int k = 0; k < 4; ++k) {
        int n = ty + k * 8;
        xtp[(size_t)(n0 + n) * CH + c0 + tx] = t[tx][n];
    }
}

__global__ __launch_bounds__(256)
void round_w_k(const float* __restrict__ src, float* __restrict__ dst, int count)
{
    int i = blockIdx.x * 256 + threadIdx.x;
    if (i < count) dst[i] = tf32r(src[i]);
}

// ---------------------------------------------------------------------------
// Row softmax over 4096-wide fp32 rows, IN PLACE, tf32-rounded output
// ---------------------------------------------------------------------------
__global__ __launch_bounds__(256)
void softmax_pos(float* __restrict__ energy)
{
    const long long row = (long long)blockIdx.y * NN + blockIdx.x;
    float* p = energy + row * NN;
    const int tid = threadIdx.x;
    __shared__ float red[8];

    float v[16];
    float mx = -1e30f;
#pragma unroll
    for (int i = 0; i < 16; ++i) {
        v[i] = p[tid + i * 256];
        mx = fmaxf(mx, v[i]);
    }
#pragma unroll
    for (int o2 = 16; o2; o2 >>= 1) mx = fmaxf(mx, __shfl_xor_sync(~0u, mx, o2));
    if ((tid & 31) == 0) red[tid >> 5] = mx;
    __syncthreads();
    mx = red[0];
#pragma unroll
    for (int i = 1; i < 8; ++i) mx = fmaxf(mx, red[i]);

    float s = 0.f;
#pragma unroll
    for (int i = 0; i < 16; ++i) { v[i] = expf(v[i] - mx); s += v[i]; }
#pragma unroll
    for (int o2 = 16; o2; o2 >>= 1) s += __shfl_xor_sync(~0u, s, o2);
    __syncthreads();
    if ((tid & 31) == 0) red[tid >> 5] = s;
    __syncthreads();
    s = 0.f;
#pragma unroll
    for (int i = 0; i < 8; ++i) s += red[i];
    float inv = 1.f / s;
#pragma unroll
    for (int i = 0; i < 16; ++i) p[tid + i * 256] = tf32r(v[i] * inv);
}

// ---------------------------------------------------------------------------
// Channel softmax IN PLACE: att_c[i,j] = exp(rowmin(G)-G[i,j]) / sum
// ---------------------------------------------------------------------------
__global__ __launch_bounds__(128)
void softmax_chan(float* __restrict__ gram)
{
    const long long row = (long long)blockIdx.y * CH + blockIdx.x;
    float* p = gram + row * CH;
    const int tid = threadIdx.x;
    __shared__ float red[4];

    float v[4];
    float mn = 1e30f;
#pragma unroll
    for (int i = 0; i < 4; ++i) { v[i] = p[tid + i * 128]; mn = fminf(mn, v[i]); }
#pragma unroll
    for (int o2 = 16; o2; o2 >>= 1) mn = fminf(mn, __shfl_xor_sync(~0u, mn, o2));
    if ((tid & 31) == 0) red[tid >> 5] = mn;
    __syncthreads();
    mn = fminf(fminf(red[0], red[1]), fminf(red[2], red[3]));

    float s = 0.f;
#pragma unroll
    for (int i = 0; i < 4; ++i) { v[i] = expf(mn - v[i]); s += v[i]; }
#pragma unroll
    for (int o2 = 16; o2; o2 >>= 1) s += __shfl_xor_sync(~0u, s, o2);
    __syncthreads();
    if ((tid & 31) == 0) red[tid >> 5] = s;
    __syncthreads();
    s = red[0] + red[1] + red[2] + red[3];
    float inv = 1.f / s;
#pragma unroll
    for (int i = 0; i < 4; ++i) p[tid + i * 128] = tf32r(v[i] * inv);
}

// ---------------------------------------------------------------------------
// Launcher
// ---------------------------------------------------------------------------
extern "C" void kernel_launch(void* const* d_in, const int* in_sizes, int n_in,
                              void* d_out, int out_size)
{
    const float* x  = (const float*)d_in[0];
    const float* wq = (const float*)d_in[1];
    const float* bq = (const float*)d_in[2];
    const float* wk = (const float*)d_in[3];
    const float* bk = (const float*)d_in[4];
    const float* wv = (const float*)d_in[5];
    const float* bv = (const float*)d_in[6];
    const float* gp = (const float*)d_in[7];
    const float* gc = (const float*)d_in[8];
    const float* al = (const float*)d_in[9];
    const float* be = (const float*)d_in[10];
    float* out = (float*)d_out;

    float *energy, *xb, *xbt, *vb, *qt, *kt, *pos, *gram;
    float *wqr, *wkr, *wvr;
    cudaGetSymbolAddress((void**)&energy, g_energy);
    cudaGetSymbolAddress((void**)&xb,    g_xb);
    cudaGetSymbolAddress((void**)&xbt,   g_xbt);
    cudaGetSymbolAddress((void**)&vb,    g_vb);
    cudaGetSymbolAddress((void**)&qt,    g_qt);
    cudaGetSymbolAddress((void**)&kt,    g_kt);
    cudaGetSymbolAddress((void**)&pos,   g_pos);
    cudaGetSymbolAddress((void**)&gram,  g_gram);
    cudaGetSymbolAddress((void**)&wqr,   g_wqr);
    cudaGetSymbolAddress((void**)&wkr,   g_wkr);
    cudaGetSymbolAddress((void**)&wvr,   g_wvr);

    const long long sX   = (long long)CH * NN;
    const long long sXT  = (long long)NN * CH;
    const long long sQT  = (long long)NN * CQ;
    const long long sAtt = (long long)NN * NN;
    const long long sGr  = (long long)CH * CH;

    // 1) tf32 rounding / transposes
    convert_x_k<<<dim3(NN / 32, CH / 32, BDIM), dim3(32, 8)>>>(x, xb, xbt);
    round_w_k<<<(CQ * CH + 255) / 256, 256>>>(wq, wqr, CQ * CH);
    round_w_k<<<(CQ * CH + 255) / 256, 256>>>(wk, wkr, CQ * CH);
    round_w_k<<<(CH * CH + 255) / 256, 256>>>(wv, wvr, CH * CH);

    // 2) projections: q_t[n,d], k_t[n,d] (rounded transposed), v[c,n] (rounded)
    mma_gemm<2, true><<<dim3(NN / 128, 1, BDIM), 256>>>(
        wqr, xbt, qt, bq, CQ, NN, CH, 0, sXT, sQT,
        nullptr, nullptr, 0, nullptr, nullptr, nullptr, nullptr);
    mma_gemm<2, true><<<dim3(NN / 128, 1, BDIM), 256>>>(
        wkr, xbt, kt, bk, CQ, NN, CH, 0, sXT, sQT,
        nullptr, nullptr, 0, nullptr, nullptr, nullptr, nullptr);
    mma_gemm<1, true><<<dim3(NN / 128, CH / 128, BDIM), 256>>>(
        wvr, xbt, vb, bv, CH, NN, CH, 0, sXT, sX,
        nullptr, nullptr, 0, nullptr, nullptr, nullptr, nullptr);

    // 3) energy[i,j] = sum_d q_t[i,d] k_t[j,d]
    mma_gemm<0, false><<<dim3(NN / 128, NN / 128, BDIM), 256>>>(
        qt, kt, energy, nullptr, NN, NN, CQ, sQT, sQT, sAtt,
        nullptr, nullptr, 0, nullptr, nullptr, nullptr, nullptr);

    // 4) softmax rows in place (energy becomes att)
    softmax_pos<<<dim3(NN, BDIM), 256>>>(energy);

    // 5) pos[c,i] = sum_j v[c,j] att[i,j]
    mma_gemm<0, false><<<dim3(NN / 128, CH / 128, BDIM), 256>>>(
        vb, energy, pos, nullptr, CH, NN, NN, sX, sAtt, sX,
        nullptr, nullptr, 0, nullptr, nullptr, nullptr, nullptr);

    // 6) gram[i,j] = sum_n xb[i,n] xb[j,n]
    mma_gemm<0, false><<<dim3(CH / 128, CH / 128, BDIM), 256>>>(
        xb, xb, gram, nullptr, CH, CH, NN, sX, sX, sGr,
        nullptr, nullptr, 0, nullptr, nullptr, nullptr, nullptr);

    // 7) channel softmax in place (gram becomes att_c)
    softmax_chan<<<dim3(CH, BDIM), 128>>>(gram);

    // 8) out = a*gp*pos + b*gc*(att_c @ x) + (a+b+1)*x
    mma_gemm<3, false><<<dim3(NN / 128, CH / 128, BDIM), 256>>>(
        gram, xbt, out, nullptr, CH, NN, CH, sGr, sXT, sX,
        pos, x, sX, al, be, gp, gc);
}

// round 7
// speedup vs baseline: 6.2693x; 1.3875x over previous
#include <cuda_runtime.h>
#include <cuda_bf16.h>
#include <cstdint>

// Problem constants
#define BDIM 2
#define CH   512
#define CQ   64
#define NN   4096
#define NSPLIT 8   // split-K factor for gram

// ---------------------------------------------------------------------------
// Scratch (allocation-free __device__ globals), fp32 (tf32-rounded operands).
// ---------------------------------------------------------------------------
__device__ __align__(256) float g_energy[(size_t)BDIM * NN * NN];          // 134 MB
__device__ __align__(256) float g_xb    [(size_t)BDIM * CH * NN];          // c-major
__device__ __align__(256) float g_xbt   [(size_t)BDIM * NN * CH];          // n-major
__device__ __align__(256) float g_vb    [(size_t)BDIM * CH * NN];
__device__ __align__(256) float g_qkt   [(size_t)BDIM * NN * 128];         // [n][q0..63,k64..127]
__device__ __align__(256) float g_pos   [(size_t)BDIM * CH * NN];
__device__ __align__(256) float g_gramp [(size_t)BDIM * NSPLIT * CH * CH]; // 16 MB parts
__device__ __align__(256) float g_attc  [(size_t)BDIM * CH * CH];
__device__ __align__(256) float g_wqk [128 * CH];
__device__ __align__(256) float g_bqk [128];
__device__ __align__(256) float g_wvr [CH * CH];

// ---------------------------------------------------------------------------
// PTX helpers
// ---------------------------------------------------------------------------
__device__ __forceinline__ uint32_t smem_u32(const void* p) {
    uint32_t a;
    asm("{ .reg .u64 t; cvta.to.shared.u64 t, %1; cvt.u32.u64 %0, t; }"
        : "=r"(a) : "l"(p));
    return a;
}

__device__ __forceinline__ float tf32r(float x) {
    uint32_t u;
    asm("cvt.rna.tf32.f32 %0, %1;" : "=r"(u) : "f"(x));
    return __uint_as_float(u);
}

#define CP_ASYNC16(dst, src, sz) \
    asm volatile("cp.async.cg.shared.global [%0], [%1], 16, %2;" \
                 :: "r"(dst), "l"(src), "r"(sz))
#define CP_COMMIT() asm volatile("cp.async.commit_group;")
#define CP_WAIT(N)  asm volatile("cp.async.wait_group %0;" :: "n"(N))

#define MMA1688(d, a, b) \
    asm volatile("mma.sync.aligned.m16n8k8.row.col.f32.tf32.tf32.f32 " \
                 "{%0,%1,%2,%3}, {%4,%5,%6,%7}, {%8,%9}, {%0,%1,%2,%3};" \
                 : "+f"((d)[0]), "+f"((d)[1]), "+f"((d)[2]), "+f"((d)[3]) \
                 : "r"((a)[0]), "r"((a)[1]), "r"((a)[2]), "r"((a)[3]), \
                   "r"((b)[0]), "r"((b)[1]))

// ---------------------------------------------------------------------------
// tf32 GEMM: D[m,n] = sum_k A[m,k]*B[n,k]. Tile BM=128 x BN=256 x BK=32,
// 8 warps (2x4 -> 64x64 warp tile), double-buffered cp.async, dynamic smem
// 96 KB. lda/ldb are row strides (elements). nsplit: blockIdx.z encodes
// (batch * nsplit + k-split); each split covers K elements starting at
// split*K; C parts are contiguous at z*sC.
// OM: 0=f32, 1=f32 tf32-rounded, 2=tf32-rounded transposed (C[n*M+m]),
//     3=f32 combine epilogue (c1*P + c2*acc + c3*X)
// ---------------------------------------------------------------------------
template <int OM, bool HAS_BIAS>
__global__ __launch_bounds__(256)
void mma_gemm(const float* __restrict__ A, const float* __restrict__ B,
              float* __restrict__ Cout, const float* __restrict__ bias,
              int Mrows, int Nrows, int K, int lda, int ldb, int nsplit,
              long long sA, long long sB, long long sC,
              const float* __restrict__ P, const float* __restrict__ X,
              long long sPX,
              const float* __restrict__ s_alpha, const float* __restrict__ s_beta,
              const float* __restrict__ s_gp, const float* __restrict__ s_gc)
{
    extern __shared__ __align__(128) uint8_t smem[];   // 2 * (16K A + 32K B)

    const int tid  = threadIdx.x;
    const int lane = tid & 31;
    const int warp = tid >> 5;
    const int mw   = warp >> 2;     // 0..1
    const int nw   = warp & 3;      // 0..3
    const int z    = blockIdx.z;
    const int bat  = z / nsplit;
    const int sp   = z - bat * nsplit;
    const int m0   = blockIdx.y * 128;
    const int n0   = blockIdx.x * 256;

    A += (long long)bat * sA + (long long)sp * K;
    B += (long long)bat * sB + (long long)sp * K;

    const uint32_t sbase = smem_u32(smem);
    const int KI = K >> 5;          // K / 32

    // A tile 128x32 fp32 = 1024 16B chunks; B tile 256x32 = 2048 chunks.
    auto load_tile = [&](int it, int buf) {
        const int k0 = it << 5;
        const uint32_t st = sbase + buf * 49152;
#pragma unroll
        for (int i = 0; i < 12; ++i) {
            int idx = tid + i * 256;           // 0..3071
            if (idx < 1024) {
                int r = idx >> 3, c = idx & 7;
                int grow = m0 + r;
                int ok = (grow < Mrows);
                const float* src = A + (long long)(ok ? grow : 0) * lda + k0 + c * 4;
                uint32_t dst = st + r * 128 + ((c ^ (r & 7)) << 4);
                CP_ASYNC16(dst, src, ok ? 16 : 0);
            } else {
                int bi = idx - 1024;
                int r = bi >> 3, c = bi & 7;
                int grow = n0 + r;
                int ok = (grow < Nrows);
                const float* src = B + (long long)(ok ? grow : 0) * ldb + k0 + c * 4;
                uint32_t dst = st + 16384 + r * 128 + ((c ^ (r & 7)) << 4);
                CP_ASYNC16(dst, src, ok ? 16 : 0);
            }
        }
    };

    float acc[4][8][4];
#pragma unroll
    for (int i = 0; i < 4; ++i)
#pragma unroll
        for (int j = 0; j < 8; ++j)
#pragma unroll
            for (int r = 0; r < 4; ++r) acc[i][j][r] = 0.f;

    load_tile(0, 0);
    CP_COMMIT();

    const int g  = lane >> 2;       // 0..7
    const int tq = lane & 3;        // 0..3

    for (int it = 0; it < KI; ++it) {
        const int buf = it & 1;
        if (it + 1 < KI) {
            load_tile(it + 1, buf ^ 1);
            CP_COMMIT();
            CP_WAIT(1);
        } else {
            CP_WAIT(0);
        }
        __syncthreads();

        const uint8_t* aP = smem + buf * 49152;
        const uint8_t* bP = aP + 16384;
        auto LDF = [&](const uint8_t* base, int r, int k) -> uint32_t {
            int off = r * 128 + (((k >> 2) ^ (r & 7)) << 4) + (k & 3) * 4;
            return *(const uint32_t*)(base + off);
        };

#pragma unroll
        for (int ks = 0; ks < 4; ++ks) {        // four k8 steps per BK=32
            const int kb = ks * 8;
            uint32_t a[4][4];
#pragma unroll
            for (int mi = 0; mi < 4; ++mi) {
                int r0 = mw * 64 + mi * 16 + g;
                a[mi][0] = LDF(aP, r0,     kb + tq);
                a[mi][1] = LDF(aP, r0 + 8, kb + tq);
                a[mi][2] = LDF(aP, r0,     kb + tq + 4);
                a[mi][3] = LDF(aP, r0 + 8, kb + tq + 4);
            }
            uint32_t b[8][2];
#pragma unroll
            for (int ni = 0; ni < 8; ++ni) {
                int rn = nw * 64 + ni * 8 + g;
                b[ni][0] = LDF(bP, rn, kb + tq);
                b[ni][1] = LDF(bP, rn, kb + tq + 4);
            }
#pragma unroll
            for (int mi = 0; mi < 4; ++mi)
#pragma unroll
                for (int ni = 0; ni < 8; ++ni)
                    MMA1688(acc[mi][ni], a[mi], b[ni]);
        }
        __syncthreads();
    }

    // ---- epilogue ----
    float c1 = 0.f, c2 = 1.f, c3 = 0.f;
    if (OM == 3) {
        float al = *s_alpha, be = *s_beta;
        c1 = al * (*s_gp);
        c2 = be * (*s_gc);
        c3 = al + be + 1.f;
        P += (long long)bat * sPX;
        X += (long long)bat * sPX;
    }
    float* C = Cout + (long long)z * sC;

#pragma unroll
    for (int mi = 0; mi < 4; ++mi) {
#pragma unroll
        for (int half = 0; half < 2; ++half) {
            int m = m0 + mw * 64 + mi * 16 + g + half * 8;
            if (m >= Mrows) continue;
            float bv = HAS_BIAS ? bias[m] : 0.f;
#pragma unroll
            for (int ni = 0; ni < 8; ++ni) {
                int n = n0 + nw * 64 + ni * 8 + tq * 2;
                float v0 = acc[mi][ni][half * 2 + 0] + bv;
                float v1 = acc[mi][ni][half * 2 + 1] + bv;
                if (OM == 2) {
                    if (n < Nrows)     C[(long long)n * Mrows + m]       = tf32r(v0);
                    if (n + 1 < Nrows) C[(long long)(n + 1) * Mrows + m] = tf32r(v1);
                } else {
                    if (n + 1 < Nrows) {
                        long long idx = (long long)m * Nrows + n;
                        if (OM == 0) {
                            *(float2*)&C[idx] = make_float2(v0, v1);
                        } else if (OM == 1) {
                            *(float2*)&C[idx] = make_float2(tf32r(v0), tf32r(v1));
                        } else { // OM == 3
                            C[idx]     = c1 * P[idx]     + c2 * v0 + c3 * X[idx];
                            C[idx + 1] = c1 * P[idx + 1] + c2 * v1 + c3 * X[idx + 1];
                        }
                    } else if (n < Nrows) {
                        long long idx = (long long)m * Nrows + n;
                        if (OM == 0)      C[idx] = v0;
                        else if (OM == 1) C[idx] = tf32r(v0);
                        else              C[idx] = c1 * P[idx] + c2 * v0 + c3 * X[idx];
                    }
                }
            }
        }
    }
}

// ---------------------------------------------------------------------------
// x (b,c,n) fp32 -> tf32-rounded xb (c-major) and xbt (n-major transposed)
// ---------------------------------------------------------------------------
__global__ __launch_bounds__(256)
void convert_x_k(const float* __restrict__ x, float* __restrict__ xb,
                 float* __restrict__ xbt)
{
    __shared__ float t[32][33];
    const int z = blockIdx.z;
    const float* xp = x + (size_t)z * CH * NN;
    float* xbp = xb + (size_t)z * CH * NN;
    float* xtp = xbt + (size_t)z * NN * CH;
    const int n0 = blockIdx.x * 32, c0 = blockIdx.y * 32;
    const int tx = threadIdx.x, ty = threadIdx.y;
#pragma unroll
    for (int k = 0; k < 4; ++k) {
        int c = ty + k * 8;
        float v = tf32r(xp[(size_t)(c0 + c) * NN + n0 + tx]);
        t[c][tx] = v;
        xbp[(size_t)(c0 + c) * NN + n0 + tx] = v;
    }
    __syncthreads();
#pragma unroll
    for (int k = 0; k < 4; ++k) {
        int n = ty + k * 8;
        xtp[(size_t)(n0 + n) * CH + c0 + tx] = t[tx][n];
    }
}

// wq (64x512) + wk (64x512) -> wqk (128x512) tf32-rounded; bq+bk -> bqk;
// wv -> wvr rounded.
__global__ __launch_bounds__(256)
void prep_weights_k(const float* __restrict__ wq, const float* __restrict__ wk,
                    const float* __restrict__ bq, const float* __restrict__ bk,
                    const float* __restrict__ wv,
                    float* __restrict__ wqk, float* __restrict__ bqk,
                    float* __restrict__ wvr)
{
    int i = blockIdx.x * 256 + threadIdx.x;
    if (i < 128 * CH) {
        int row = i >> 9;   // /512
        float v = (row < 64) ? wq[i] : wk[i - 64 * CH];
        wqk[i] = tf32r(v);
    }
    if (i < 128) bqk[i] = (i < 64) ? bq[i] : bk[i - 64];
    if (i < CH * CH) wvr[i] = tf32r(wv[i]);
}

// ---------------------------------------------------------------------------
// Row softmax over 4096-wide fp32 rows, IN PLACE, tf32-rounded output
// ---------------------------------------------------------------------------
__global__ __launch_bounds__(256)
void softmax_pos(float* __restrict__ energy)
{
    const long long row = (long long)blockIdx.y * NN + blockIdx.x;
    float* p = energy + row * NN;
    const int tid = threadIdx.x;
    __shared__ float red[8];

    float v[16];
    float mx = -1e30f;
#pragma unroll
    for (int i = 0; i < 16; ++i) {
        v[i] = p[tid + i * 256];
        mx = fmaxf(mx, v[i]);
    }
#pragma unroll
    for (int o2 = 16; o2; o2 >>= 1) mx = fmaxf(mx, __shfl_xor_sync(~0u, mx, o2));
    if ((tid & 31) == 0) red[tid >> 5] = mx;
    __syncthreads();
    mx = red[0];
#pragma unroll
    for (int i = 1; i < 8; ++i) mx = fmaxf(mx, red[i]);

    float s = 0.f;
#pragma unroll
    for (int i = 0; i < 16; ++i) { v[i] = expf(v[i] - mx); s += v[i]; }
#pragma unroll
    for (int o2 = 16; o2; o2 >>= 1) s += __shfl_xor_sync(~0u, s, o2);
    __syncthreads();
    if ((tid & 31) == 0) red[tid >> 5] = s;
    __syncthreads();
    s = 0.f;
#pragma unroll
    for (int i = 0; i < 8; ++i) s += red[i];
    float inv = 1.f / s;
#pragma unroll
    for (int i = 0; i < 16; ++i) p[tid + i * 256] = tf32r(v[i] * inv);
}

// ---------------------------------------------------------------------------
// Channel softmax, fused split-K reduction:
//   G[i,j] = sum_s gramp[bat*NSPLIT+s][i][j]; att_c = softmax_j(rowmin - G)
// ---------------------------------------------------------------------------
__global__ __launch_bounds__(128)
void softmax_chan(const float* __restrict__ gramp, float* __restrict__ attc)
{
    const int bat = blockIdx.y;
    const int row = blockIdx.x;
    const float* base = gramp + ((size_t)bat * NSPLIT) * CH * CH + (size_t)row * CH;
    float* o = attc + ((size_t)bat * CH + row) * CH;
    const int tid = threadIdx.x;
    __shared__ float red[4];

    float v[4];
    float mn = 1e30f;
#pragma unroll
    for (int i = 0; i < 4; ++i) {
        float s = 0.f;
#pragma unroll
        for (int sp = 0; sp < NSPLIT; ++sp)
            s += base[(size_t)sp * CH * CH + tid + i * 128];
        v[i] = s;
        mn = fminf(mn, s);
    }
#pragma unroll
    for (int o2 = 16; o2; o2 >>= 1) mn = fminf(mn, __shfl_xor_sync(~0u, mn, o2));
    if ((tid & 31) == 0) red[tid >> 5] = mn;
    __syncthreads();
    mn = fminf(fminf(red[0], red[1]), fminf(red[2], red[3]));

    float s = 0.f;
#pragma unroll
    for (int i = 0; i < 4; ++i) { v[i] = expf(mn - v[i]); s += v[i]; }
#pragma unroll
    for (int o2 = 16; o2; o2 >>= 1) s += __shfl_xor_sync(~0u, s, o2);
    __syncthreads();
    if ((tid & 31) == 0) red[tid >> 5] = s;
    __syncthreads();
    s = red[0] + red[1] + red[2] + red[3];
    float inv = 1.f / s;
#pragma unroll
    for (int i = 0; i < 4; ++i) o[tid + i * 128] = tf32r(v[i] * inv);
}

// ---------------------------------------------------------------------------
// Launcher
// ---------------------------------------------------------------------------
extern "C" void kernel_launch(void* const* d_in, const int* in_sizes, int n_in,
                              void* d_out, int out_size)
{
    const float* x  = (const float*)d_in[0];
    const float* wq = (const float*)d_in[1];
    const float* bq = (const float*)d_in[2];
    const float* wk = (const float*)d_in[3];
    const float* bk = (const float*)d_in[4];
    const float* wv = (const float*)d_in[5];
    const float* bv = (const float*)d_in[6];
    const float* gp = (const float*)d_in[7];
    const float* gc = (const float*)d_in[8];
    const float* al = (const float*)d_in[9];
    const float* be = (const float*)d_in[10];
    float* out = (float*)d_out;

    float *energy, *xb, *xbt, *vb, *qkt, *pos, *gramp, *attc;
    float *wqk, *bqk, *wvr;
    cudaGetSymbolAddress((void**)&energy, g_energy);
    cudaGetSymbolAddress((void**)&xb,    g_xb);
    cudaGetSymbolAddress((void**)&xbt,   g_xbt);
    cudaGetSymbolAddress((void**)&vb,    g_vb);
    cudaGetSymbolAddress((void**)&qkt,   g_qkt);
    cudaGetSymbolAddress((void**)&pos,   g_pos);
    cudaGetSymbolAddress((void**)&gramp, g_gramp);
    cudaGetSymbolAddress((void**)&attc,  g_attc);
    cudaGetSymbolAddress((void**)&wqk,   g_wqk);
    cudaGetSymbolAddress((void**)&bqk,   g_bqk);
    cudaGetSymbolAddress((void**)&wvr,   g_wvr);

    const long long sX   = (long long)CH * NN;
    const long long sXT  = (long long)NN * CH;
    const long long sQK  = (long long)NN * 128;
    const long long sAtt = (long long)NN * NN;
    const long long sGr  = (long long)CH * CH;

    const int SMEM = 98304;   // 2 stages * (16K + 32K)
    static bool attr_done = false;
    if (!attr_done) {
        cudaFuncSetAttribute(mma_gemm<2, true>,  cudaFuncAttributeMaxDynamicSharedMemorySize, SMEM);
        cudaFuncSetAttribute(mma_gemm<1, true>,  cudaFuncAttributeMaxDynamicSharedMemorySize, SMEM);
        cudaFuncSetAttribute(mma_gemm<0, false>, cudaFuncAttributeMaxDynamicSharedMemorySize, SMEM);
        cudaFuncSetAttribute(mma_gemm<3, false>, cudaFuncAttributeMaxDynamicSharedMemorySize, SMEM);
        attr_done = true;
    }

    // 1) conversions / weight prep
    convert_x_k<<<dim3(NN / 32, CH / 32, BDIM), dim3(32, 8)>>>(x, xb, xbt);
    prep_weights_k<<<(CH * CH + 255) / 256, 256>>>(wq, wk, bq, bk, wv, wqk, bqk, wvr);

    // 2) fused q|k projection -> qkt[n][128] (transposed, rounded, +bias)
    mma_gemm<2, true><<<dim3(NN / 256, 1, BDIM), 256, SMEM>>>(
        wqk, xbt, qkt, bqk, 128, NN, CH, CH, CH, 1, 0, sXT, sQK,
        nullptr, nullptr, 0, nullptr, nullptr, nullptr, nullptr);

    // 3) v projection -> vb[c][n] (rounded, +bias)
    mma_gemm<1, true><<<dim3(NN / 256, CH / 128, BDIM), 256, SMEM>>>(
        wvr, xbt, vb, bv, CH, NN, CH, CH, CH, 1, 0, sXT, sX,
        nullptr, nullptr, 0, nullptr, nullptr, nullptr, nullptr);

    // 4) energy[i,j] = sum_d q[i,d] k[j,d]; both operands strided in qkt
    mma_gemm<0, false><<<dim3(NN / 256, NN / 128, BDIM), 256, SMEM>>>(
        qkt, qkt + 64, energy, nullptr, NN, NN, CQ, 128, 128, 1, sQK, sQK, sAtt,
        nullptr, nullptr, 0, nullptr, nullptr, nullptr, nullptr);

    // 5) softmax rows in place (energy becomes att, rounded)
    softmax_pos<<<dim3(NN, BDIM), 256>>>(energy);

    // 6) pos[c,i] = sum_j v[c,j] att[i,j]
    mma_gemm<0, false><<<dim3(NN / 256, CH / 128, BDIM), 256, SMEM>>>(
        vb, energy, pos, nullptr, CH, NN, NN, NN, NN, 1, sX, sAtt, sX,
        nullptr, nullptr, 0, nullptr, nullptr, nullptr, nullptr);

    // 7) gram split-K parts: z = bat*NSPLIT + sp, each over K=512
    mma_gemm<0, false><<<dim3(CH / 256, CH / 128, BDIM * NSPLIT), 256, SMEM>>>(
        xb, xb, gramp, nullptr, CH, CH, NN / NSPLIT, NN, NN, NSPLIT, sX, sX, sGr,
        nullptr, nullptr, 0, nullptr, nullptr, nullptr, nullptr);

    // 8) channel softmax with fused part-reduction -> attc (rounded)
    softmax_chan<<<dim3(CH, BDIM), 128>>>(gramp, attc);

    // 9) out = a*gp*pos + b*gc*(att_c @ x) + (a+b+1)*x
    mma_gemm<3, false><<<dim3(NN / 256, CH / 128, BDIM), 256, SMEM>>>(
        attc, xbt, out, nullptr, CH, NN, CH, CH, CH, 1, sGr, sXT, sX,
        pos, x, sX, al, be, gp, gc);
}

// round 8
// speedup vs baseline: 8.1381x; 1.2981x over previous
#include <cuda_runtime.h>
#include <cuda_bf16.h>
#include <cstdint>

#define BDIM 2
#define CH   512
#define CQ   64
#define NN   4096
#define NSPLIT 8

typedef __nv_bfloat16 bf16;

// ---------------------------------------------------------------------------
// Scratch (allocation-free __device__ globals). bf16 att lives IN PLACE in
// the first half of each fp32 energy row (row stride 2*NN bf16 elements).
// ---------------------------------------------------------------------------
__device__ __align__(256) float g_energy[(size_t)BDIM * NN * NN];          // 134 MB
__device__ __align__(256) float g_xb    [(size_t)BDIM * CH * NN];          // tf32, c-major
__device__ __align__(256) float g_xbt   [(size_t)BDIM * NN * CH];          // tf32, n-major
__device__ __align__(256) bf16  g_xbt_b [(size_t)BDIM * NN * CH];          // bf16, n-major
__device__ __align__(256) bf16  g_vb    [(size_t)BDIM * CH * NN];          // bf16
__device__ __align__(256) float g_qkt   [(size_t)BDIM * NN * 128];
__device__ __align__(256) float g_pos   [(size_t)BDIM * CH * NN];
__device__ __align__(256) float g_gramp [(size_t)BDIM * NSPLIT * CH * CH];
__device__ __align__(256) bf16  g_attcb [(size_t)BDIM * CH * CH];
__device__ __align__(256) float g_wqk [128 * CH];
__device__ __align__(256) float g_bqk [128];
__device__ __align__(256) float g_wvr [CH * CH];

// ---------------------------------------------------------------------------
// PTX helpers
// ---------------------------------------------------------------------------
__device__ __forceinline__ uint32_t smem_u32(const void* p) {
    uint32_t a;
    asm("{ .reg .u64 t; cvta.to.shared.u64 t, %1; cvt.u32.u64 %0, t; }"
        : "=r"(a) : "l"(p));
    return a;
}
__device__ __forceinline__ float tf32r(float x) {
    uint32_t u;
    asm("cvt.rna.tf32.f32 %0, %1;" : "=r"(u) : "f"(x));
    return __uint_as_float(u);
}

#define CP_ASYNC16(dst, src, sz) \
    asm volatile("cp.async.cg.shared.global [%0], [%1], 16, %2;" \
                 :: "r"(dst), "l"(src), "r"(sz))
#define CP_COMMIT() asm volatile("cp.async.commit_group;")
#define CP_WAIT(N)  asm volatile("cp.async.wait_group %0;" :: "n"(N))

#define MMA1688(d, a, b) \
    asm volatile("mma.sync.aligned.m16n8k8.row.col.f32.tf32.tf32.f32 " \
                 "{%0,%1,%2,%3}, {%4,%5,%6,%7}, {%8,%9}, {%0,%1,%2,%3};" \
                 : "+f"((d)[0]), "+f"((d)[1]), "+f"((d)[2]), "+f"((d)[3]) \
                 : "r"((a)[0]), "r"((a)[1]), "r"((a)[2]), "r"((a)[3]), \
                   "r"((b)[0]), "r"((b)[1]))

#define MMA16816(d, a, b) \
    asm volatile("mma.sync.aligned.m16n8k16.row.col.f32.bf16.bf16.f32 " \
                 "{%0,%1,%2,%3}, {%4,%5,%6,%7}, {%8,%9}, {%0,%1,%2,%3};" \
                 : "+f"((d)[0]), "+f"((d)[1]), "+f"((d)[2]), "+f"((d)[3]) \
                 : "r"((a)[0]), "r"((a)[1]), "r"((a)[2]), "r"((a)[3]), \
                   "r"((b)[0]), "r"((b)[1]))

#define LDSM4(R, addr) \
    asm volatile("ldmatrix.sync.aligned.m8n8.x4.shared.b16 {%0,%1,%2,%3}, [%4];" \
                 : "=r"((R)[0]), "=r"((R)[1]), "=r"((R)[2]), "=r"((R)[3]) \
                 : "r"(addr))

// 4-chunk (16B) swizzle within a 64B row
__device__ __forceinline__ int swzc(int r, int c) {
    return (c ^ (r & 3) ^ ((r >> 2) & 1)) & 3;
}

// ---------------------------------------------------------------------------
// tf32 GEMM: D[m,n]=sum_k A[m,k]*B[n,k]. BM128 x BN256 x BK32, 8 warps
// (64x64 warp tiles), double-buffered cp.async, 96 KB dyn smem. nsplit: z
// encodes (batch*nsplit + split); split covers K elems at split*K.
// OM: 0=f32, 2=tf32-rounded transposed (C[n*M+m]), 4=bf16 row-major
// ---------------------------------------------------------------------------
template <int OM, bool HAS_BIAS>
__global__ __launch_bounds__(256)
void mma_gemm(const float* __restrict__ A, const float* __restrict__ B,
              float* __restrict__ Cout, const float* __restrict__ bias,
              int Mrows, int Nrows, int K, int lda, int ldb, int nsplit,
              long long sA, long long sB, long long sC)
{
    extern __shared__ __align__(128) uint8_t smem[];

    const int tid  = threadIdx.x;
    const int lane = tid & 31;
    const int warp = tid >> 5;
    const int mw   = warp >> 2;
    const int nw   = warp & 3;
    const int z    = blockIdx.z;
    const int bat  = z / nsplit;
    const int sp   = z - bat * nsplit;
    const int m0   = blockIdx.y * 128;
    const int n0   = blockIdx.x * 256;

    A += (long long)bat * sA + (long long)sp * K;
    B += (long long)bat * sB + (long long)sp * K;

    const uint32_t sbase = smem_u32(smem);
    const int KI = K >> 5;

    auto load_tile = [&](int it, int buf) {
        const int k0 = it << 5;
        const uint32_t st = sbase + buf * 49152;
#pragma unroll
        for (int i = 0; i < 12; ++i) {
            int idx = tid + i * 256;
            if (idx < 1024) {
                int r = idx >> 3, c = idx & 7;
                int grow = m0 + r;
                int ok = (grow < Mrows);
                const float* src = A + (long long)(ok ? grow : 0) * lda + k0 + c * 4;
                uint32_t dst = st + r * 128 + ((c ^ (r & 7)) << 4);
                CP_ASYNC16(dst, src, ok ? 16 : 0);
            } else {
                int bi = idx - 1024;
                int r = bi >> 3, c = bi & 7;
                int grow = n0 + r;
                int ok = (grow < Nrows);
                const float* src = B + (long long)(ok ? grow : 0) * ldb + k0 + c * 4;
                uint32_t dst = st + 16384 + r * 128 + ((c ^ (r & 7)) << 4);
                CP_ASYNC16(dst, src, ok ? 16 : 0);
            }
        }
    };

    float acc[4][8][4];
#pragma unroll
    for (int i = 0; i < 4; ++i)
#pragma unroll
        for (int j = 0; j < 8; ++j)
#pragma unroll
            for (int r = 0; r < 4; ++r) acc[i][j][r] = 0.f;

    load_tile(0, 0);
    CP_COMMIT();

    const int g  = lane >> 2;
    const int tq = lane & 3;

    for (int it = 0; it < KI; ++it) {
        const int buf = it & 1;
        if (it + 1 < KI) { load_tile(it + 1, buf ^ 1); CP_COMMIT(); CP_WAIT(1); }
        else             { CP_WAIT(0); }
        __syncthreads();

        const uint8_t* aP = smem + buf * 49152;
        const uint8_t* bP = aP + 16384;
        auto LDF = [&](const uint8_t* base, int r, int k) -> uint32_t {
            int off = r * 128 + (((k >> 2) ^ (r & 7)) << 4) + (k & 3) * 4;
            return *(const uint32_t*)(base + off);
        };

#pragma unroll
        for (int ks = 0; ks < 4; ++ks) {
            const int kb = ks * 8;
            uint32_t a[4][4];
#pragma unroll
            for (int mi = 0; mi < 4; ++mi) {
                int r0 = mw * 64 + mi * 16 + g;
                a[mi][0] = LDF(aP, r0,     kb + tq);
                a[mi][1] = LDF(aP, r0 + 8, kb + tq);
                a[mi][2] = LDF(aP, r0,     kb + tq + 4);
                a[mi][3] = LDF(aP, r0 + 8, kb + tq + 4);
            }
            uint32_t b[8][2];
#pragma unroll
            for (int ni = 0; ni < 8; ++ni) {
                int rn = nw * 64 + ni * 8 + g;
                b[ni][0] = LDF(bP, rn, kb + tq);
                b[ni][1] = LDF(bP, rn, kb + tq + 4);
            }
#pragma unroll
            for (int mi = 0; mi < 4; ++mi)
#pragma unroll
                for (int ni = 0; ni < 8; ++ni)
                    MMA1688(acc[mi][ni], a[mi], b[ni]);
        }
        __syncthreads();
    }

    float* C  = Cout + (long long)z * sC;
    bf16*  Cb = (bf16*)Cout + (long long)z * sC;

#pragma unroll
    for (int mi = 0; mi < 4; ++mi) {
#pragma unroll
        for (int half = 0; half < 2; ++half) {
            int m = m0 + mw * 64 + mi * 16 + g + half * 8;
            if (m >= Mrows) continue;
            float bv = HAS_BIAS ? bias[m] : 0.f;
#pragma unroll
            for (int ni = 0; ni < 8; ++ni) {
                int n = n0 + nw * 64 + ni * 8 + tq * 2;
                float v0 = acc[mi][ni][half * 2 + 0] + bv;
                float v1 = acc[mi][ni][half * 2 + 1] + bv;
                if (OM == 2) {
                    if (n < Nrows)     C[(long long)n * Mrows + m]       = tf32r(v0);
                    if (n + 1 < Nrows) C[(long long)(n + 1) * Mrows + m] = tf32r(v1);
                } else if (OM == 4) {
                    if (n + 1 < Nrows) {
                        uint32_t pk = ((uint32_t)__bfloat16_as_ushort(__float2bfloat16(v1)) << 16)
                                    | (uint32_t)__bfloat16_as_ushort(__float2bfloat16(v0));
                        *(uint32_t*)&Cb[(long long)m * Nrows + n] = pk;
                    } else if (n < Nrows) {
                        Cb[(long long)m * Nrows + n] = __float2bfloat16(v0);
                    }
                } else {
                    if (n + 1 < Nrows)
                        *(float2*)&C[(long long)m * Nrows + n] = make_float2(v0, v1);
                    else if (n < Nrows)
                        C[(long long)m * Nrows + n] = v0;
                }
            }
        }
    }
}

// ---------------------------------------------------------------------------
// bf16 GEMM: D[m,n]=sum_k A[m,k]*B[n,k], bf16 operands (ldmatrix), fp32 acc.
// BM128 x BN256 x BK32, 8 warps (64x64), double-buffered, 48 KB static smem.
// OM: 0 = f32 row-major, 3 = combine epilogue (c1*P + c2*acc + c3*X)
// Fragment mapping verified in round 4.
// ---------------------------------------------------------------------------
template <int OM>
__global__ __launch_bounds__(256)
void bf_gemm(const bf16* __restrict__ A, const bf16* __restrict__ B,
             float* __restrict__ Cout,
             int Mrows, int Nrows, int K, int lda, int ldb,
             long long sA, long long sB, long long sC,
             const float* __restrict__ P, const float* __restrict__ X,
             long long sPX,
             const float* __restrict__ s_alpha, const float* __restrict__ s_beta,
             const float* __restrict__ s_gp, const float* __restrict__ s_gc)
{
    __shared__ __align__(128) uint8_t smem[49152];  // 2 stages * (A 8K + B 16K)

    const int tid  = threadIdx.x;
    const int lane = tid & 31;
    const int warp = tid >> 5;
    const int mw   = warp >> 2;
    const int nw   = warp & 3;
    const int z    = blockIdx.z;
    const int m0   = blockIdx.y * 128;
    const int n0   = blockIdx.x * 256;

    A += (long long)z * sA;
    B += (long long)z * sB;

    const uint32_t sbase = smem_u32(smem);
    const int KI = K >> 5;

    // A: 128 rows x 64B (32 bf16) = 512 chunks; B: 256 rows = 1024 chunks
    auto load_tile = [&](int it, int buf) {
        const int k0 = it << 5;
        const uint32_t st = sbase + buf * 24576;
#pragma unroll
        for (int i = 0; i < 6; ++i) {
            int idx = tid + i * 256;
            if (idx < 512) {
                int r = idx >> 2, c = idx & 3;
                int grow = m0 + r;
                int ok = (grow < Mrows);
                const bf16* src = A + (long long)(ok ? grow : 0) * lda + k0 + c * 8;
                uint32_t dst = st + r * 64 + swzc(r, c) * 16;
                CP_ASYNC16(dst, src, ok ? 16 : 0);
            } else {
                int bi = idx - 512;
                int r = bi >> 2, c = bi & 3;
                int grow = n0 + r;
                int ok = (grow < Nrows);
                const bf16* src = B + (long long)(ok ? grow : 0) * ldb + k0 + c * 8;
                uint32_t dst = st + 8192 + r * 64 + swzc(r, c) * 16;
                CP_ASYNC16(dst, src, ok ? 16 : 0);
            }
        }
    };

    float acc[4][8][4];
#pragma unroll
    for (int i = 0; i < 4; ++i)
#pragma unroll
        for (int j = 0; j < 8; ++j)
#pragma unroll
            for (int r = 0; r < 4; ++r) acc[i][j][r] = 0.f;

    load_tile(0, 0);
    CP_COMMIT();

    const int sub  = lane >> 3;
    const int lrow = lane & 7;

    for (int it = 0; it < KI; ++it) {
        const int buf = it & 1;
        if (it + 1 < KI) { load_tile(it + 1, buf ^ 1); CP_COMMIT(); CP_WAIT(1); }
        else             { CP_WAIT(0); }
        __syncthreads();

        const uint32_t aB = sbase + buf * 24576;
        const uint32_t bB = aB + 8192;

#pragma unroll
        for (int ks = 0; ks < 2; ++ks) {        // two k16 steps per BK=32
            uint32_t a[4][4];
#pragma unroll
            for (int mi = 0; mi < 4; ++mi) {
                int row = mw * 64 + mi * 16 + (sub & 1) * 8 + lrow;
                int kc  = ks * 2 + (sub >> 1);
                uint32_t addr = aB + row * 64 + swzc(row, kc) * 16;
                LDSM4(a[mi], addr);
            }
            uint32_t b[8][2];
#pragma unroll
            for (int p = 0; p < 4; ++p) {
                int row = nw * 64 + p * 16 + (sub >> 1) * 8 + lrow;
                int kc  = ks * 2 + (sub & 1);
                uint32_t addr = bB + row * 64 + swzc(row, kc) * 16;
                uint32_t t[4];
                LDSM4(t, addr);
                b[2 * p][0]     = t[0];
                b[2 * p][1]     = t[1];
                b[2 * p + 1][0] = t[2];
                b[2 * p + 1][1] = t[3];
            }
#pragma unroll
            for (int mi = 0; mi < 4; ++mi)
#pragma unroll
                for (int ni = 0; ni < 8; ++ni)
                    MMA16816(acc[mi][ni], a[mi], b[ni]);
        }
        __syncthreads();
    }

    float c1 = 0.f, c2 = 1.f, c3 = 0.f;
    if (OM == 3) {
        float al = *s_alpha, be = *s_beta;
        c1 = al * (*s_gp);
        c2 = be * (*s_gc);
        c3 = al + be + 1.f;
        P += (long long)z * sPX;
        X += (long long)z * sPX;
    }
    float* C = Cout + (long long)z * sC;

    const int g  = lane >> 2;
    const int tq = lane & 3;

#pragma unroll
    for (int mi = 0; mi < 4; ++mi) {
#pragma unroll
        for (int half = 0; half < 2; ++half) {
            int m = m0 + mw * 64 + mi * 16 + g + half * 8;
            if (m >= Mrows) continue;
#pragma unroll
            for (int ni = 0; ni < 8; ++ni) {
                int n = n0 + nw * 64 + ni * 8 + tq * 2;
                float v0 = acc[mi][ni][half * 2 + 0];
                float v1 = acc[mi][ni][half * 2 + 1];
                if (n + 1 < Nrows) {
                    long long idx = (long long)m * Nrows + n;
                    if (OM == 0) {
                        *(float2*)&C[idx] = make_float2(v0, v1);
                    } else {
                        C[idx]     = c1 * P[idx]     + c2 * v0 + c3 * X[idx];
                        C[idx + 1] = c1 * P[idx + 1] + c2 * v1 + c3 * X[idx + 1];
                    }
                } else if (n < Nrows) {
                    long long idx = (long long)m * Nrows + n;
                    if (OM == 0) C[idx] = v0;
                    else         C[idx] = c1 * P[idx] + c2 * v0 + c3 * X[idx];
                }
            }
        }
    }
}

// ---------------------------------------------------------------------------
// x (b,c,n) fp32 -> tf32 xb (c-major), tf32 xbt (n-major), bf16 xbt_b
// ---------------------------------------------------------------------------
__global__ __launch_bounds__(256)
void convert_x_k(const float* __restrict__ x, float* __restrict__ xb,
                 float* __restrict__ xbt, bf16* __restrict__ xbt_b)
{
    __shared__ float t[32][33];
    const int z = blockIdx.z;
    const float* xp = x + (size_t)z * CH * NN;
    float* xbp = xb + (size_t)z * CH * NN;
    float* xtp = xbt + (size_t)z * NN * CH;
    bf16*  xtb = xbt_b + (size_t)z * NN * CH;
    const int n0 = blockIdx.x * 32, c0 = blockIdx.y * 32;
    const int tx = threadIdx.x, ty = threadIdx.y;
#pragma unroll
    for (int k = 0; k < 4; ++k) {
        int c = ty + k * 8;
        float raw = xp[(size_t)(c0 + c) * NN + n0 + tx];
        float v = tf32r(raw);
        t[c][tx] = raw;
        xbp[(size_t)(c0 + c) * NN + n0 + tx] = v;
    }
    __syncthreads();
#pragma unroll
    for (int k = 0; k < 4; ++k) {
        int n = ty + k * 8;
        float raw = t[tx][n];
        xtp[(size_t)(n0 + n) * CH + c0 + tx] = tf32r(raw);
        xtb[(size_t)(n0 + n) * CH + c0 + tx] = __float2bfloat16(raw);
    }
}

__global__ __launch_bounds__(256)
void prep_weights_k(const float* __restrict__ wq, const float* __restrict__ wk,
                    const float* __restrict__ bq, const float* __restrict__ bk,
                    const float* __restrict__ wv,
                    float* __restrict__ wqk, float* __restrict__ bqk,
                    float* __restrict__ wvr)
{
    int i = blockIdx.x * 256 + threadIdx.x;
    if (i < 128 * CH) {
        int row = i >> 9;
        float v = (row < 64) ? wq[i] : wk[i - 64 * CH];
        wqk[i] = tf32r(v);
    }
    if (i < 128) bqk[i] = (i < 64) ? bq[i] : bk[i - 64];
    if (i < CH * CH) wvr[i] = tf32r(wv[i]);
}

// ---------------------------------------------------------------------------
// Row softmax, fp32 in, bf16 out IN PLACE (first half of each fp32 row).
// ---------------------------------------------------------------------------
__global__ __launch_bounds__(256)
void softmax_pos(float* __restrict__ energy)
{
    const long long row = (long long)blockIdx.y * NN + blockIdx.x;
    float* p = energy + row * NN;
    bf16*  ob = (bf16*)p;
    const int tid = threadIdx.x;
    __shared__ float red[8];

    float v[16];
    float mx = -1e30f;
#pragma unroll
    for (int i = 0; i < 16; ++i) {
        v[i] = p[tid + i * 256];
        mx = fmaxf(mx, v[i]);
    }
#pragma unroll
    for (int o2 = 16; o2; o2 >>= 1) mx = fmaxf(mx, __shfl_xor_sync(~0u, mx, o2));
    if ((tid & 31) == 0) red[tid >> 5] = mx;
    __syncthreads();
    mx = red[0];
#pragma unroll
    for (int i = 1; i < 8; ++i) mx = fmaxf(mx, red[i]);

    float s = 0.f;
#pragma unroll
    for (int i = 0; i < 16; ++i) { v[i] = expf(v[i] - mx); s += v[i]; }
#pragma unroll
    for (int o2 = 16; o2; o2 >>= 1) s += __shfl_xor_sync(~0u, s, o2);
    __syncthreads();
    if ((tid & 31) == 0) red[tid >> 5] = s;
    __syncthreads();
    s = 0.f;
#pragma unroll
    for (int i = 0; i < 8; ++i) s += red[i];
    float inv = 1.f / s;
#pragma unroll
    for (int i = 0; i < 16; ++i) ob[tid + i * 256] = __float2bfloat16(v[i] * inv);
}

// ---------------------------------------------------------------------------
// Channel softmax with fused split-K reduction -> bf16 att_c
// ---------------------------------------------------------------------------
__global__ __launch_bounds__(128)
void softmax_chan(const float* __restrict__ gramp, bf16* __restrict__ attcb)
{
    const int bat = blockIdx.y;
    const int row = blockIdx.x;
    const float* base = gramp + ((size_t)bat * NSPLIT) * CH * CH + (size_t)row * CH;
    bf16* o = attcb + ((size_t)bat * CH + row) * CH;
    const int tid = threadIdx.x;
    __shared__ float red[4];

    float v[4];
    float mn = 1e30f;
#pragma unroll
    for (int i = 0; i < 4; ++i) {
        float s = 0.f;
#pragma unroll
        for (int sp = 0; sp < NSPLIT; ++sp)
            s += base[(size_t)sp * CH * CH + tid + i * 128];
        v[i] = s;
        mn = fminf(mn, s);
    }
#pragma unroll
    for (int o2 = 16; o2; o2 >>= 1) mn = fminf(mn, __shfl_xor_sync(~0u, mn, o2));
    if ((tid & 31) == 0) red[tid >> 5] = mn;
    __syncthreads();
    mn = fminf(fminf(red[0], red[1]), fminf(red[2], red[3]));

    float s = 0.f;
#pragma unroll
    for (int i = 0; i < 4; ++i) { v[i] = expf(mn - v[i]); s += v[i]; }
#pragma unroll
    for (int o2 = 16; o2; o2 >>= 1) s += __shfl_xor_sync(~0u, s, o2);
    __syncthreads();
    if ((tid & 31) == 0) red[tid >> 5] = s;
    __syncthreads();
    s = red[0] + red[1] + red[2] + red[3];
    float inv = 1.f / s;
#pragma unroll
    for (int i = 0; i < 4; ++i) o[tid + i * 128] = __float2bfloat16(v[i] * inv);
}

// ---------------------------------------------------------------------------
// Launcher
// ---------------------------------------------------------------------------
extern "C" void kernel_launch(void* const* d_in, const int* in_sizes, int n_in,
                              void* d_out, int out_size)
{
    const float* x  = (const float*)d_in[0];
    const float* wq = (const float*)d_in[1];
    const float* bq = (const float*)d_in[2];
    const float* wk = (const float*)d_in[3];
    const float* bk = (const float*)d_in[4];
    const float* wv = (const float*)d_in[5];
    const float* bv = (const float*)d_in[6];
    const float* gp = (const float*)d_in[7];
    const float* gc = (const float*)d_in[8];
    const float* al = (const float*)d_in[9];
    const float* be = (const float*)d_in[10];
    float* out = (float*)d_out;

    float *energy, *xb, *xbt, *qkt, *pos, *gramp;
    bf16 *xbt_b, *vb, *attcb;
    float *wqk, *bqk, *wvr;
    cudaGetSymbolAddress((void**)&energy, g_energy);
    cudaGetSymbolAddress((void**)&xb,    g_xb);
    cudaGetSymbolAddress((void**)&xbt,   g_xbt);
    cudaGetSymbolAddress((void**)&xbt_b, g_xbt_b);
    cudaGetSymbolAddress((void**)&vb,    g_vb);
    cudaGetSymbolAddress((void**)&qkt,   g_qkt);
    cudaGetSymbolAddress((void**)&pos,   g_pos);
    cudaGetSymbolAddress((void**)&gramp, g_gramp);
    cudaGetSymbolAddress((void**)&attcb, g_attcb);
    cudaGetSymbolAddress((void**)&wqk,   g_wqk);
    cudaGetSymbolAddress((void**)&bqk,   g_bqk);
    cudaGetSymbolAddress((void**)&wvr,   g_wvr);

    const long long sX   = (long long)CH * NN;
    const long long sXT  = (long long)NN * CH;
    const long long sQK  = (long long)NN * 128;
    const long long sAtt = (long long)NN * NN;
    const long long sGr  = (long long)CH * CH;

    const int SMEM = 98304;
    static bool attr_done = false;
    if (!attr_done) {
        cudaFuncSetAttribute(mma_gemm<2, true>,  cudaFuncAttributeMaxDynamicSharedMemorySize, SMEM);
        cudaFuncSetAttribute(mma_gemm<4, true>,  cudaFuncAttributeMaxDynamicSharedMemorySize, SMEM);
        cudaFuncSetAttribute(mma_gemm<0, false>, cudaFuncAttributeMaxDynamicSharedMemorySize, SMEM);
        attr_done = true;
    }

    // 1) conversions / weight prep
    convert_x_k<<<dim3(NN / 32, CH / 32, BDIM), dim3(32, 8)>>>(x, xb, xbt, xbt_b);
    prep_weights_k<<<(CH * CH + 255) / 256, 256>>>(wq, wk, bq, bk, wv, wqk, bqk, wvr);

    // 2) fused q|k projection -> qkt[n][128] (tf32, transposed, +bias)
    mma_gemm<2, true><<<dim3(NN / 256, 1, BDIM), 256, SMEM>>>(
        wqk, xbt, qkt, bqk, 128, NN, CH, CH, CH, 1, 0, sXT, sQK);

    // 3) v projection -> vb[c][n] bf16 (+bias)
    mma_gemm<4, true><<<dim3(NN / 256, CH / 128, BDIM), 256, SMEM>>>(
        wvr, xbt, (float*)vb, bv, CH, NN, CH, CH, CH, 1, 0, sXT, sX);

    // 4) energy[i,j] = sum_d q[i,d] k[j,d]
    mma_gemm<0, false><<<dim3(NN / 256, NN / 128, BDIM), 256, SMEM>>>(
        qkt, qkt + 64, energy, nullptr, NN, NN, CQ, 128, 128, 1, sQK, sQK, sAtt);

    // 5) softmax rows -> bf16 att in place (row stride 2*NN bf16)
    softmax_pos<<<dim3(NN, BDIM), 256>>>(energy);

    // 6) pos[c,i] = sum_j v[c,j] att[i,j]  (bf16 GEMM)
    bf_gemm<0><<<dim3(NN / 256, CH / 128, BDIM), 256>>>(
        vb, (const bf16*)energy, pos, CH, NN, NN, NN, 2 * NN, sX, 2 * sAtt, sX,
        nullptr, nullptr, 0, nullptr, nullptr, nullptr, nullptr);

    // 7) gram split-K parts (tf32)
    mma_gemm<0, false><<<dim3(CH / 256, CH / 128, BDIM * NSPLIT), 256, SMEM>>>(
        xb, xb, gramp, nullptr, CH, CH, NN / NSPLIT, NN, NN, NSPLIT, sX, sX, sGr);

    // 8) channel softmax + fused part-reduction -> bf16 att_c
    softmax_chan<<<dim3(CH, BDIM), 128>>>(gramp, attcb);

    // 9) out = a*gp*pos + b*gc*(att_c @ x) + (a+b+1)*x  (bf16 GEMM, combine)
    bf_gemm<3><<<dim3(NN / 256, CH / 128, BDIM), 256>>>(
        attcb, xbt_b, out, CH, NN, CH, CH, CH, sGr, sXT, sX,
        pos, x, sX, al, be, gp, gc);
}

// round 10
// speedup vs baseline: 8.2753x; 1.0169x over previous
#include <cuda_runtime.h>
#include <cuda_bf16.h>
#include <cstdint>

#define BDIM 2
#define CH   512
#define CQ   64
#define NN   4096
#define NSPLIT 8

typedef __nv_bfloat16 bf16;

// ---------------------------------------------------------------------------
// Scratch. bf16 att lives IN PLACE in the first half of each fp32 energy row.
// ---------------------------------------------------------------------------
__device__ __align__(256) float g_energy[(size_t)BDIM * NN * NN];
__device__ __align__(256) float g_xb    [(size_t)BDIM * CH * NN];     // tf32 c-major
__device__ __align__(256) float g_xbt   [(size_t)BDIM * NN * CH];     // tf32 n-major
__device__ __align__(256) bf16  g_xbt_b [(size_t)BDIM * NN * CH];     // bf16 n-major
__device__ __align__(256) bf16  g_vb    [(size_t)BDIM * CH * NN];
__device__ __align__(256) bf16  g_qkt   [(size_t)BDIM * NN * 128];    // bf16 [n][q|k]
__device__ __align__(256) float g_pos   [(size_t)BDIM * CH * NN];
__device__ __align__(256) float g_gramp [(size_t)BDIM * NSPLIT * CH * CH];
__device__ __align__(256) bf16  g_attcb [(size_t)BDIM * CH * CH];
__device__ __align__(256) float g_wqk [128 * CH];
__device__ __align__(256) float g_bqk [128];
__device__ __align__(256) float g_wvr [CH * CH];

// ---------------------------------------------------------------------------
__device__ __forceinline__ uint32_t smem_u32(const void* p) {
    uint32_t a;
    asm("{ .reg .u64 t; cvta.to.shared.u64 t, %1; cvt.u32.u64 %0, t; }"
        : "=r"(a) : "l"(p));
    return a;
}
__device__ __forceinline__ float tf32r(float x) {
    uint32_t u;
    asm("cvt.rna.tf32.f32 %0, %1;" : "=r"(u) : "f"(x));
    return __uint_as_float(u);
}

#define CP_ASYNC16(dst, src, sz) \
    asm volatile("cp.async.cg.shared.global [%0], [%1], 16, %2;" \
                 :: "r"(dst), "l"(src), "r"(sz))
#define CP_COMMIT() asm volatile("cp.async.commit_group;")
#define CP_WAIT(N)  asm volatile("cp.async.wait_group %0;" :: "n"(N))

#define MMA1688(d, a, b) \
    asm volatile("mma.sync.aligned.m16n8k8.row.col.f32.tf32.tf32.f32 " \
                 "{%0,%1,%2,%3}, {%4,%5,%6,%7}, {%8,%9}, {%0,%1,%2,%3};" \
                 : "+f"((d)[0]), "+f"((d)[1]), "+f"((d)[2]), "+f"((d)[3]) \
                 : "r"((a)[0]), "r"((a)[1]), "r"((a)[2]), "r"((a)[3]), \
                   "r"((b)[0]), "r"((b)[1]))

#define MMA16816(d, a, b) \
    asm volatile("mma.sync.aligned.m16n8k16.row.col.f32.bf16.bf16.f32 " \
                 "{%0,%1,%2,%3}, {%4,%5,%6,%7}, {%8,%9}, {%0,%1,%2,%3};" \
                 : "+f"((d)[0]), "+f"((d)[1]), "+f"((d)[2]), "+f"((d)[3]) \
                 : "r"((a)[0]), "r"((a)[1]), "r"((a)[2]), "r"((a)[3]), \
                   "r"((b)[0]), "r"((b)[1]))

#define LDSM4(R, addr) \
    asm volatile("ldmatrix.sync.aligned.m8n8.x4.shared.b16 {%0,%1,%2,%3}, [%4];" \
                 : "=r"((R)[0]), "=r"((R)[1]), "=r"((R)[2]), "=r"((R)[3]) \
                 : "r"(addr))

__device__ __forceinline__ int swzc(int r, int c) {
    return (c ^ (r & 3) ^ ((r >> 2) & 1)) & 3;
}

// ---------------------------------------------------------------------------
// tf32 GEMM, BM128 x BN256 x BK32, 3-stage cp.async pipeline, 1 sync/iter.
// OM: 0=f32 row-major, 4=bf16 row-major, 5=bf16 transposed (C[n*M+m])
// ---------------------------------------------------------------------------
template <int OM, bool HAS_BIAS>
__global__ __launch_bounds__(256)
void mma_gemm(const float* __restrict__ A, const float* __restrict__ B,
              float* __restrict__ Cout, const float* __restrict__ bias,
              int Mrows, int Nrows, int K, int lda, int ldb, int nsplit,
              long long sA, long long sB, long long sC)
{
    extern __shared__ __align__(128) uint8_t smem[];   // 3 * 48 KB

    const int tid  = threadIdx.x;
    const int lane = tid & 31;
    const int warp = tid >> 5;
    const int mw   = warp >> 2;
    const int nw   = warp & 3;
    const int z    = blockIdx.z;
    const int bat  = z / nsplit;
    const int sp   = z - bat * nsplit;
    const int m0   = blockIdx.y * 128;
    const int n0   = blockIdx.x * 256;

    A += (long long)bat * sA + (long long)sp * K;
    B += (long long)bat * sB + (long long)sp * K;

    const uint32_t sbase = smem_u32(smem);
    const int KI = K >> 5;

    auto load_tile = [&](int it) {
        const int k0 = it << 5;
        const uint32_t st = sbase + (uint32_t)(it % 3) * 49152;
#pragma unroll
        for (int i = 0; i < 12; ++i) {
            int idx = tid + i * 256;
            if (idx < 1024) {
                int r = idx >> 3, c = idx & 7;
                int grow = m0 + r;
                int ok = (grow < Mrows);
                const float* src = A + (long long)(ok ? grow : 0) * lda + k0 + c * 4;
                uint32_t dst = st + r * 128 + ((c ^ (r & 7)) << 4);
                CP_ASYNC16(dst, src, ok ? 16 : 0);
            } else {
                int bi = idx - 1024;
                int r = bi >> 3, c = bi & 7;
                int grow = n0 + r;
                int ok = (grow < Nrows);
                const float* src = B + (long long)(ok ? grow : 0) * ldb + k0 + c * 4;
                uint32_t dst = st + 16384 + r * 128 + ((c ^ (r & 7)) << 4);
                CP_ASYNC16(dst, src, ok ? 16 : 0);
            }
        }
    };

    float acc[4][8][4];
#pragma unroll
    for (int i = 0; i < 4; ++i)
#pragma unroll
        for (int j = 0; j < 8; ++j)
#pragma unroll
            for (int r = 0; r < 4; ++r) acc[i][j][r] = 0.f;

    load_tile(0); CP_COMMIT();
    if (KI > 1) { load_tile(1); CP_COMMIT(); }

    const int g  = lane >> 2;
    const int tq = lane & 3;

    for (int it = 0; it < KI; ++it) {
        if (it + 1 < KI) CP_WAIT(1); else CP_WAIT(0);
        __syncthreads();
        if (it + 2 < KI) { load_tile(it + 2); CP_COMMIT(); }

        const uint8_t* aP = smem + (it % 3) * 49152;
        const uint8_t* bP = aP + 16384;
        auto LDF = [&](const uint8_t* base, int r, int k) -> uint32_t {
            int off = r * 128 + (((k >> 2) ^ (r & 7)) << 4) + (k & 3) * 4;
            return *(const uint32_t*)(base + off);
        };

#pragma unroll
        for (int ks = 0; ks < 4; ++ks) {
            const int kb = ks * 8;
            uint32_t a[4][4];
#pragma unroll
            for (int mi = 0; mi < 4; ++mi) {
                int r0 = mw * 64 + mi * 16 + g;
                a[mi][0] = LDF(aP, r0,     kb + tq);
                a[mi][1] = LDF(aP, r0 + 8, kb + tq);
                a[mi][2] = LDF(aP, r0,     kb + tq + 4);
                a[mi][3] = LDF(aP, r0 + 8, kb + tq + 4);
            }
            uint32_t b[8][2];
#pragma unroll
            for (int ni = 0; ni < 8; ++ni) {
                int rn = nw * 64 + ni * 8 + g;
                b[ni][0] = LDF(bP, rn, kb + tq);
                b[ni][1] = LDF(bP, rn, kb + tq + 4);
            }
#pragma unroll
            for (int mi = 0; mi < 4; ++mi)
#pragma unroll
                for (int ni = 0; ni < 8; ++ni)
                    MMA1688(acc[mi][ni], a[mi], b[ni]);
        }
    }

    float* C  = Cout + (long long)z * sC;
    bf16*  Cb = (bf16*)Cout + (long long)z * sC;

#pragma unroll
    for (int mi = 0; mi < 4; ++mi) {
#pragma unroll
        for (int half = 0; half < 2; ++half) {
            int m = m0 + mw * 64 + mi * 16 + g + half * 8;
            if (m >= Mrows) continue;
            float bv = HAS_BIAS ? bias[m] : 0.f;
#pragma unroll
            for (int ni = 0; ni < 8; ++ni) {
                int n = n0 + nw * 64 + ni * 8 + tq * 2;
                float v0 = acc[mi][ni][half * 2 + 0] + bv;
                float v1 = acc[mi][ni][half * 2 + 1] + bv;
                if (OM == 5) {
                    if (n < Nrows)     Cb[(long long)n * Mrows + m]       = __float2bfloat16(v0);
                    if (n + 1 < Nrows) Cb[(long long)(n + 1) * Mrows + m] = __float2bfloat16(v1);
                } else if (OM == 4) {
                    if (n + 1 < Nrows) {
                        uint32_t pk = ((uint32_t)__bfloat16_as_ushort(__float2bfloat16(v1)) << 16)
                                    | (uint32_t)__bfloat16_as_ushort(__float2bfloat16(v0));
                        *(uint32_t*)&Cb[(long long)m * Nrows + n] = pk;
                    } else if (n < Nrows) {
                        Cb[(long long)m * Nrows + n] = __float2bfloat16(v0);
                    }
                } else {
                    if (n + 1 < Nrows)
                        *(float2*)&C[(long long)m * Nrows + n] = make_float2(v0, v1);
                    else if (n < Nrows)
                        C[(long long)m * Nrows + n] = v0;
                }
            }
        }
    }
}

// ---------------------------------------------------------------------------
// bf16 GEMM, BM128 x BN256 x BK32, ldmatrix + m16n8k16, 3-stage pipeline.
// OM: 0 = f32 row-major, 3 = combine epilogue
// ---------------------------------------------------------------------------
template <int OM>
__global__ __launch_bounds__(256)
void bf_gemm(const bf16* __restrict__ A, const bf16* __restrict__ B,
             float* __restrict__ Cout,
             int Mrows, int Nrows, int K, int lda, int ldb,
             long long sA, long long sB, long long sC,
             const float* __restrict__ P, const float* __restrict__ X,
             long long sPX,
             const float* __restrict__ s_alpha, const float* __restrict__ s_beta,
             const float* __restrict__ s_gp, const float* __restrict__ s_gc)
{
    extern __shared__ __align__(128) uint8_t smem[];   // 3 * 24 KB

    const int tid  = threadIdx.x;
    const int lane = tid & 31;
    const int warp = tid >> 5;
    const int mw   = warp >> 2;
    const int nw   = warp & 3;
    const int z    = blockIdx.z;
    const int m0   = blockIdx.y * 128;
    const int n0   = blockIdx.x * 256;

    A += (long long)z * sA;
    B += (long long)z * sB;

    const uint32_t sbase = smem_u32(smem);
    const int KI = K >> 5;

    auto load_tile = [&](int it) {
        const int k0 = it << 5;
        const uint32_t st = sbase + (uint32_t)(it % 3) * 24576;
#pragma unroll
        for (int i = 0; i < 6; ++i) {
            int idx = tid + i * 256;
            if (idx < 512) {
                int r = idx >> 2, c = idx & 3;
                int grow = m0 + r;
                int ok = (grow < Mrows);
                const bf16* src = A + (long long)(ok ? grow : 0) * lda + k0 + c * 8;
                uint32_t dst = st + r * 64 + swzc(r, c) * 16;
                CP_ASYNC16(dst, src, ok ? 16 : 0);
            } else {
                int bi = idx - 512;
                int r = bi >> 2, c = bi & 3;
                int grow = n0 + r;
                int ok = (grow < Nrows);
                const bf16* src = B + (long long)(ok ? grow : 0) * ldb + k0 + c * 8;
                uint32_t dst = st + 8192 + r * 64 + swzc(r, c) * 16;
                CP_ASYNC16(dst, src, ok ? 16 : 0);
            }
        }
    };

    float acc[4][8][4];
#pragma unroll
    for (int i = 0; i < 4; ++i)
#pragma unroll
        for (int j = 0; j < 8; ++j)
#pragma unroll
            for (int r = 0; r < 4; ++r) acc[i][j][r] = 0.f;

    load_tile(0); CP_COMMIT();
    if (KI > 1) { load_tile(1); CP_COMMIT(); }

    const int sub  = lane >> 3;
    const int lrow = lane & 7;

    for (int it = 0; it < KI; ++it) {
        if (it + 1 < KI) CP_WAIT(1); else CP_WAIT(0);
        __syncthreads();
        if (it + 2 < KI) { load_tile(it + 2); CP_COMMIT(); }

        const uint32_t aB = sbase + (uint32_t)(it % 3) * 24576;
        const uint32_t bB = aB + 8192;

#pragma unroll
        for (int ks = 0; ks < 2; ++ks) {
            uint32_t a[4][4];
#pragma unroll
            for (int mi = 0; mi < 4; ++mi) {
                int row = mw * 64 + mi * 16 + (sub & 1) * 8 + lrow;
                int kc  = ks * 2 + (sub >> 1);
                uint32_t addr = aB + row * 64 + swzc(row, kc) * 16;
                LDSM4(a[mi], addr);
            }
            uint32_t b[8][2];
#pragma unroll
            for (int p = 0; p < 4; ++p) {
                int row = nw * 64 + p * 16 + (sub >> 1) * 8 + lrow;
                int kc  = ks * 2 + (sub & 1);
                uint32_t addr = bB + row * 64 + swzc(row, kc) * 16;
                uint32_t t[4];
                LDSM4(t, addr);
                b[2 * p][0]     = t[0];
                b[2 * p][1]     = t[1];
                b[2 * p + 1][0] = t[2];
                b[2 * p + 1][1] = t[3];
            }
#pragma unroll
            for (int mi = 0; mi < 4; ++mi)
#pragma unroll
                for (int ni = 0; ni < 8; ++ni)
                    MMA16816(acc[mi][ni], a[mi], b[ni]);
        }
    }

    float c1 = 0.f, c2 = 1.f, c3 = 0.f;
    if (OM == 3) {
        float al = *s_alpha, be = *s_beta;
        c1 = al * (*s_gp);
        c2 = be * (*s_gc);
        c3 = al + be + 1.f;
        P += (long long)z * sPX;
        X += (long long)z * sPX;
    }
    float* C = Cout + (long long)z * sC;

    const int g  = lane >> 2;
    const int tq = lane & 3;

#pragma unroll
    for (int mi = 0; mi < 4; ++mi) {
#pragma unroll
        for (int half = 0; half < 2; ++half) {
            int m = m0 + mw * 64 + mi * 16 + g + half * 8;
            if (m >= Mrows) continue;
#pragma unroll
            for (int ni = 0; ni < 8; ++ni) {
                int n = n0 + nw * 64 + ni * 8 + tq * 2;
                float v0 = acc[mi][ni][half * 2 + 0];
                float v1 = acc[mi][ni][half * 2 + 1];
                if (n + 1 < Nrows) {
                    long long idx = (long long)m * Nrows + n;
                    if (OM == 0) {
                        *(float2*)&C[idx] = make_float2(v0, v1);
                    } else {
                        C[idx]     = c1 * P[idx]     + c2 * v0 + c3 * X[idx];
                        C[idx + 1] = c1 * P[idx + 1] + c2 * v1 + c3 * X[idx + 1];
                    }
                } else if (n < Nrows) {
                    long long idx = (long long)m * Nrows + n;
                    if (OM == 0) C[idx] = v0;
                    else         C[idx] = c1 * P[idx] + c2 * v0 + c3 * X[idx];
                }
            }
        }
    }
}

// ---------------------------------------------------------------------------
__global__ __launch_bounds__(256)
void convert_x_k(const float* __restrict__ x, float* __restrict__ xb,
                 float* __restrict__ xbt, bf16* __restrict__ xbt_b)
{
    __shared__ float t[32][33];
    const int z = blockIdx.z;
    const float* xp = x + (size_t)z * CH * NN;
    float* xbp = xb + (size_t)z * CH * NN;
    float* xtp = xbt + (size_t)z * NN * CH;
    bf16*  xtb = xbt_b + (size_t)z * NN * CH;
    const int n0 = blockIdx.x * 32, c0 = blockIdx.y * 32;
    const int tx = threadIdx.x, ty = threadIdx.y;
#pragma unroll
    for (int k = 0; k < 4; ++k) {
        int c = ty + k * 8;
        float raw = xp[(size_t)(c0 + c) * NN + n0 + tx];
        t[c][tx] = raw;
        xbp[(size_t)(c0 + c) * NN + n0 + tx] = tf32r(raw);
    }
    __syncthreads();
#pragma unroll
    for (int k = 0; k < 4; ++k) {
        int n = ty + k * 8;
        float raw = t[tx][n];
        xtp[(size_t)(n0 + n) * CH + c0 + tx] = tf32r(raw);
        xtb[(size_t)(n0 + n) * CH + c0 + tx] = __float2bfloat16(raw);
    }
}

__global__ __launch_bounds__(256)
void prep_weights_k(const float* __restrict__ wq, const float* __restrict__ wk,
                    const float* __restrict__ bq, const float* __restrict__ bk,
                    const float* __restrict__ wv,
                    float* __restrict__ wqk, float* __restrict__ bqk,
                    float* __restrict__ wvr)
{
    int i = blockIdx.x * 256 + threadIdx.x;
    if (i < 128 * CH) {
        int row = i >> 9;
        float v = (row < 64) ? wq[i] : wk[i - 64 * CH];
        wqk[i] = tf32r(v);
    }
    if (i < 128) bqk[i] = (i < 64) ? bq[i] : bk[i - 64];
    if (i < CH * CH) wvr[i] = tf32r(wv[i]);
}

// ---------------------------------------------------------------------------
// Row softmax, fp32 in, bf16 out IN PLACE (first half of each fp32 row).
// ---------------------------------------------------------------------------
__global__ __launch_bounds__(256)
void softmax_pos(float* __restrict__ energy)
{
    const long long row = (long long)blockIdx.y * NN + blockIdx.x;
    float* p = energy + row * NN;
    bf16*  ob = (bf16*)p;
    const int tid = threadIdx.x;
    __shared__ float red[8];

    float v[16];
    float mx = -1e30f;
#pragma unroll
    for (int i = 0; i < 16; ++i) {
        v[i] = p[tid + i * 256];
        mx = fmaxf(mx, v[i]);
    }
#pragma unroll
    for (int o2 = 16; o2; o2 >>= 1) mx = fmaxf(mx, __shfl_xor_sync(~0u, mx, o2));
    if ((tid & 31) == 0) red[tid >> 5] = mx;
    __syncthreads();
    mx = red[0];
#pragma unroll
    for (int i = 1; i < 8; ++i) mx = fmaxf(mx, red[i]);

    float s = 0.f;
#pragma unroll
    for (int i = 0; i < 16; ++i) { v[i] = expf(v[i] - mx); s += v[i]; }
#pragma unroll
    for (int o2 = 16; o2; o2 >>= 1) s += __shfl_xor_sync(~0u, s, o2);
    __syncthreads();
    if ((tid & 31) == 0) red[tid >> 5] = s;
    __syncthreads();
    s = 0.f;
#pragma unroll
    for (int i = 0; i < 8; ++i) s += red[i];
    float inv = 1.f / s;
#pragma unroll
    for (int i = 0; i < 16; ++i) ob[tid + i * 256] = __float2bfloat16(v[i] * inv);
}

// ---------------------------------------------------------------------------
__global__ __launch_bounds__(128)
void softmax_chan(const float* __restrict__ gramp, bf16* __restrict__ attcb)
{
    const int bat = blockIdx.y;
    const int row = blockIdx.x;
    const float* base = gramp + ((size_t)bat * NSPLIT) * CH * CH + (size_t)row * CH;
    bf16* o = attcb + ((size_t)bat * CH + row) * CH;
    const int tid = threadIdx.x;
    __shared__ float red[4];

    float v[4];
    float mn = 1e30f;
#pragma unroll
    for (int i = 0; i < 4; ++i) {
        float s = 0.f;
#pragma unroll
        for (int sp = 0; sp < NSPLIT; ++sp)
            s += base[(size_t)sp * CH * CH + tid + i * 128];
        v[i] = s;
        mn = fminf(mn, s);
    }
#pragma unroll
    for (int o2 = 16; o2; o2 >>= 1) mn = fminf(mn, __shfl_xor_sync(~0u, mn, o2));
    if ((tid & 31) == 0) red[tid >> 5] = mn;
    __syncthreads();
    mn = fminf(fminf(red[0], red[1]), fminf(red[2], red[3]));

    float s = 0.f;
#pragma unroll
    for (int i = 0; i < 4; ++i) { v[i] = expf(mn - v[i]); s += v[i]; }
#pragma unroll
    for (int o2 = 16; o2; o2 >>= 1) s += __shfl_xor_sync(~0u, s, o2);
    __syncthreads();
    if ((tid & 31) == 0) red[tid >> 5] = s;
    __syncthreads();
    s = red[0] + red[1] + red[2] + red[3];
    float inv = 1.f / s;
#pragma unroll
    for (int i = 0; i < 4; ++i) o[tid + i * 128] = __float2bfloat16(v[i] * inv);
}

// ---------------------------------------------------------------------------
extern "C" void kernel_launch(void* const* d_in, const int* in_sizes, int n_in,
                              void* d_out, int out_size)
{
    const float* x  = (const float*)d_in[0];
    const float* wq = (const float*)d_in[1];
    const float* bq = (const float*)d_in[2];
    const float* wk = (const float*)d_in[3];
    const float* bk = (const float*)d_in[4];
    const float* wv = (const float*)d_in[5];
    const float* bv = (const float*)d_in[6];
    const float* gp = (const float*)d_in[7];
    const float* gc = (const float*)d_in[8];
    const float* al = (const float*)d_in[9];
    const float* be = (const float*)d_in[10];
    float* out = (float*)d_out;

    float *energy, *xb, *xbt, *pos, *gramp;
    bf16 *xbt_b, *vb, *qkt, *attcb;
    float *wqk, *bqk, *wvr;
    cudaGetSymbolAddress((void**)&energy, g_energy);
    cudaGetSymbolAddress((void**)&xb,    g_xb);
    cudaGetSymbolAddress((void**)&xbt,   g_xbt);
    cudaGetSymbolAddress((void**)&xbt_b, g_xbt_b);
    cudaGetSymbolAddress((void**)&vb,    g_vb);
    cudaGetSymbolAddress((void**)&qkt,   g_qkt);
    cudaGetSymbolAddress((void**)&pos,   g_pos);
    cudaGetSymbolAddress((void**)&gramp, g_gramp);
    cudaGetSymbolAddress((void**)&attcb, g_attcb);
    cudaGetSymbolAddress((void**)&wqk,   g_wqk);
    cudaGetSymbolAddress((void**)&bqk,   g_bqk);
    cudaGetSymbolAddress((void**)&wvr,   g_wvr);

    const long long sX   = (long long)CH * NN;
    const long long sXT  = (long long)NN * CH;
    const long long sQK  = (long long)NN * 128;
    const long long sAtt = (long long)NN * NN;
    const long long sGr  = (long long)CH * CH;

    const int SMEM_T = 3 * 49152;   // tf32 kernel
    const int SMEM_B = 3 * 24576;   // bf16 kernel
    static bool attr_done = false;
    if (!attr_done) {
        cudaFuncSetAttribute(mma_gemm<5, true>,  cudaFuncAttributeMaxDynamicSharedMemorySize, SMEM_T);
        cudaFuncSetAttribute(mma_gemm<4, true>,  cudaFuncAttributeMaxDynamicSharedMemorySize, SMEM_T);
        cudaFuncSetAttribute(mma_gemm<0, false>, cudaFuncAttributeMaxDynamicSharedMemorySize, SMEM_T);
        cudaFuncSetAttribute(bf_gemm<0>, cudaFuncAttributeMaxDynamicSharedMemorySize, SMEM_B);
        cudaFuncSetAttribute(bf_gemm<3>, cudaFuncAttributeMaxDynamicSharedMemorySize, SMEM_B);
        attr_done = true;
    }

    // 1) conversions / weight prep
    convert_x_k<<<dim3(NN / 32, CH / 32, BDIM), dim3(32, 8)>>>(x, xb, xbt, xbt_b);
    prep_weights_k<<<(CH * CH + 255) / 256, 256>>>(wq, wk, bq, bk, wv, wqk, bqk, wvr);

    // 2) fused q|k projection -> qkt[n][128] bf16 (transposed, +bias)
    mma_gemm<5, true><<<dim3(NN / 256, 1, BDIM), 256, SMEM_T>>>(
        wqk, xbt, (float*)qkt, bqk, 128, NN, CH, CH, CH, 1, 0, sXT, sQK);

    // 3) v projection -> vb[c][n] bf16 (+bias)
    mma_gemm<4, true><<<dim3(NN / 256, CH / 128, BDIM), 256, SMEM_T>>>(
        wvr, xbt, (float*)vb, bv, CH, NN, CH, CH, CH, 1, 0, sXT, sX);

    // 4) energy[i,j] = sum_d q[i,d] k[j,d]  (bf16 GEMM, fp32 out)
    bf_gemm<0><<<dim3(NN / 256, NN / 128, BDIM), 256, SMEM_B>>>(
        qkt, qkt + 64, energy, NN, NN, CQ, 128, 128, sQK, sQK, sAtt,
        nullptr, nullptr, 0, nullptr, nullptr, nullptr, nullptr);

    // 5) softmax rows -> bf16 att in place
    softmax_pos<<<dim3(NN, BDIM), 256>>>(energy);

    // 6) pos[c,i] = sum_j v[c,j] att[i,j]  (bf16 GEMM)
    bf_gemm<0><<<dim3(NN / 256, CH / 128, BDIM), 256, SMEM_B>>>(
        vb, (const bf16*)energy, pos, CH, NN, NN, NN, 2 * NN, sX, 2 * sAtt, sX,
        nullptr, nullptr, 0, nullptr, nullptr, nullptr, nullptr);

    // 7) gram split-K parts (tf32)
    mma_gemm<0, false><<<dim3(CH / 256, CH / 128, BDIM * NSPLIT), 256, SMEM_T>>>(
        xb, xb, gramp, nullptr, CH, CH, NN / NSPLIT, NN, NN, NSPLIT, sX, sX, sGr);

    // 8) channel softmax + fused part-reduction -> bf16 att_c
    softmax_chan<<<dim3(CH, BDIM), 128>>>(gramp, attcb);

    // 9) out = a*gp*pos + b*gc*(att_c @ x) + (a+b+1)*x  (bf16 GEMM, combine)
    bf_gemm<3><<<dim3(NN / 256, CH / 128, BDIM), 256, SMEM_B>>>(
        attcb, xbt_b, out, CH, NN, CH, CH, CH, sGr, sXT, sX,
        pos, x, sX, al, be, gp, gc);
}

// round 11
// speedup vs baseline: 9.1491x; 1.1056x over previous
#include <cuda_runtime.h>
#include <cuda_bf16.h>
#include <cuda_fp16.h>
#include <cstdint>

#define BDIM 2
#define CH   512
#define CQ   64
#define NN   4096
#define NSPLIT 8

typedef __nv_bfloat16 bf16;

// ---------------------------------------------------------------------------
// Scratch. g_energy is fp16; softmax overwrites it in place with bf16 att.
// ---------------------------------------------------------------------------
__device__ __align__(256) __half g_energy[(size_t)BDIM * NN * NN];   // 67 MB
__device__ __align__(256) float g_xb    [(size_t)BDIM * CH * NN];    // tf32 c-major (gram)
__device__ __align__(256) bf16  g_xbt_b [(size_t)BDIM * NN * CH];    // bf16 n-major
__device__ __align__(256) bf16  g_vb    [(size_t)BDIM * CH * NN];
__device__ __align__(256) bf16  g_qkt   [(size_t)BDIM * NN * 128];   // bf16 [n][q|k]
__device__ __align__(256) float g_pos   [(size_t)BDIM * CH * NN];
__device__ __align__(256) float g_gramp [(size_t)BDIM * NSPLIT * CH * CH];
__device__ __align__(256) bf16  g_attcb [(size_t)BDIM * CH * CH];
__device__ __align__(256) bf16  g_wqk [128 * CH];
__device__ __align__(256) float g_bqk [128];
__device__ __align__(256) bf16  g_wvr [CH * CH];

// ---------------------------------------------------------------------------
__device__ __forceinline__ uint32_t smem_u32(const void* p) {
    uint32_t a;
    asm("{ .reg .u64 t; cvta.to.shared.u64 t, %1; cvt.u32.u64 %0, t; }"
        : "=r"(a) : "l"(p));
    return a;
}
__device__ __forceinline__ float tf32r(float x) {
    uint32_t u;
    asm("cvt.rna.tf32.f32 %0, %1;" : "=r"(u) : "f"(x));
    return __uint_as_float(u);
}

#define CP_ASYNC16(dst, src, sz) \
    asm volatile("cp.async.cg.shared.global [%0], [%1], 16, %2;" \
                 :: "r"(dst), "l"(src), "r"(sz))
#define CP_COMMIT() asm volatile("cp.async.commit_group;")
#define CP_WAIT(N)  asm volatile("cp.async.wait_group %0;" :: "n"(N))

#define MMA1688(d, a, b) \
    asm volatile("mma.sync.aligned.m16n8k8.row.col.f32.tf32.tf32.f32 " \
                 "{%0,%1,%2,%3}, {%4,%5,%6,%7}, {%8,%9}, {%0,%1,%2,%3};" \
                 : "+f"((d)[0]), "+f"((d)[1]), "+f"((d)[2]), "+f"((d)[3]) \
                 : "r"((a)[0]), "r"((a)[1]), "r"((a)[2]), "r"((a)[3]), \
                   "r"((b)[0]), "r"((b)[1]))

#define MMA16816(d, a, b) \
    asm volatile("mma.sync.aligned.m16n8k16.row.col.f32.bf16.bf16.f32 " \
                 "{%0,%1,%2,%3}, {%4,%5,%6,%7}, {%8,%9}, {%0,%1,%2,%3};" \
                 : "+f"((d)[0]), "+f"((d)[1]), "+f"((d)[2]), "+f"((d)[3]) \
                 : "r"((a)[0]), "r"((a)[1]), "r"((a)[2]), "r"((a)[3]), \
                   "r"((b)[0]), "r"((b)[1]))

#define LDSM4(R, addr) \
    asm volatile("ldmatrix.sync.aligned.m8n8.x4.shared.b16 {%0,%1,%2,%3}, [%4];" \
                 : "=r"((R)[0]), "=r"((R)[1]), "=r"((R)[2]), "=r"((R)[3]) \
                 : "r"(addr))

__device__ __forceinline__ int swzc(int r, int c) {
    return (c ^ (r & 3) ^ ((r >> 2) & 1)) & 3;
}

// ---------------------------------------------------------------------------
// tf32 GEMM (gram only). BM128 x BN256 x BK32, 3-stage pipeline.
// ---------------------------------------------------------------------------
__global__ __launch_bounds__(256)
void tf_gemm(const float* __restrict__ A, const float* __restrict__ B,
             float* __restrict__ Cout,
             int Mrows, int Nrows, int K, int lda, int ldb, int nsplit,
             long long sA, long long sB, long long sC)
{
    extern __shared__ __align__(128) uint8_t smem[];

    const int tid  = threadIdx.x;
    const int lane = tid & 31;
    const int warp = tid >> 5;
    const int mw   = warp >> 2;
    const int nw   = warp & 3;
    const int z    = blockIdx.z;
    const int bat  = z / nsplit;
    const int sp   = z - bat * nsplit;
    const int m0   = blockIdx.y * 128;
    const int n0   = blockIdx.x * 256;

    A += (long long)bat * sA + (long long)sp * K;
    B += (long long)bat * sB + (long long)sp * K;

    const uint32_t sbase = smem_u32(smem);
    const int KI = K >> 5;

    auto load_tile = [&](int it) {
        const int k0 = it << 5;
        const uint32_t st = sbase + (uint32_t)(it % 3) * 49152;
#pragma unroll
        for (int i = 0; i < 12; ++i) {
            int idx = tid + i * 256;
            if (idx < 1024) {
                int r = idx >> 3, c = idx & 7;
                int grow = m0 + r;
                int ok = (grow < Mrows);
                const float* src = A + (long long)(ok ? grow : 0) * lda + k0 + c * 4;
                uint32_t dst = st + r * 128 + ((c ^ (r & 7)) << 4);
                CP_ASYNC16(dst, src, ok ? 16 : 0);
            } else {
                int bi = idx - 1024;
                int r = bi >> 3, c = bi & 7;
                int grow = n0 + r;
                int ok = (grow < Nrows);
                const float* src = B + (long long)(ok ? grow : 0) * ldb + k0 + c * 4;
                uint32_t dst = st + 16384 + r * 128 + ((c ^ (r & 7)) << 4);
                CP_ASYNC16(dst, src, ok ? 16 : 0);
            }
        }
    };

    float acc[4][8][4];
#pragma unroll
    for (int i = 0; i < 4; ++i)
#pragma unroll
        for (int j = 0; j < 8; ++j)
#pragma unroll
            for (int r = 0; r < 4; ++r) acc[i][j][r] = 0.f;

    load_tile(0); CP_COMMIT();
    if (KI > 1) { load_tile(1); CP_COMMIT(); }

    const int g  = lane >> 2;
    const int tq = lane & 3;

    for (int it = 0; it < KI; ++it) {
        if (it + 1 < KI) CP_WAIT(1); else CP_WAIT(0);
        __syncthreads();
        if (it + 2 < KI) { load_tile(it + 2); CP_COMMIT(); }

        const uint8_t* aP = smem + (it % 3) * 49152;
        const uint8_t* bP = aP + 16384;
        auto LDF = [&](const uint8_t* base, int r, int k) -> uint32_t {
            int off = r * 128 + (((k >> 2) ^ (r & 7)) << 4) + (k & 3) * 4;
            return *(const uint32_t*)(base + off);
        };

#pragma unroll
        for (int ks = 0; ks < 4; ++ks) {
            const int kb = ks * 8;
            uint32_t a[4][4];
#pragma unroll
            for (int mi = 0; mi < 4; ++mi) {
                int r0 = mw * 64 + mi * 16 + g;
                a[mi][0] = LDF(aP, r0,     kb + tq);
                a[mi][1] = LDF(aP, r0 + 8, kb + tq);
                a[mi][2] = LDF(aP, r0,     kb + tq + 4);
                a[mi][3] = LDF(aP, r0 + 8, kb + tq + 4);
            }
            uint32_t b[8][2];
#pragma unroll
            for (int ni = 0; ni < 8; ++ni) {
                int rn = nw * 64 + ni * 8 + g;
                b[ni][0] = LDF(bP, rn, kb + tq);
                b[ni][1] = LDF(bP, rn, kb + tq + 4);
            }
#pragma unroll
            for (int mi = 0; mi < 4; ++mi)
#pragma unroll
                for (int ni = 0; ni < 8; ++ni)
                    MMA1688(acc[mi][ni], a[mi], b[ni]);
        }
    }

    float* C = Cout + (long long)z * sC;
#pragma unroll
    for (int mi = 0; mi < 4; ++mi) {
#pragma unroll
        for (int half = 0; half < 2; ++half) {
            int m = m0 + mw * 64 + mi * 16 + g + half * 8;
            if (m >= Mrows) continue;
#pragma unroll
            for (int ni = 0; ni < 8; ++ni) {
                int n = n0 + nw * 64 + ni * 8 + tq * 2;
                if (n + 1 < Nrows)
                    *(float2*)&C[(long long)m * Nrows + n] =
                        make_float2(acc[mi][ni][half * 2], acc[mi][ni][half * 2 + 1]);
                else if (n < Nrows)
                    C[(long long)m * Nrows + n] = acc[mi][ni][half * 2];
            }
        }
    }
}

// ---------------------------------------------------------------------------
// bf16 GEMM, BM128 x BN256 x BK32, ldmatrix + m16n8k16, 3-stage pipeline.
// OM: 0=f32 row-major, 3=combine epilogue, 4=bf16 row-major,
//     5=bf16 transposed (C[n*M+m]), 6=fp16 row-major
// ---------------------------------------------------------------------------
template <int OM, bool HAS_BIAS>
__global__ __launch_bounds__(256)
void bf_gemm(const bf16* __restrict__ A, const bf16* __restrict__ B,
             void* __restrict__ Cout, const float* __restrict__ bias,
             int Mrows, int Nrows, int K, int lda, int ldb,
             long long sA, long long sB, long long sC,
             const float* __restrict__ P, const float* __restrict__ X,
             long long sPX,
             const float* __restrict__ s_alpha, const float* __restrict__ s_beta,
             const float* __restrict__ s_gp, const float* __restrict__ s_gc)
{
    extern __shared__ __align__(128) uint8_t smem[];   // 3 * 24 KB

    const int tid  = threadIdx.x;
    const int lane = tid & 31;
    const int warp = tid >> 5;
    const int mw   = warp >> 2;
    const int nw   = warp & 3;
    const int z    = blockIdx.z;
    const int m0   = blockIdx.y * 128;
    const int n0   = blockIdx.x * 256;

    A += (long long)z * sA;
    B += (long long)z * sB;

    const uint32_t sbase = smem_u32(smem);
    const int KI = K >> 5;

    auto load_tile = [&](int it) {
        const int k0 = it << 5;
        const uint32_t st = sbase + (uint32_t)(it % 3) * 24576;
#pragma unroll
        for (int i = 0; i < 6; ++i) {
            int idx = tid + i * 256;
            if (idx < 512) {
                int r = idx >> 2, c = idx & 3;
                int grow = m0 + r;
                int ok = (grow < Mrows);
                const bf16* src = A + (long long)(ok ? grow : 0) * lda + k0 + c * 8;
                uint32_t dst = st + r * 64 + swzc(r, c) * 16;
                CP_ASYNC16(dst, src, ok ? 16 : 0);
            } else {
                int bi = idx - 512;
                int r = bi >> 2, c = bi & 3;
                int grow = n0 + r;
                int ok = (grow < Nrows);
                const bf16* src = B + (long long)(ok ? grow : 0) * ldb + k0 + c * 8;
                uint32_t dst = st + 8192 + r * 64 + swzc(r, c) * 16;
                CP_ASYNC16(dst, src, ok ? 16 : 0);
            }
        }
    };

    float acc[4][8][4];
#pragma unroll
    for (int i = 0; i < 4; ++i)
#pragma unroll
        for (int j = 0; j < 8; ++j)
#pragma unroll
            for (int r = 0; r < 4; ++r) acc[i][j][r] = 0.f;

    load_tile(0); CP_COMMIT();
    if (KI > 1) { load_tile(1); CP_COMMIT(); }

    const int sub  = lane >> 3;
    const int lrow = lane & 7;

    for (int it = 0; it < KI; ++it) {
        if (it + 1 < KI) CP_WAIT(1); else CP_WAIT(0);
        __syncthreads();
        if (it + 2 < KI) { load_tile(it + 2); CP_COMMIT(); }

        const uint32_t aB = sbase + (uint32_t)(it % 3) * 24576;
        const uint32_t bB = aB + 8192;

#pragma unroll
        for (int ks = 0; ks < 2; ++ks) {
            uint32_t a[4][4];
#pragma unroll
            for (int mi = 0; mi < 4; ++mi) {
                int row = mw * 64 + mi * 16 + (sub & 1) * 8 + lrow;
                int kc  = ks * 2 + (sub >> 1);
                uint32_t addr = aB + row * 64 + swzc(row, kc) * 16;
                LDSM4(a[mi], addr);
            }
            uint32_t b[8][2];
#pragma unroll
            for (int p = 0; p < 4; ++p) {
                int row = nw * 64 + p * 16 + (sub >> 1) * 8 + lrow;
                int kc  = ks * 2 + (sub & 1);
                uint32_t addr = bB + row * 64 + swzc(row, kc) * 16;
                uint32_t t[4];
                LDSM4(t, addr);
                b[2 * p][0]     = t[0];
                b[2 * p][1]     = t[1];
                b[2 * p + 1][0] = t[2];
                b[2 * p + 1][1] = t[3];
            }
#pragma unroll
            for (int mi = 0; mi < 4; ++mi)
#pragma unroll
                for (int ni = 0; ni < 8; ++ni)
                    MMA16816(acc[mi][ni], a[mi], b[ni]);
        }
    }

    float c1 = 0.f, c2 = 1.f, c3 = 0.f;
    if (OM == 3) {
        float al = *s_alpha, be = *s_beta;
        c1 = al * (*s_gp);
        c2 = be * (*s_gc);
        c3 = al + be + 1.f;
        P += (long long)z * sPX;
        X += (long long)z * sPX;
    }
    float*  Cf = (float*)Cout + (long long)z * sC;
    bf16*   Cb = (bf16*)Cout + (long long)z * sC;
    __half* Ch = (__half*)Cout + (long long)z * sC;

    const int g  = lane >> 2;
    const int tq = lane & 3;

#pragma unroll
    for (int mi = 0; mi < 4; ++mi) {
#pragma unroll
        for (int half = 0; half < 2; ++half) {
            int m = m0 + mw * 64 + mi * 16 + g + half * 8;
            if (m >= Mrows) continue;
            float bv = HAS_BIAS ? bias[m] : 0.f;
#pragma unroll
            for (int ni = 0; ni < 8; ++ni) {
                int n = n0 + nw * 64 + ni * 8 + tq * 2;
                float v0 = acc[mi][ni][half * 2 + 0] + bv;
                float v1 = acc[mi][ni][half * 2 + 1] + bv;
                if (OM == 5) {
                    if (n < Nrows)     Cb[(long long)n * Mrows + m]       = __float2bfloat16(v0);
                    if (n + 1 < Nrows) Cb[(long long)(n + 1) * Mrows + m] = __float2bfloat16(v1);
                } else if (n + 1 < Nrows) {
                    long long idx = (long long)m * Nrows + n;
                    if (OM == 0) {
                        *(float2*)&Cf[idx] = make_float2(v0, v1);
                    } else if (OM == 3) {
                        Cf[idx]     = c1 * P[idx]     + c2 * v0 + c3 * X[idx];
                        Cf[idx + 1] = c1 * P[idx + 1] + c2 * v1 + c3 * X[idx + 1];
                    } else if (OM == 4) {
                        uint32_t pk = ((uint32_t)__bfloat16_as_ushort(__float2bfloat16(v1)) << 16)
                                    | (uint32_t)__bfloat16_as_ushort(__float2bfloat16(v0));
                        *(uint32_t*)&Cb[idx] = pk;
                    } else { // OM == 6
                        __half2 h = __floats2half2_rn(v0, v1);
                        *(__half2*)&Ch[idx] = h;
                    }
                } else if (n < Nrows) {
                    long long idx = (long long)m * Nrows + n;
                    if (OM == 0)      Cf[idx] = v0;
                    else if (OM == 3) Cf[idx] = c1 * P[idx] + c2 * v0 + c3 * X[idx];
                    else if (OM == 4) Cb[idx] = __float2bfloat16(v0);
                    else              Ch[idx] = __float2half_rn(v0);
                }
            }
        }
    }
}

// ---------------------------------------------------------------------------
// x (b,c,n) fp32 -> tf32 xb (c-major, for gram) and bf16 xbt_b (n-major)
// ---------------------------------------------------------------------------
__global__ __launch_bounds__(256)
void convert_x_k(const float* __restrict__ x, float* __restrict__ xb,
                 bf16* __restrict__ xbt_b)
{
    __shared__ float t[32][33];
    const int z = blockIdx.z;
    const float* xp = x + (size_t)z * CH * NN;
    float* xbp = xb + (size_t)z * CH * NN;
    bf16*  xtb = xbt_b + (size_t)z * NN * CH;
    const int n0 = blockIdx.x * 32, c0 = blockIdx.y * 32;
    const int tx = threadIdx.x, ty = threadIdx.y;
#pragma unroll
    for (int k = 0; k < 4; ++k) {
        int c = ty + k * 8;
        float raw = xp[(size_t)(c0 + c) * NN + n0 + tx];
        t[c][tx] = raw;
        xbp[(size_t)(c0 + c) * NN + n0 + tx] = tf32r(raw);
    }
    __syncthreads();
#pragma unroll
    for (int k = 0; k < 4; ++k) {
        int n = ty + k * 8;
        xtb[(size_t)(n0 + n) * CH + c0 + tx] = __float2bfloat16(t[tx][n]);
    }
}

__global__ __launch_bounds__(256)
void prep_weights_k(const float* __restrict__ wq, const float* __restrict__ wk,
                    const float* __restrict__ bq, const float* __restrict__ bk,
                    const float* __restrict__ wv,
                    bf16* __restrict__ wqk, float* __restrict__ bqk,
                    bf16* __restrict__ wvr)
{
    int i = blockIdx.x * 256 + threadIdx.x;
    if (i < 128 * CH) {
        int row = i >> 9;
        float v = (row < 64) ? wq[i] : wk[i - 64 * CH];
        wqk[i] = __float2bfloat16(v);
    }
    if (i < 128) bqk[i] = (i < 64) ? bq[i] : bk[i - 64];
    if (i < CH * CH) wvr[i] = __float2bfloat16(wv[i]);
}

// ---------------------------------------------------------------------------
// Row softmax: fp16 in, bf16 out IN PLACE (same buffer, same addresses).
// ---------------------------------------------------------------------------
__global__ __launch_bounds__(256)
void softmax_pos(__half* __restrict__ energy)
{
    const long long row = (long long)blockIdx.y * NN + blockIdx.x;
    __half* p = energy + row * NN;
    bf16*  ob = (bf16*)p;
    const int tid = threadIdx.x;
    __shared__ float red[8];

    float v[16];
    float mx = -1e30f;
#pragma unroll
    for (int i = 0; i < 16; ++i) {
        v[i] = __half2float(p[tid + i * 256]);
        mx = fmaxf(mx, v[i]);
    }
#pragma unroll
    for (int o2 = 16; o2; o2 >>= 1) mx = fmaxf(mx, __shfl_xor_sync(~0u, mx, o2));
    if ((tid & 31) == 0) red[tid >> 5] = mx;
    __syncthreads();
    mx = red[0];
#pragma unroll
    for (int i = 1; i < 8; ++i) mx = fmaxf(mx, red[i]);

    float s = 0.f;
#pragma unroll
    for (int i = 0; i < 16; ++i) { v[i] = expf(v[i] - mx); s += v[i]; }
#pragma unroll
    for (int o2 = 16; o2; o2 >>= 1) s += __shfl_xor_sync(~0u, s, o2);
    __syncthreads();
    if ((tid & 31) == 0) red[tid >> 5] = s;
    __syncthreads();
    s = 0.f;
#pragma unroll
    for (int i = 0; i < 8; ++i) s += red[i];
    float inv = 1.f / s;
#pragma unroll
    for (int i = 0; i < 16; ++i) ob[tid + i * 256] = __float2bfloat16(v[i] * inv);
}

// ---------------------------------------------------------------------------
__global__ __launch_bounds__(128)
void softmax_chan(const float* __restrict__ gramp, bf16* __restrict__ attcb)
{
    const int bat = blockIdx.y;
    const int row = blockIdx.x;
    const float* base = gramp + ((size_t)bat * NSPLIT) * CH * CH + (size_t)row * CH;
    bf16* o = attcb + ((size_t)bat * CH + row) * CH;
    const int tid = threadIdx.x;
    __shared__ float red[4];

    float v[4];
    float mn = 1e30f;
#pragma unroll
    for (int i = 0; i < 4; ++i) {
        float s = 0.f;
#pragma unroll
        for (int sp = 0; sp < NSPLIT; ++sp)
            s += base[(size_t)sp * CH * CH + tid + i * 128];
        v[i] = s;
        mn = fminf(mn, s);
    }
#pragma unroll
    for (int o2 = 16; o2; o2 >>= 1) mn = fminf(mn, __shfl_xor_sync(~0u, mn, o2));
    if ((tid & 31) == 0) red[tid >> 5] = mn;
    __syncthreads();
    mn = fminf(fminf(red[0], red[1]), fminf(red[2], red[3]));

    float s = 0.f;
#pragma unroll
    for (int i = 0; i < 4; ++i) { v[i] = expf(mn - v[i]); s += v[i]; }
#pragma unroll
    for (int o2 = 16; o2; o2 >>= 1) s += __shfl_xor_sync(~0u, s, o2);
    __syncthreads();
    if ((tid & 31) == 0) red[tid >> 5] = s;
    __syncthreads();
    s = red[0] + red[1] + red[2] + red[3];
    float inv = 1.f / s;
#pragma unroll
    for (int i = 0; i < 4; ++i) o[tid + i * 128] = __float2bfloat16(v[i] * inv);
}

// ---------------------------------------------------------------------------
extern "C" void kernel_launch(void* const* d_in, const int* in_sizes, int n_in,
                              void* d_out, int out_size)
{
    const float* x  = (const float*)d_in[0];
    const float* wq = (const float*)d_in[1];
    const float* bq = (const float*)d_in[2];
    const float* wk = (const float*)d_in[3];
    const float* bk = (const float*)d_in[4];
    const float* wv = (const float*)d_in[5];
    const float* bv = (const float*)d_in[6];
    const float* gp = (const float*)d_in[7];
    const float* gc = (const float*)d_in[8];
    const float* al = (const float*)d_in[9];
    const float* be = (const float*)d_in[10];
    float* out = (float*)d_out;

    __half* energy;
    float *xb, *pos, *gramp, *bqk;
    bf16 *xbt_b, *vb, *qkt, *attcb, *wqk, *wvr;
    cudaGetSymbolAddress((void**)&energy, g_energy);
    cudaGetSymbolAddress((void**)&xb,    g_xb);
    cudaGetSymbolAddress((void**)&xbt_b, g_xbt_b);
    cudaGetSymbolAddress((void**)&vb,    g_vb);
    cudaGetSymbolAddress((void**)&qkt,   g_qkt);
    cudaGetSymbolAddress((void**)&pos,   g_pos);
    cudaGetSymbolAddress((void**)&gramp, g_gramp);
    cudaGetSymbolAddress((void**)&attcb, g_attcb);
    cudaGetSymbolAddress((void**)&wqk,   g_wqk);
    cudaGetSymbolAddress((void**)&bqk,   g_bqk);
    cudaGetSymbolAddress((void**)&wvr,   g_wvr);

    const long long sX   = (long long)CH * NN;
    const long long sXT  = (long long)NN * CH;
    const long long sQK  = (long long)NN * 128;
    const long long sAtt = (long long)NN * NN;
    const long long sGr  = (long long)CH * CH;

    const int SMEM_T = 3 * 49152;
    const int SMEM_B = 3 * 24576;
    static bool attr_done = false;
    if (!attr_done) {
        cudaFuncSetAttribute(tf_gemm, cudaFuncAttributeMaxDynamicSharedMemorySize, SMEM_T);
        cudaFuncSetAttribute(bf_gemm<5, true>,  cudaFuncAttributeMaxDynamicSharedMemorySize, SMEM_B);
        cudaFuncSetAttribute(bf_gemm<4, true>,  cudaFuncAttributeMaxDynamicSharedMemorySize, SMEM_B);
        cudaFuncSetAttribute(bf_gemm<6, false>, cudaFuncAttributeMaxDynamicSharedMemorySize, SMEM_B);
        cudaFuncSetAttribute(bf_gemm<0, false>, cudaFuncAttributeMaxDynamicSharedMemorySize, SMEM_B);
        cudaFuncSetAttribute(bf_gemm<3, false>, cudaFuncAttributeMaxDynamicSharedMemorySize, SMEM_B);
        attr_done = true;
    }

    // 1) conversions / weight prep
    convert_x_k<<<dim3(NN / 32, CH / 32, BDIM), dim3(32, 8)>>>(x, xb, xbt_b);
    prep_weights_k<<<(CH * CH + 255) / 256, 256>>>(wq, wk, bq, bk, wv, wqk, bqk, wvr);

    // 2) fused q|k projection -> qkt[n][128] bf16 (transposed, +bias)
    bf_gemm<5, true><<<dim3(NN / 256, 1, BDIM), 256, SMEM_B>>>(
        wqk, xbt_b, qkt, bqk, 128, NN, CH, CH, CH, 0, sXT, sQK,
        nullptr, nullptr, 0, nullptr, nullptr, nullptr, nullptr);

    // 3) v projection -> vb[c][n] bf16 (+bias)
    bf_gemm<4, true><<<dim3(NN / 256, CH / 128, BDIM), 256, SMEM_B>>>(
        wvr, xbt_b, vb, bv, CH, NN, CH, CH, CH, 0, sXT, sX,
        nullptr, nullptr, 0, nullptr, nullptr, nullptr, nullptr);

    // 4) energy[i,j] = sum_d q[i,d] k[j,d] -> fp16
    bf_gemm<6, false><<<dim3(NN / 256, NN / 128, BDIM), 256, SMEM_B>>>(
        qkt, qkt + 64, energy, nullptr, NN, NN, CQ, 128, 128, sQK, sQK, sAtt,
        nullptr, nullptr, 0, nullptr, nullptr, nullptr, nullptr);

    // 5) softmax rows: fp16 in -> bf16 att in place
    softmax_pos<<<dim3(NN, BDIM), 256>>>(energy);

    // 6) pos[c,i] = sum_j v[c,j] att[i,j]  (bf16 GEMM)
    bf_gemm<0, false><<<dim3(NN / 256, CH / 128, BDIM), 256, SMEM_B>>>(
        vb, (const bf16*)energy, pos, nullptr, CH, NN, NN, NN, NN, sX, sAtt, sX,
        nullptr, nullptr, 0, nullptr, nullptr, nullptr, nullptr);

    // 7) gram split-K parts (tf32)
    tf_gemm<<<dim3(CH / 256, CH / 128, BDIM * NSPLIT), 256, SMEM_T>>>(
        xb, xb, gramp, CH, CH, NN / NSPLIT, NN, NN, NSPLIT, sX, sX, sGr);

    // 8) channel softmax + fused part-reduction -> bf16 att_c
    softmax_chan<<<dim3(CH, BDIM), 128>>>(gramp, attcb);

    // 9) out = a*gp*pos + b*gc*(att_c @ x) + (a+b+1)*x  (bf16 GEMM, combine)
    bf_gemm<3, false><<<dim3(NN / 256, CH / 128, BDIM), 256, SMEM_B>>>(
        attcb, xbt_b, out, nullptr, CH, NN, CH, CH, CH, sGr, sXT, sX,
        pos, x, sX, al, be, gp, gc);
}

// round 13
// speedup vs baseline: 10.2281x; 1.1179x over previous
#include <cuda_runtime.h>
#include <cuda_bf16.h>
#include <cuda_fp16.h>
#include <cstdint>

#define BDIM 2
#define CH   512
#define CQ   64
#define NN   4096
#define NSPLIT 8

typedef __nv_bfloat16 bf16;

// ---------------------------------------------------------------------------
// Scratch. g_energy is fp16; softmax overwrites it in place with bf16 att.
// ---------------------------------------------------------------------------
__device__ __align__(256) __half g_energy[(size_t)BDIM * NN * NN];   // 67 MB
__device__ __align__(256) float g_xb    [(size_t)BDIM * CH * NN];    // tf32 c-major (gram)
__device__ __align__(256) bf16  g_xbt_b [(size_t)BDIM * NN * CH];    // bf16 n-major
__device__ __align__(256) bf16  g_vb    [(size_t)BDIM * CH * NN];
__device__ __align__(256) bf16  g_qkt   [(size_t)BDIM * NN * 128];   // bf16 [n][q|k]
__device__ __align__(256) float g_pos   [(size_t)BDIM * CH * NN];
__device__ __align__(256) float g_gramp [(size_t)BDIM * NSPLIT * CH * CH];
__device__ __align__(256) bf16  g_attcb [(size_t)BDIM * CH * CH];
__device__ __align__(256) bf16  g_wqk [128 * CH];
__device__ __align__(256) float g_bqk [128];
__device__ __align__(256) bf16  g_wvr [CH * CH];

// ---------------------------------------------------------------------------
__device__ __forceinline__ uint32_t smem_u32(const void* p) {
    uint32_t a;
    asm("{ .reg .u64 t; cvta.to.shared.u64 t, %1; cvt.u32.u64 %0, t; }"
        : "=r"(a) : "l"(p));
    return a;
}
__device__ __forceinline__ float tf32r(float x) {
    uint32_t u;
    asm("cvt.rna.tf32.f32 %0, %1;" : "=r"(u) : "f"(x));
    return __uint_as_float(u);
}

#define CP_ASYNC16(dst, src, sz) \
    asm volatile("cp.async.cg.shared.global [%0], [%1], 16, %2;" \
                 :: "r"(dst), "l"(src), "r"(sz))
#define CP_COMMIT() asm volatile("cp.async.commit_group;")
#define CP_WAIT(N)  asm volatile("cp.async.wait_group %0;" :: "n"(N))

#define MMA1688(d, a, b) \
    asm volatile("mma.sync.aligned.m16n8k8.row.col.f32.tf32.tf32.f32 " \
                 "{%0,%1,%2,%3}, {%4,%5,%6,%7}, {%8,%9}, {%0,%1,%2,%3};" \
                 : "+f"((d)[0]), "+f"((d)[1]), "+f"((d)[2]), "+f"((d)[3]) \
                 : "r"((a)[0]), "r"((a)[1]), "r"((a)[2]), "r"((a)[3]), \
                   "r"((b)[0]), "r"((b)[1]))

#define MMA16816(d, a, b) \
    asm volatile("mma.sync.aligned.m16n8k16.row.col.f32.bf16.bf16.f32 " \
                 "{%0,%1,%2,%3}, {%4,%5,%6,%7}, {%8,%9}, {%0,%1,%2,%3};" \
                 : "+f"((d)[0]), "+f"((d)[1]), "+f"((d)[2]), "+f"((d)[3]) \
                 : "r"((a)[0]), "r"((a)[1]), "r"((a)[2]), "r"((a)[3]), \
                   "r"((b)[0]), "r"((b)[1]))

#define LDSM4(R, addr) \
    asm volatile("ldmatrix.sync.aligned.m8n8.x4.shared.b16 {%0,%1,%2,%3}, [%4];" \
                 : "=r"((R)[0]), "=r"((R)[1]), "=r"((R)[2]), "=r"((R)[3]) \
                 : "r"(addr))

__device__ __forceinline__ int swzc(int r, int c) {
    return (c ^ (r & 3) ^ ((r >> 2) & 1)) & 3;
}

// ---------------------------------------------------------------------------
// tf32 GEMM (gram only). BM128 x BN256 x BK32, 256 thr, 3-stage pipeline.
// ---------------------------------------------------------------------------
__global__ __launch_bounds__(256)
void tf_gemm(const float* __restrict__ A, const float* __restrict__ B,
             float* __restrict__ Cout,
             int Mrows, int Nrows, int K, int lda, int ldb, int nsplit,
             long long sA, long long sB, long long sC)
{
    extern __shared__ __align__(128) uint8_t smem[];

    const int tid  = threadIdx.x;
    const int lane = tid & 31;
    const int warp = tid >> 5;
    const int mw   = warp >> 2;
    const int nw   = warp & 3;
    const int z    = blockIdx.z;
    const int bat  = z / nsplit;
    const int sp   = z - bat * nsplit;
    const int m0   = blockIdx.y * 128;
    const int n0   = blockIdx.x * 256;

    A += (long long)bat * sA + (long long)sp * K;
    B += (long long)bat * sB + (long long)sp * K;

    const uint32_t sbase = smem_u32(smem);
    const int KI = K >> 5;

    auto load_tile = [&](int it) {
        const int k0 = it << 5;
        const uint32_t st = sbase + (uint32_t)(it % 3) * 49152;
#pragma unroll
        for (int i = 0; i < 12; ++i) {
            int idx = tid + i * 256;
            if (idx < 1024) {
                int r = idx >> 3, c = idx & 7;
                int grow = m0 + r;
                int ok = (grow < Mrows);
                const float* src = A + (long long)(ok ? grow : 0) * lda + k0 + c * 4;
                uint32_t dst = st + r * 128 + ((c ^ (r & 7)) << 4);
                CP_ASYNC16(dst, src, ok ? 16 : 0);
            } else {
                int bi = idx - 1024;
                int r = bi >> 3, c = bi & 7;
                int grow = n0 + r;
                int ok = (grow < Nrows);
                const float* src = B + (long long)(ok ? grow : 0) * ldb + k0 + c * 4;
                uint32_t dst = st + 16384 + r * 128 + ((c ^ (r & 7)) << 4);
                CP_ASYNC16(dst, src, ok ? 16 : 0);
            }
        }
    };

    float acc[4][8][4];
#pragma unroll
    for (int i = 0; i < 4; ++i)
#pragma unroll
        for (int j = 0; j < 8; ++j)
#pragma unroll
            for (int r = 0; r < 4; ++r) acc[i][j][r] = 0.f;

    load_tile(0); CP_COMMIT();
    if (KI > 1) { load_tile(1); CP_COMMIT(); }

    const int g  = lane >> 2;
    const int tq = lane & 3;

    for (int it = 0; it < KI; ++it) {
        if (it + 1 < KI) CP_WAIT(1); else CP_WAIT(0);
        __syncthreads();
        if (it + 2 < KI) { load_tile(it + 2); CP_COMMIT(); }

        const uint8_t* aP = smem + (it % 3) * 49152;
        const uint8_t* bP = aP + 16384;
        auto LDF = [&](const uint8_t* base, int r, int k) -> uint32_t {
            int off = r * 128 + (((k >> 2) ^ (r & 7)) << 4) + (k & 3) * 4;
            return *(const uint32_t*)(base + off);
        };

#pragma unroll
        for (int ks = 0; ks < 4; ++ks) {
            const int kb = ks * 8;
            uint32_t a[4][4];
#pragma unroll
            for (int mi = 0; mi < 4; ++mi) {
                int r0 = mw * 64 + mi * 16 + g;
                a[mi][0] = LDF(aP, r0,     kb + tq);
                a[mi][1] = LDF(aP, r0 + 8, kb + tq);
                a[mi][2] = LDF(aP, r0,     kb + tq + 4);
                a[mi][3] = LDF(aP, r0 + 8, kb + tq + 4);
            }
            uint32_t b[8][2];
#pragma unroll
            for (int ni = 0; ni < 8; ++ni) {
                int rn = nw * 64 + ni * 8 + g;
                b[ni][0] = LDF(bP, rn, kb + tq);
                b[ni][1] = LDF(bP, rn, kb + tq + 4);
            }
#pragma unroll
            for (int mi = 0; mi < 4; ++mi)
#pragma unroll
                for (int ni = 0; ni < 8; ++ni)
                    MMA1688(acc[mi][ni], a[mi], b[ni]);
        }
    }

    float* C = Cout + (long long)z * sC;
#pragma unroll
    for (int mi = 0; mi < 4; ++mi) {
#pragma unroll
        for (int half = 0; half < 2; ++half) {
            int m = m0 + mw * 64 + mi * 16 + g + half * 8;
            if (m >= Mrows) continue;
#pragma unroll
            for (int ni = 0; ni < 8; ++ni) {
                int n = n0 + nw * 64 + ni * 8 + tq * 2;
                if (n + 1 < Nrows)
                    *(float2*)&C[(long long)m * Nrows + n] =
                        make_float2(acc[mi][ni][half * 2], acc[mi][ni][half * 2 + 1]);
                else if (n < Nrows)
                    C[(long long)m * Nrows + n] = acc[mi][ni][half * 2];
            }
        }
    }
}

// ---------------------------------------------------------------------------
// bf16 GEMM, BM128 x BN256 x BK32, 512 threads (16 warps, 4x4, 32x64 warp
// tile -> 4 warps/SMSP), ldmatrix + m16n8k16, 3-stage pipeline.
// OM: 0=f32 row-major, 3=combine epilogue, 4=bf16 row-major,
//     5=bf16 transposed (C[n*M+m]), 6=fp16 row-major
// ---------------------------------------------------------------------------
template <int OM, bool HAS_BIAS>
__global__ __launch_bounds__(512)
void bf_gemm(const bf16* __restrict__ A, const bf16* __restrict__ B,
             void* __restrict__ Cout, const float* __restrict__ bias,
             int Mrows, int Nrows, int K, int lda, int ldb,
             long long sA, long long sB, long long sC,
             const float* __restrict__ P, const float* __restrict__ X,
             long long sPX,
             const float* __restrict__ s_alpha, const float* __restrict__ s_beta,
             const float* __restrict__ s_gp, const float* __restrict__ s_gc)
{
    extern __shared__ __align__(128) uint8_t smem[];   // 3 * 24 KB

    const int tid  = threadIdx.x;
    const int lane = tid & 31;
    const int warp = tid >> 5;      // 0..15
    const int mw   = warp >> 2;     // 0..3 (32-row strips)
    const int nw   = warp & 3;      // 0..3 (64-col strips)
    const int z    = blockIdx.z;
    const int m0   = blockIdx.y * 128;
    const int n0   = blockIdx.x * 256;

    A += (long long)z * sA;
    B += (long long)z * sB;

    const uint32_t sbase = smem_u32(smem);
    const int KI = K >> 5;

    // A: 512 chunks, B: 1024 chunks; 1536 total over 512 threads = 3 each.
    auto load_tile = [&](int it) {
        const int k0 = it << 5;
        const uint32_t st = sbase + (uint32_t)(it % 3) * 24576;
#pragma unroll
        for (int i = 0; i < 3; ++i) {
            int idx = tid + i * 512;
            if (idx < 512) {
                int r = idx >> 2, c = idx & 3;
                int grow = m0 + r;
                int ok = (grow < Mrows);
                const bf16* src = A + (long long)(ok ? grow : 0) * lda + k0 + c * 8;
                uint32_t dst = st + r * 64 + swzc(r, c) * 16;
                CP_ASYNC16(dst, src, ok ? 16 : 0);
            } else {
                int bi = idx - 512;
                int r = bi >> 2, c = bi & 3;
                int grow = n0 + r;
                int ok = (grow < Nrows);
                const bf16* src = B + (long long)(ok ? grow : 0) * ldb + k0 + c * 8;
                uint32_t dst = st + 8192 + r * 64 + swzc(r, c) * 16;
                CP_ASYNC16(dst, src, ok ? 16 : 0);
            }
        }
    };

    float acc[2][8][4];
#pragma unroll
    for (int i = 0; i < 2; ++i)
#pragma unroll
        for (int j = 0; j < 8; ++j)
#pragma unroll
            for (int r = 0; r < 4; ++r) acc[i][j][r] = 0.f;

    load_tile(0); CP_COMMIT();
    if (KI > 1) { load_tile(1); CP_COMMIT(); }

    const int sub  = lane >> 3;
    const int lrow = lane & 7;

    for (int it = 0; it < KI; ++it) {
        if (it + 1 < KI) CP_WAIT(1); else CP_WAIT(0);
        __syncthreads();
        if (it + 2 < KI) { load_tile(it + 2); CP_COMMIT(); }

        const uint32_t aB = sbase + (uint32_t)(it % 3) * 24576;
        const uint32_t bB = aB + 8192;

#pragma unroll
        for (int ks = 0; ks < 2; ++ks) {
            uint32_t a[2][4];
#pragma unroll
            for (int mi = 0; mi < 2; ++mi) {
                int row = mw * 32 + mi * 16 + (sub & 1) * 8 + lrow;
                int kc  = ks * 2 + (sub >> 1);
                uint32_t addr = aB + row * 64 + swzc(row, kc) * 16;
                LDSM4(a[mi], addr);
            }
            uint32_t b[8][2];
#pragma unroll
            for (int p = 0; p < 4; ++p) {
                int row = nw * 64 + p * 16 + (sub >> 1) * 8 + lrow;
                int kc  = ks * 2 + (sub & 1);
                uint32_t addr = bB + row * 64 + swzc(row, kc) * 16;
                uint32_t t[4];
                LDSM4(t, addr);
                b[2 * p][0]     = t[0];
                b[2 * p][1]     = t[1];
                b[2 * p + 1][0] = t[2];
                b[2 * p + 1][1] = t[3];
            }
#pragma unroll
            for (int mi = 0; mi < 2; ++mi)
#pragma unroll
                for (int ni = 0; ni < 8; ++ni)
                    MMA16816(acc[mi][ni], a[mi], b[ni]);
        }
    }

    float c1 = 0.f, c2 = 1.f, c3 = 0.f;
    if (OM == 3) {
        float al = *s_alpha, be = *s_beta;
        c1 = al * (*s_gp);
        c2 = be * (*s_gc);
        c3 = al + be + 1.f;
        P += (long long)z * sPX;
        X += (long long)z * sPX;
    }
    float*  Cf = (float*)Cout + (long long)z * sC;
    bf16*   Cb = (bf16*)Cout + (long long)z * sC;
    __half* Ch = (__half*)Cout + (long long)z * sC;

    const int g  = lane >> 2;
    const int tq = lane & 3;

#pragma unroll
    for (int mi = 0; mi < 2; ++mi) {
#pragma unroll
        for (int half = 0; half < 2; ++half) {
            int m = m0 + mw * 32 + mi * 16 + g + half * 8;
            if (m >= Mrows) continue;
            float bv = HAS_BIAS ? bias[m] : 0.f;
#pragma unroll
            for (int ni = 0; ni < 8; ++ni) {
                int n = n0 + nw * 64 + ni * 8 + tq * 2;
                float v0 = acc[mi][ni][half * 2 + 0] + bv;
                float v1 = acc[mi][ni][half * 2 + 1] + bv;
                if (OM == 5) {
                    if (n < Nrows)     Cb[(long long)n * Mrows + m]       = __float2bfloat16(v0);
                    if (n + 1 < Nrows) Cb[(long long)(n + 1) * Mrows + m] = __float2bfloat16(v1);
                } else if (n + 1 < Nrows) {
                    long long idx = (long long)m * Nrows + n;
                    if (OM == 0) {
                        *(float2*)&Cf[idx] = make_float2(v0, v1);
                    } else if (OM == 3) {
                        Cf[idx]     = c1 * P[idx]     + c2 * v0 + c3 * X[idx];
                        Cf[idx + 1] = c1 * P[idx + 1] + c2 * v1 + c3 * X[idx + 1];
                    } else if (OM == 4) {
                        uint32_t pk = ((uint32_t)__bfloat16_as_ushort(__float2bfloat16(v1)) << 16)
                                    | (uint32_t)__bfloat16_as_ushort(__float2bfloat16(v0));
                        *(uint32_t*)&Cb[idx] = pk;
                    } else { // OM == 6
                        __half2 h = __floats2half2_rn(v0, v1);
                        *(__half2*)&Ch[idx] = h;
                    }
                } else if (n < Nrows) {
                    long long idx = (long long)m * Nrows + n;
                    if (OM == 0)      Cf[idx] = v0;
                    else if (OM == 3) Cf[idx] = c1 * P[idx] + c2 * v0 + c3 * X[idx];
                    else if (OM == 4) Cb[idx] = __float2bfloat16(v0);
                    else              Ch[idx] = __float2half_rn(v0);
                }
            }
        }
    }
}

// ---------------------------------------------------------------------------
// x (b,c,n) fp32 -> tf32 xb (c-major, for gram) and bf16 xbt_b (n-major)
// ---------------------------------------------------------------------------
__global__ __launch_bounds__(256)
void convert_x_k(const float* __restrict__ x, float* __restrict__ xb,
                 bf16* __restrict__ xbt_b)
{
    __shared__ float t[32][33];
    const int z = blockIdx.z;
    const float* xp = x + (size_t)z * CH * NN;
    float* xbp = xb + (size_t)z * CH * NN;
    bf16*  xtb = xbt_b + (size_t)z * NN * CH;
    const int n0 = blockIdx.x * 32, c0 = blockIdx.y * 32;
    const int tx = threadIdx.x, ty = threadIdx.y;
#pragma unroll
    for (int k = 0; k < 4; ++k) {
        int c = ty + k * 8;
        float raw = xp[(size_t)(c0 + c) * NN + n0 + tx];
        t[c][tx] = raw;
        xbp[(size_t)(c0 + c) * NN + n0 + tx] = tf32r(raw);
    }
    __syncthreads();
#pragma unroll
    for (int k = 0; k < 4; ++k) {
        int n = ty + k * 8;
        xtb[(size_t)(n0 + n) * CH + c0 + tx] = __float2bfloat16(t[tx][n]);
    }
}

__global__ __launch_bounds__(256)
void prep_weights_k(const float* __restrict__ wq, const float* __restrict__ wk,
                    const float* __restrict__ bq, const float* __restrict__ bk,
                    const float* __restrict__ wv,
                    bf16* __restrict__ wqk, float* __restrict__ bqk,
                    bf16* __restrict__ wvr)
{
    int i = blockIdx.x * 256 + threadIdx.x;
    if (i < 128 * CH) {
        int row = i >> 9;
        float v = (row < 64) ? wq[i] : wk[i - 64 * CH];
        wqk[i] = __float2bfloat16(v);
    }
    if (i < 128) bqk[i] = (i < 64) ? bq[i] : bk[i - 64];
    if (i < CH * CH) wvr[i] = __float2bfloat16(wv[i]);
}

// ---------------------------------------------------------------------------
// Row softmax: fp16 in, bf16 out IN PLACE (same buffer, same addresses).
// ---------------------------------------------------------------------------
__global__ __launch_bounds__(256)
void softmax_pos(__half* __restrict__ energy)
{
    const long long row = (long long)blockIdx.y * NN + blockIdx.x;
    __half* p = energy + row * NN;
    bf16*  ob = (bf16*)p;
    const int tid = threadIdx.x;
    __shared__ float red[8];

    float v[16];
    float mx = -1e30f;
#pragma unroll
    for (int i = 0; i < 16; ++i) {
        v[i] = __half2float(p[tid + i * 256]);
        mx = fmaxf(mx, v[i]);
    }
#pragma unroll
    for (int o2 = 16; o2; o2 >>= 1) mx = fmaxf(mx, __shfl_xor_sync(~0u, mx, o2));
    if ((tid & 31) == 0) red[tid >> 5] = mx;
    __syncthreads();
    mx = red[0];
#pragma unroll
    for (int i = 1; i < 8; ++i) mx = fmaxf(mx, red[i]);

    float s = 0.f;
#pragma unroll
    for (int i = 0; i < 16; ++i) { v[i] = expf(v[i] - mx); s += v[i]; }
#pragma unroll
    for (int o2 = 16; o2; o2 >>= 1) s += __shfl_xor_sync(~0u, s, o2);
    __syncthreads();
    if ((tid & 31) == 0) red[tid >> 5] = s;
    __syncthreads();
    s = 0.f;
#pragma unroll
    for (int i = 0; i < 8; ++i) s += red[i];
    float inv = 1.f / s;
#pragma unroll
    for (int i = 0; i < 16; ++i) ob[tid + i * 256] = __float2bfloat16(v[i] * inv);
}

// ---------------------------------------------------------------------------
__global__ __launch_bounds__(128)
void softmax_chan(const float* __restrict__ gramp, bf16* __restrict__ attcb)
{
    const int bat = blockIdx.y;
    const int row = blockIdx.x;
    const float* base = gramp + ((size_t)bat * NSPLIT) * CH * CH + (size_t)row * CH;
    bf16* o = attcb + ((size_t)bat * CH + row) * CH;
    const int tid = threadIdx.x;
    __shared__ float red[4];

    float v[4];
    float mn = 1e30f;
#pragma unroll
    for (int i = 0; i < 4; ++i) {
        float s = 0.f;
#pragma unroll
        for (int sp = 0; sp < NSPLIT; ++sp)
            s += base[(size_t)sp * CH * CH + tid + i * 128];
        v[i] = s;
        mn = fminf(mn, s);
    }
#pragma unroll
    for (int o2 = 16; o2; o2 >>= 1) mn = fminf(mn, __shfl_xor_sync(~0u, mn, o2));
    if ((tid & 31) == 0) red[tid >> 5] = mn;
    __syncthreads();
    mn = fminf(fminf(red[0], red[1]), fminf(red[2], red[3]));

    float s = 0.f;
#pragma unroll
    for (int i = 0; i < 4; ++i) { v[i] = expf(mn - v[i]); s += v[i]; }
#pragma unroll
    for (int o2 = 16; o2; o2 >>= 1) s += __shfl_xor_sync(~0u, s, o2);
    __syncthreads();
    if ((tid & 31) == 0) red[tid >> 5] = s;
    __syncthreads();
    s = red[0] + red[1] + red[2] + red[3];
    float inv = 1.f / s;
#pragma unroll
    for (int i = 0; i < 4; ++i) o[tid + i * 128] = __float2bfloat16(v[i] * inv);
}

// ---------------------------------------------------------------------------
extern "C" void kernel_launch(void* const* d_in, const int* in_sizes, int n_in,
                              void* d_out, int out_size)
{
    const float* x  = (const float*)d_in[0];
    const float* wq = (const float*)d_in[1];
    const float* bq = (const float*)d_in[2];
    const float* wk = (const float*)d_in[3];
    const float* bk = (const float*)d_in[4];
    const float* wv = (const float*)d_in[5];
    const float* bv = (const float*)d_in[6];
    const float* gp = (const float*)d_in[7];
    const float* gc = (const float*)d_in[8];
    const float* al = (const float*)d_in[9];
    const float* be = (const float*)d_in[10];
    float* out = (float*)d_out;

    __half* energy;
    float *xb, *pos, *gramp, *bqk;
    bf16 *xbt_b, *vb, *qkt, *attcb, *wqk, *wvr;
    cudaGetSymbolAddress((void**)&energy, g_energy);
    cudaGetSymbolAddress((void**)&xb,    g_xb);
    cudaGetSymbolAddress((void**)&xbt_b, g_xbt_b);
    cudaGetSymbolAddress((void**)&vb,    g_vb);
    cudaGetSymbolAddress((void**)&qkt,   g_qkt);
    cudaGetSymbolAddress((void**)&pos,   g_pos);
    cudaGetSymbolAddress((void**)&gramp, g_gramp);
    cudaGetSymbolAddress((void**)&attcb, g_attcb);
    cudaGetSymbolAddress((void**)&wqk,   g_wqk);
    cudaGetSymbolAddress((void**)&bqk,   g_bqk);
    cudaGetSymbolAddress((void**)&wvr,   g_wvr);

    const long long sX   = (long long)CH * NN;
    const long long sXT  = (long long)NN * CH;
    const long long sQK  = (long long)NN * 128;
    const long long sAtt = (long long)NN * NN;
    const long long sGr  = (long long)CH * CH;

    const int SMEM_T = 3 * 49152;
    const int SMEM_B = 3 * 24576;
    static bool attr_done = false;
    if (!attr_done) {
        cudaFuncSetAttribute(tf_gemm, cudaFuncAttributeMaxDynamicSharedMemorySize, SMEM_T);
        cudaFuncSetAttribute(bf_gemm<5, true>,  cudaFuncAttributeMaxDynamicSharedMemorySize, SMEM_B);
        cudaFuncSetAttribute(bf_gemm<4, true>,  cudaFuncAttributeMaxDynamicSharedMemorySize, SMEM_B);
        cudaFuncSetAttribute(bf_gemm<6, false>, cudaFuncAttributeMaxDynamicSharedMemorySize, SMEM_B);
        cudaFuncSetAttribute(bf_gemm<0, false>, cudaFuncAttributeMaxDynamicSharedMemorySize, SMEM_B);
        cudaFuncSetAttribute(bf_gemm<3, false>, cudaFuncAttributeMaxDynamicSharedMemorySize, SMEM_B);
        attr_done = true;
    }

    // 1) conversions / weight prep
    convert_x_k<<<dim3(NN / 32, CH / 32, BDIM), dim3(32, 8)>>>(x, xb, xbt_b);
    prep_weights_k<<<(CH * CH + 255) / 256, 256>>>(wq, wk, bq, bk, wv, wqk, bqk, wvr);

    // 2) fused q|k projection -> qkt[n][128] bf16 (transposed, +bias)
    bf_gemm<5, true><<<dim3(NN / 256, 1, BDIM), 512, SMEM_B>>>(
        wqk, xbt_b, qkt, bqk, 128, NN, CH, CH, CH, 0, sXT, sQK,
        nullptr, nullptr, 0, nullptr, nullptr, nullptr, nullptr);

    // 3) v projection -> vb[c][n] bf16 (+bias)
    bf_gemm<4, true><<<dim3(NN / 256, CH / 128, BDIM), 512, SMEM_B>>>(
        wvr, xbt_b, vb, bv, CH, NN, CH, CH, CH, 0, sXT, sX,
        nullptr, nullptr, 0, nullptr, nullptr, nullptr, nullptr);

    // 4) energy[i,j] = sum_d q[i,d] k[j,d] -> fp16
    bf_gemm<6, false><<<dim3(NN / 256, NN / 128, BDIM), 512, SMEM_B>>>(
        qkt, qkt + 64, energy, nullptr, NN, NN, CQ, 128, 128, sQK, sQK, sAtt,
        nullptr, nullptr, 0, nullptr, nullptr, nullptr, nullptr);

    // 5) softmax rows: fp16 in -> bf16 att in place
    softmax_pos<<<dim3(NN, BDIM), 256>>>(energy);

    // 6) pos[c,i] = sum_j v[c,j] att[i,j]  (bf16 GEMM)
    bf_gemm<0, false><<<dim3(NN / 256, CH / 128, BDIM), 512, SMEM_B>>>(
        vb, (const bf16*)energy, pos, nullptr, CH, NN, NN, NN, NN, sX, sAtt, sX,
        nullptr, nullptr, 0, nullptr, nullptr, nullptr, nullptr);

    // 7) gram split-K parts (tf32)
    tf_gemm<<<dim3(CH / 256, CH / 128, BDIM * NSPLIT), 256, SMEM_T>>>(
        xb, xb, gramp, CH, CH, NN / NSPLIT, NN, NN, NSPLIT, sX, sX, sGr);

    // 8) channel softmax + fused part-reduction -> bf16 att_c
    softmax_chan<<<dim3(CH, BDIM), 128>>>(gramp, attcb);

    // 9) out = a*gp*pos + b*gc*(att_c @ x) + (a+b+1)*x  (bf16 GEMM, combine)
    bf_gemm<3, false><<<dim3(NN / 256, CH / 128, BDIM), 512, SMEM_B>>>(
        attcb, xbt_b, out, nullptr, CH, NN, CH, CH, CH, sGr, sXT, sX,
        pos, x, sX, al, be, gp, gc);
}

// round 14
// speedup vs baseline: 11.2429x; 1.0992x over previous
#include <cuda_runtime.h>
#include <cuda_bf16.h>
#include <cuda_fp16.h>
#include <cstdint>

#define BDIM 2
#define CH   512
#define CQ   64
#define NN   4096
#define NSPLIT 8

typedef __nv_bfloat16 bf16;

// ---------------------------------------------------------------------------
// Scratch. g_energy is fp16; softmax overwrites it in place with bf16 att.
// ---------------------------------------------------------------------------
__device__ __align__(256) __half g_energy[(size_t)BDIM * NN * NN];   // 67 MB
__device__ __align__(256) float g_xb    [(size_t)BDIM * CH * NN];    // tf32 c-major (gram)
__device__ __align__(256) bf16  g_xbt_b [(size_t)BDIM * NN * CH];    // bf16 n-major
__device__ __align__(256) bf16  g_vb    [(size_t)BDIM * CH * NN];
__device__ __align__(256) bf16  g_qkt   [(size_t)BDIM * NN * 128];   // bf16 [n][q|k]
__device__ __align__(256) float g_pos   [(size_t)BDIM * CH * NN];
__device__ __align__(256) float g_gramp [(size_t)BDIM * NSPLIT * CH * CH];
__device__ __align__(256) bf16  g_attcb [(size_t)BDIM * CH * CH];
__device__ __align__(256) bf16  g_wqk [128 * CH];
__device__ __align__(256) float g_bqk [128];
__device__ __align__(256) bf16  g_wvr [CH * CH];

// ---------------------------------------------------------------------------
__device__ __forceinline__ uint32_t smem_u32(const void* p) {
    uint32_t a;
    asm("{ .reg .u64 t; cvta.to.shared.u64 t, %1; cvt.u32.u64 %0, t; }"
        : "=r"(a) : "l"(p));
    return a;
}
__device__ __forceinline__ float tf32r(float x) {
    uint32_t u;
    asm("cvt.rna.tf32.f32 %0, %1;" : "=r"(u) : "f"(x));
    return __uint_as_float(u);
}

#define CP_ASYNC16(dst, src, sz) \
    asm volatile("cp.async.cg.shared.global [%0], [%1], 16, %2;" \
                 :: "r"(dst), "l"(src), "r"(sz))
#define CP_COMMIT() asm volatile("cp.async.commit_group;")
#define CP_WAIT(N)  asm volatile("cp.async.wait_group %0;" :: "n"(N))

#define MMA1688(d, a, b) \
    asm volatile("mma.sync.aligned.m16n8k8.row.col.f32.tf32.tf32.f32 " \
                 "{%0,%1,%2,%3}, {%4,%5,%6,%7}, {%8,%9}, {%0,%1,%2,%3};" \
                 : "+f"((d)[0]), "+f"((d)[1]), "+f"((d)[2]), "+f"((d)[3]) \
                 : "r"((a)[0]), "r"((a)[1]), "r"((a)[2]), "r"((a)[3]), \
                   "r"((b)[0]), "r"((b)[1]))

#define MMA16816(d, a, b) \
    asm volatile("mma.sync.aligned.m16n8k16.row.col.f32.bf16.bf16.f32 " \
                 "{%0,%1,%2,%3}, {%4,%5,%6,%7}, {%8,%9}, {%0,%1,%2,%3};" \
                 : "+f"((d)[0]), "+f"((d)[1]), "+f"((d)[2]), "+f"((d)[3]) \
                 : "r"((a)[0]), "r"((a)[1]), "r"((a)[2]), "r"((a)[3]), \
                   "r"((b)[0]), "r"((b)[1]))

#define LDSM4(R, addr) \
    asm volatile("ldmatrix.sync.aligned.m8n8.x4.shared.b16 {%0,%1,%2,%3}, [%4];" \
                 : "=r"((R)[0]), "=r"((R)[1]), "=r"((R)[2]), "=r"((R)[3]) \
                 : "r"(addr))

__device__ __forceinline__ int swzc(int r, int c) {
    return (c ^ (r & 3) ^ ((r >> 2) & 1)) & 3;
}

// ---------------------------------------------------------------------------
// tf32 GEMM (gram only). BM128 x BN256 x BK32, 256 thr, 3-stage pipeline.
// ---------------------------------------------------------------------------
__global__ __launch_bounds__(256)
void tf_gemm(const float* __restrict__ A, const float* __restrict__ B,
             float* __restrict__ Cout,
             int Mrows, int Nrows, int K, int lda, int ldb, int nsplit,
             long long sA, long long sB, long long sC)
{
    extern __shared__ __align__(128) uint8_t smem[];

    const int tid  = threadIdx.x;
    const int lane = tid & 31;
    const int warp = tid >> 5;
    const int mw   = warp >> 2;
    const int nw   = warp & 3;
    const int z    = blockIdx.z;
    const int bat  = z / nsplit;
    const int sp   = z - bat * nsplit;
    const int m0   = blockIdx.y * 128;
    const int n0   = blockIdx.x * 256;

    A += (long long)bat * sA + (long long)sp * K;
    B += (long long)bat * sB + (long long)sp * K;

    const uint32_t sbase = smem_u32(smem);
    const int KI = K >> 5;

    auto load_tile = [&](int it) {
        const int k0 = it << 5;
        const uint32_t st = sbase + (uint32_t)(it % 3) * 49152;
#pragma unroll
        for (int i = 0; i < 12; ++i) {
            int idx = tid + i * 256;
            if (idx < 1024) {
                int r = idx >> 3, c = idx & 7;
                int grow = m0 + r;
                int ok = (grow < Mrows);
                const float* src = A + (long long)(ok ? grow : 0) * lda + k0 + c * 4;
                uint32_t dst = st + r * 128 + ((c ^ (r & 7)) << 4);
                CP_ASYNC16(dst, src, ok ? 16 : 0);
            } else {
                int bi = idx - 1024;
                int r = bi >> 3, c = bi & 7;
                int grow = n0 + r;
                int ok = (grow < Nrows);
                const float* src = B + (long long)(ok ? grow : 0) * ldb + k0 + c * 4;
                uint32_t dst = st + 16384 + r * 128 + ((c ^ (r & 7)) << 4);
                CP_ASYNC16(dst, src, ok ? 16 : 0);
            }
        }
    };

    float acc[4][8][4];
#pragma unroll
    for (int i = 0; i < 4; ++i)
#pragma unroll
        for (int j = 0; j < 8; ++j)
#pragma unroll
            for (int r = 0; r < 4; ++r) acc[i][j][r] = 0.f;

    load_tile(0); CP_COMMIT();
    if (KI > 1) { load_tile(1); CP_COMMIT(); }

    const int g  = lane >> 2;
    const int tq = lane & 3;

    for (int it = 0; it < KI; ++it) {
        if (it + 1 < KI) CP_WAIT(1); else CP_WAIT(0);
        __syncthreads();
        if (it + 2 < KI) { load_tile(it + 2); CP_COMMIT(); }

        const uint8_t* aP = smem + (it % 3) * 49152;
        const uint8_t* bP = aP + 16384;
        auto LDF = [&](const uint8_t* base, int r, int k) -> uint32_t {
            int off = r * 128 + (((k >> 2) ^ (r & 7)) << 4) + (k & 3) * 4;
            return *(const uint32_t*)(base + off);
        };

#pragma unroll
        for (int ks = 0; ks < 4; ++ks) {
            const int kb = ks * 8;
            uint32_t a[4][4];
#pragma unroll
            for (int mi = 0; mi < 4; ++mi) {
                int r0 = mw * 64 + mi * 16 + g;
                a[mi][0] = LDF(aP, r0,     kb + tq);
                a[mi][1] = LDF(aP, r0 + 8, kb + tq);
                a[mi][2] = LDF(aP, r0,     kb + tq + 4);
                a[mi][3] = LDF(aP, r0 + 8, kb + tq + 4);
            }
            uint32_t b[8][2];
#pragma unroll
            for (int ni = 0; ni < 8; ++ni) {
                int rn = nw * 64 + ni * 8 + g;
                b[ni][0] = LDF(bP, rn, kb + tq);
                b[ni][1] = LDF(bP, rn, kb + tq + 4);
            }
#pragma unroll
            for (int mi = 0; mi < 4; ++mi)
#pragma unroll
                for (int ni = 0; ni < 8; ++ni)
                    MMA1688(acc[mi][ni], a[mi], b[ni]);
        }
    }

    float* C = Cout + (long long)z * sC;
#pragma unroll
    for (int mi = 0; mi < 4; ++mi) {
#pragma unroll
        for (int half = 0; half < 2; ++half) {
            int m = m0 + mw * 64 + mi * 16 + g + half * 8;
            if (m >= Mrows) continue;
#pragma unroll
            for (int ni = 0; ni < 8; ++ni) {
                int n = n0 + nw * 64 + ni * 8 + tq * 2;
                if (n + 1 < Nrows)
                    *(float2*)&C[(long long)m * Nrows + n] =
                        make_float2(acc[mi][ni][half * 2], acc[mi][ni][half * 2 + 1]);
                else if (n < Nrows)
                    C[(long long)m * Nrows + n] = acc[mi][ni][half * 2];
            }
        }
    }
}

// ---------------------------------------------------------------------------
// bf16 GEMM, BM128 x BN256 x BK32, 512 threads (16 warps, 4x4, 32x64 warp
// tile), ldmatrix + m16n8k16, 3-stage pipeline.
// OM: 0=f32 row-major, 3=combine epilogue, 4=bf16 row-major,
//     5=bf16 transposed (C[n*M+m]), 6=fp16 row-major
// ---------------------------------------------------------------------------
template <int OM, bool HAS_BIAS>
__global__ __launch_bounds__(512)
void bf_gemm(const bf16* __restrict__ A, const bf16* __restrict__ B,
             void* __restrict__ Cout, const float* __restrict__ bias,
             int Mrows, int Nrows, int K, int lda, int ldb,
             long long sA, long long sB, long long sC,
             const float* __restrict__ P, const float* __restrict__ X,
             long long sPX,
             const float* __restrict__ s_alpha, const float* __restrict__ s_beta,
             const float* __restrict__ s_gp, const float* __restrict__ s_gc)
{
    extern __shared__ __align__(128) uint8_t smem[];   // 3 * 24 KB

    const int tid  = threadIdx.x;
    const int lane = tid & 31;
    const int warp = tid >> 5;      // 0..15
    const int mw   = warp >> 2;     // 0..3 (32-row strips)
    const int nw   = warp & 3;      // 0..3 (64-col strips)
    const int z    = blockIdx.z;
    const int m0   = blockIdx.y * 128;
    const int n0   = blockIdx.x * 256;

    A += (long long)z * sA;
    B += (long long)z * sB;

    const uint32_t sbase = smem_u32(smem);
    const int KI = K >> 5;

    auto load_tile = [&](int it) {
        const int k0 = it << 5;
        const uint32_t st = sbase + (uint32_t)(it % 3) * 24576;
#pragma unroll
        for (int i = 0; i < 3; ++i) {
            int idx = tid + i * 512;
            if (idx < 512) {
                int r = idx >> 2, c = idx & 3;
                int grow = m0 + r;
                int ok = (grow < Mrows);
                const bf16* src = A + (long long)(ok ? grow : 0) * lda + k0 + c * 8;
                uint32_t dst = st + r * 64 + swzc(r, c) * 16;
                CP_ASYNC16(dst, src, ok ? 16 : 0);
            } else {
                int bi = idx - 512;
                int r = bi >> 2, c = bi & 3;
                int grow = n0 + r;
                int ok = (grow < Nrows);
                const bf16* src = B + (long long)(ok ? grow : 0) * ldb + k0 + c * 8;
                uint32_t dst = st + 8192 + r * 64 + swzc(r, c) * 16;
                CP_ASYNC16(dst, src, ok ? 16 : 0);
            }
        }
    };

    float acc[2][8][4];
#pragma unroll
    for (int i = 0; i < 2; ++i)
#pragma unroll
        for (int j = 0; j < 8; ++j)
#pragma unroll
            for (int r = 0; r < 4; ++r) acc[i][j][r] = 0.f;

    load_tile(0); CP_COMMIT();
    if (KI > 1) { load_tile(1); CP_COMMIT(); }

    const int sub  = lane >> 3;
    const int lrow = lane & 7;

    for (int it = 0; it < KI; ++it) {
        if (it + 1 < KI) CP_WAIT(1); else CP_WAIT(0);
        __syncthreads();
        if (it + 2 < KI) { load_tile(it + 2); CP_COMMIT(); }

        const uint32_t aB = sbase + (uint32_t)(it % 3) * 24576;
        const uint32_t bB = aB + 8192;

#pragma unroll
        for (int ks = 0; ks < 2; ++ks) {
            uint32_t a[2][4];
#pragma unroll
            for (int mi = 0; mi < 2; ++mi) {
                int row = mw * 32 + mi * 16 + (sub & 1) * 8 + lrow;
                int kc  = ks * 2 + (sub >> 1);
                uint32_t addr = aB + row * 64 + swzc(row, kc) * 16;
                LDSM4(a[mi], addr);
            }
            uint32_t b[8][2];
#pragma unroll
            for (int p = 0; p < 4; ++p) {
                int row = nw * 64 + p * 16 + (sub >> 1) * 8 + lrow;
                int kc  = ks * 2 + (sub & 1);
                uint32_t addr = bB + row * 64 + swzc(row, kc) * 16;
                uint32_t t[4];
                LDSM4(t, addr);
                b[2 * p][0]     = t[0];
                b[2 * p][1]     = t[1];
                b[2 * p + 1][0] = t[2];
                b[2 * p + 1][1] = t[3];
            }
#pragma unroll
            for (int mi = 0; mi < 2; ++mi)
#pragma unroll
                for (int ni = 0; ni < 8; ++ni)
                    MMA16816(acc[mi][ni], a[mi], b[ni]);
        }
    }

    float c1 = 0.f, c2 = 1.f, c3 = 0.f;
    if (OM == 3) {
        float al = *s_alpha, be = *s_beta;
        c1 = al * (*s_gp);
        c2 = be * (*s_gc);
        c3 = al + be + 1.f;
        P += (long long)z * sPX;
        X += (long long)z * sPX;
    }
    float*  Cf = (float*)Cout + (long long)z * sC;
    bf16*   Cb = (bf16*)Cout + (long long)z * sC;
    __half* Ch = (__half*)Cout + (long long)z * sC;

    const int g  = lane >> 2;
    const int tq = lane & 3;

#pragma unroll
    for (int mi = 0; mi < 2; ++mi) {
#pragma unroll
        for (int half = 0; half < 2; ++half) {
            int m = m0 + mw * 32 + mi * 16 + g + half * 8;
            if (m >= Mrows) continue;
            float bv = HAS_BIAS ? bias[m] : 0.f;
#pragma unroll
            for (int ni = 0; ni < 8; ++ni) {
                int n = n0 + nw * 64 + ni * 8 + tq * 2;
                float v0 = acc[mi][ni][half * 2 + 0] + bv;
                float v1 = acc[mi][ni][half * 2 + 1] + bv;
                if (OM == 5) {
                    if (n < Nrows)     Cb[(long long)n * Mrows + m]       = __float2bfloat16(v0);
                    if (n + 1 < Nrows) Cb[(long long)(n + 1) * Mrows + m] = __float2bfloat16(v1);
                } else if (n + 1 < Nrows) {
                    long long idx = (long long)m * Nrows + n;
                    if (OM == 0) {
                        *(float2*)&Cf[idx] = make_float2(v0, v1);
                    } else if (OM == 3) {
                        Cf[idx]     = c1 * P[idx]     + c2 * v0 + c3 * X[idx];
                        Cf[idx + 1] = c1 * P[idx + 1] + c2 * v1 + c3 * X[idx + 1];
                    } else if (OM == 4) {
                        uint32_t pk = ((uint32_t)__bfloat16_as_ushort(__float2bfloat16(v1)) << 16)
                                    | (uint32_t)__bfloat16_as_ushort(__float2bfloat16(v0));
                        *(uint32_t*)&Cb[idx] = pk;
                    } else { // OM == 6
                        __half2 h = __floats2half2_rn(v0, v1);
                        *(__half2*)&Ch[idx] = h;
                    }
                } else if (n < Nrows) {
                    long long idx = (long long)m * Nrows + n;
                    if (OM == 0)      Cf[idx] = v0;
                    else if (OM == 3) Cf[idx] = c1 * P[idx] + c2 * v0 + c3 * X[idx];
                    else if (OM == 4) Cb[idx] = __float2bfloat16(v0);
                    else              Ch[idx] = __float2half_rn(v0);
                }
            }
        }
    }
}

// ---------------------------------------------------------------------------
// x (b,c,n) fp32 -> tf32 xb (c-major, for gram) and bf16 xbt_b (n-major)
// ---------------------------------------------------------------------------
__global__ __launch_bounds__(256)
void convert_x_k(const float* __restrict__ x, float* __restrict__ xb,
                 bf16* __restrict__ xbt_b)
{
    __shared__ float t[32][33];
    const int z = blockIdx.z;
    const float* xp = x + (size_t)z * CH * NN;
    float* xbp = xb + (size_t)z * CH * NN;
    bf16*  xtb = xbt_b + (size_t)z * NN * CH;
    const int n0 = blockIdx.x * 32, c0 = blockIdx.y * 32;
    const int tx = threadIdx.x, ty = threadIdx.y;
#pragma unroll
    for (int k = 0; k < 4; ++k) {
        int c = ty + k * 8;
        float raw = xp[(size_t)(c0 + c) * NN + n0 + tx];
        t[c][tx] = raw;
        xbp[(size_t)(c0 + c) * NN + n0 + tx] = tf32r(raw);
    }
    __syncthreads();
#pragma unroll
    for (int k = 0; k < 4; ++k) {
        int n = ty + k * 8;
        xtb[(size_t)(n0 + n) * CH + c0 + tx] = __float2bfloat16(t[tx][n]);
    }
}

__global__ __launch_bounds__(256)
void prep_weights_k(const float* __restrict__ wq, const float* __restrict__ wk,
                    const float* __restrict__ bq, const float* __restrict__ bk,
                    const float* __restrict__ wv,
                    bf16* __restrict__ wqk, float* __restrict__ bqk,
                    bf16* __restrict__ wvr)
{
    int i = blockIdx.x * 256 + threadIdx.x;
    if (i < 128 * CH) {
        int row = i >> 9;
        float v = (row < 64) ? wq[i] : wk[i - 64 * CH];
        wqk[i] = __float2bfloat16(v);
    }
    if (i < 128) bqk[i] = (i < 64) ? bq[i] : bk[i - 64];
    if (i < CH * CH) wvr[i] = __float2bfloat16(wv[i]);
}

// ---------------------------------------------------------------------------
// Row softmax: fp16 in, bf16 out IN PLACE (same buffer, same addresses).
// ---------------------------------------------------------------------------
__global__ __launch_bounds__(256)
void softmax_pos(__half* __restrict__ energy)
{
    const long long row = (long long)blockIdx.y * NN + blockIdx.x;
    __half* p = energy + row * NN;
    bf16*  ob = (bf16*)p;
    const int tid = threadIdx.x;
    __shared__ float red[8];

    float v[16];
    float mx = -1e30f;
#pragma unroll
    for (int i = 0; i < 16; ++i) {
        v[i] = __half2float(p[tid + i * 256]);
        mx = fmaxf(mx, v[i]);
    }
#pragma unroll
    for (int o2 = 16; o2; o2 >>= 1) mx = fmaxf(mx, __shfl_xor_sync(~0u, mx, o2));
    if ((tid & 31) == 0) red[tid >> 5] = mx;
    __syncthreads();
    mx = red[0];
#pragma unroll
    for (int i = 1; i < 8; ++i) mx = fmaxf(mx, red[i]);

    float s = 0.f;
#pragma unroll
    for (int i = 0; i < 16; ++i) { v[i] = expf(v[i] - mx); s += v[i]; }
#pragma unroll
    for (int o2 = 16; o2; o2 >>= 1) s += __shfl_xor_sync(~0u, s, o2);
    __syncthreads();
    if ((tid & 31) == 0) red[tid >> 5] = s;
    __syncthreads();
    s = 0.f;
#pragma unroll
    for (int i = 0; i < 8; ++i) s += red[i];
    float inv = 1.f / s;
#pragma unroll
    for (int i = 0; i < 16; ++i) ob[tid + i * 256] = __float2bfloat16(v[i] * inv);
}

// ---------------------------------------------------------------------------
__global__ __launch_bounds__(128)
void softmax_chan(const float* __restrict__ gramp, bf16* __restrict__ attcb)
{
    const int bat = blockIdx.y;
    const int row = blockIdx.x;
    const float* base = gramp + ((size_t)bat * NSPLIT) * CH * CH + (size_t)row * CH;
    bf16* o = attcb + ((size_t)bat * CH + row) * CH;
    const int tid = threadIdx.x;
    __shared__ float red[4];

    float v[4];
    float mn = 1e30f;
#pragma unroll
    for (int i = 0; i < 4; ++i) {
        float s = 0.f;
#pragma unroll
        for (int sp = 0; sp < NSPLIT; ++sp)
            s += base[(size_t)sp * CH * CH + tid + i * 128];
        v[i] = s;
        mn = fminf(mn, s);
    }
#pragma unroll
    for (int o2 = 16; o2; o2 >>= 1) mn = fminf(mn, __shfl_xor_sync(~0u, mn, o2));
    if ((tid & 31) == 0) red[tid >> 5] = mn;
    __syncthreads();
    mn = fminf(fminf(red[0], red[1]), fminf(red[2], red[3]));

    float s = 0.f;
#pragma unroll
    for (int i = 0; i < 4; ++i) { v[i] = expf(mn - v[i]); s += v[i]; }
#pragma unroll
    for (int o2 = 16; o2; o2 >>= 1) s += __shfl_xor_sync(~0u, s, o2);
    __syncthreads();
    if ((tid & 31) == 0) red[tid >> 5] = s;
    __syncthreads();
    s = red[0] + red[1] + red[2] + red[3];
    float inv = 1.f / s;
#pragma unroll
    for (int i = 0; i < 4; ++i) o[tid + i * 128] = __float2bfloat16(v[i] * inv);
}

// ---------------------------------------------------------------------------
extern "C" void kernel_launch(void* const* d_in, const int* in_sizes, int n_in,
                              void* d_out, int out_size)
{
    const float* x  = (const float*)d_in[0];
    const float* wq = (const float*)d_in[1];
    const float* bq = (const float*)d_in[2];
    const float* wk = (const float*)d_in[3];
    const float* bk = (const float*)d_in[4];
    const float* wv = (const float*)d_in[5];
    const float* bv = (const float*)d_in[6];
    const float* gp = (const float*)d_in[7];
    const float* gc = (const float*)d_in[8];
    const float* al = (const float*)d_in[9];
    const float* be = (const float*)d_in[10];
    float* out = (float*)d_out;

    __half* energy;
    float *xb, *pos, *gramp, *bqk;
    bf16 *xbt_b, *vb, *qkt, *attcb, *wqk, *wvr;
    cudaGetSymbolAddress((void**)&energy, g_energy);
    cudaGetSymbolAddress((void**)&xb,    g_xb);
    cudaGetSymbolAddress((void**)&xbt_b, g_xbt_b);
    cudaGetSymbolAddress((void**)&vb,    g_vb);
    cudaGetSymbolAddress((void**)&qkt,   g_qkt);
    cudaGetSymbolAddress((void**)&pos,   g_pos);
    cudaGetSymbolAddress((void**)&gramp, g_gramp);
    cudaGetSymbolAddress((void**)&attcb, g_attcb);
    cudaGetSymbolAddress((void**)&wqk,   g_wqk);
    cudaGetSymbolAddress((void**)&bqk,   g_bqk);
    cudaGetSymbolAddress((void**)&wvr,   g_wvr);

    const long long sX   = (long long)CH * NN;
    const long long sXT  = (long long)NN * CH;
    const long long sQK  = (long long)NN * 128;
    const long long sAtt = (long long)NN * NN;
    const long long sGr  = (long long)CH * CH;

    const int SMEM_T = 3 * 49152;
    const int SMEM_B = 3 * 24576;

    static bool init_done = false;
    static cudaStream_t sA, sB;
    static cudaEvent_t evFork, evV, evA, evB;
    if (!init_done) {
        cudaFuncSetAttribute(tf_gemm, cudaFuncAttributeMaxDynamicSharedMemorySize, SMEM_T);
        cudaFuncSetAttribute(bf_gemm<5, true>,  cudaFuncAttributeMaxDynamicSharedMemorySize, SMEM_B);
        cudaFuncSetAttribute(bf_gemm<4, true>,  cudaFuncAttributeMaxDynamicSharedMemorySize, SMEM_B);
        cudaFuncSetAttribute(bf_gemm<6, false>, cudaFuncAttributeMaxDynamicSharedMemorySize, SMEM_B);
        cudaFuncSetAttribute(bf_gemm<0, false>, cudaFuncAttributeMaxDynamicSharedMemorySize, SMEM_B);
        cudaFuncSetAttribute(bf_gemm<3, false>, cudaFuncAttributeMaxDynamicSharedMemorySize, SMEM_B);
        cudaStreamCreateWithFlags(&sA, cudaStreamNonBlocking);
        cudaStreamCreateWithFlags(&sB, cudaStreamNonBlocking);
        cudaEventCreateWithFlags(&evFork, cudaEventDisableTiming);
        cudaEventCreateWithFlags(&evV,    cudaEventDisableTiming);
        cudaEventCreateWithFlags(&evA,    cudaEventDisableTiming);
        cudaEventCreateWithFlags(&evB,    cudaEventDisableTiming);
        init_done = true;
    }

    // ---- prologue on the default (capture) stream ----
    convert_x_k<<<dim3(NN / 32, CH / 32, BDIM), dim3(32, 8)>>>(x, xb, xbt_b);
    prep_weights_k<<<(CH * CH + 255) / 256, 256>>>(wq, wk, bq, bk, wv, wqk, bqk, wvr);

    // ---- fork ----
    cudaEventRecord(evFork, 0);
    cudaStreamWaitEvent(sA, evFork, 0);
    cudaStreamWaitEvent(sB, evFork, 0);

    // chain A (stream sA): qk-proj -> energy -> softmax_pos
    bf_gemm<5, true><<<dim3(NN / 256, 1, BDIM), 512, SMEM_B, sA>>>(
        wqk, xbt_b, qkt, bqk, 128, NN, CH, CH, CH, 0, sXT, sQK,
        nullptr, nullptr, 0, nullptr, nullptr, nullptr, nullptr);
    bf_gemm<6, false><<<dim3(NN / 256, NN / 128, BDIM), 512, SMEM_B, sA>>>(
        qkt, qkt + 64, energy, nullptr, NN, NN, CQ, 128, 128, sQK, sQK, sAtt,
        nullptr, nullptr, 0, nullptr, nullptr, nullptr, nullptr);
    softmax_pos<<<dim3(NN, BDIM), 256, 0, sA>>>(energy);

    // chain B (stream sB): v-proj -> gram -> softmax_chan
    bf_gemm<4, true><<<dim3(NN / 256, CH / 128, BDIM), 512, SMEM_B, sB>>>(
        wvr, xbt_b, vb, bv, CH, NN, CH, CH, CH, 0, sXT, sX,
        nullptr, nullptr, 0, nullptr, nullptr, nullptr, nullptr);
    cudaEventRecord(evV, sB);
    tf_gemm<<<dim3(CH / 256, CH / 128, BDIM * NSPLIT), 256, SMEM_T, sB>>>(
        xb, xb, gramp, CH, CH, NN / NSPLIT, NN, NN, NSPLIT, sX, sX, sGr);
    softmax_chan<<<dim3(CH, BDIM), 128, 0, sB>>>(gramp, attcb);

    // pos needs chain A's att AND chain B's v
    cudaStreamWaitEvent(sA, evV, 0);
    bf_gemm<0, false><<<dim3(NN / 256, CH / 128, BDIM), 512, SMEM_B, sA>>>(
        vb, (const bf16*)energy, pos, nullptr, CH, NN, NN, NN, NN, sX, sAtt, sX,
        nullptr, nullptr, 0, nullptr, nullptr, nullptr, nullptr);

    // ---- join back to the default stream ----
    cudaEventRecord(evA, sA);
    cudaEventRecord(evB, sB);
    cudaStreamWaitEvent(0, evA, 0);
    cudaStreamWaitEvent(0, evB, 0);

    // combine on default stream
    bf_gemm<3, false><<<dim3(NN / 256, CH / 128, BDIM), 512, SMEM_B>>>(
        attcb, xbt_b, out, nullptr, CH, NN, CH, CH, CH, sGr, sXT, sX,
        pos, x, sX, al, be, gp, gc);
}

// round 15
// speedup vs baseline: 11.5984x; 1.0316x over previous
#include <cuda_runtime.h>
#include <cuda_bf16.h>
#include <cuda_fp16.h>
#include <cstdint>

#define BDIM 2
#define CH   512
#define CQ   64
#define NN   4096
#define NSPLIT 8

typedef __nv_bfloat16 bf16;

// ---------------------------------------------------------------------------
// Scratch. g_energy is fp16; softmax overwrites it in place with bf16 att.
// ---------------------------------------------------------------------------
__device__ __align__(256) __half g_energy[(size_t)BDIM * NN * NN];   // 67 MB
__device__ __align__(256) float g_xb    [(size_t)BDIM * CH * NN];    // tf32 c-major (gram)
__device__ __align__(256) bf16  g_xbt_b [(size_t)BDIM * NN * CH];    // bf16 n-major
__device__ __align__(256) bf16  g_vb    [(size_t)BDIM * CH * NN];
__device__ __align__(256) bf16  g_qkt   [(size_t)BDIM * NN * 128];   // bf16 [n][q|k]
__device__ __align__(256) float g_pos   [(size_t)BDIM * CH * NN];
__device__ __align__(256) float g_gramp [(size_t)BDIM * NSPLIT * CH * CH];
__device__ __align__(256) bf16  g_attcb [(size_t)BDIM * CH * CH];
__device__ __align__(256) bf16  g_wqk [128 * CH];
__device__ __align__(256) float g_bqk [128];
__device__ __align__(256) bf16  g_wvr [CH * CH];

// ---------------------------------------------------------------------------
__device__ __forceinline__ uint32_t smem_u32(const void* p) {
    uint32_t a;
    asm("{ .reg .u64 t; cvta.to.shared.u64 t, %1; cvt.u32.u64 %0, t; }"
        : "=r"(a) : "l"(p));
    return a;
}
__device__ __forceinline__ float tf32r(float x) {
    uint32_t u;
    asm("cvt.rna.tf32.f32 %0, %1;" : "=r"(u) : "f"(x));
    return __uint_as_float(u);
}

#define CP_ASYNC16(dst, src, sz) \
    asm volatile("cp.async.cg.shared.global [%0], [%1], 16, %2;" \
                 :: "r"(dst), "l"(src), "r"(sz))
#define CP_COMMIT() asm volatile("cp.async.commit_group;")
#define CP_WAIT(N)  asm volatile("cp.async.wait_group %0;" :: "n"(N))

#define MMA1688(d, a, b) \
    asm volatile("mma.sync.aligned.m16n8k8.row.col.f32.tf32.tf32.f32 " \
                 "{%0,%1,%2,%3}, {%4,%5,%6,%7}, {%8,%9}, {%0,%1,%2,%3};" \
                 : "+f"((d)[0]), "+f"((d)[1]), "+f"((d)[2]), "+f"((d)[3]) \
                 : "r"((a)[0]), "r"((a)[1]), "r"((a)[2]), "r"((a)[3]), \
                   "r"((b)[0]), "r"((b)[1]))

#define MMA16816(d, a, b) \
    asm volatile("mma.sync.aligned.m16n8k16.row.col.f32.bf16.bf16.f32 " \
                 "{%0,%1,%2,%3}, {%4,%5,%6,%7}, {%8,%9}, {%0,%1,%2,%3};" \
                 : "+f"((d)[0]), "+f"((d)[1]), "+f"((d)[2]), "+f"((d)[3]) \
                 : "r"((a)[0]), "r"((a)[1]), "r"((a)[2]), "r"((a)[3]), \
                   "r"((b)[0]), "r"((b)[1]))

#define LDSM4(R, addr) \
    asm volatile("ldmatrix.sync.aligned.m8n8.x4.shared.b16 {%0,%1,%2,%3}, [%4];" \
                 : "=r"((R)[0]), "=r"((R)[1]), "=r"((R)[2]), "=r"((R)[3]) \
                 : "r"(addr))

// ---------------------------------------------------------------------------
// tf32 GEMM (gram only). BM128 x BN256 x BK32, 256 thr, 3-stage pipeline.
// ---------------------------------------------------------------------------
__global__ __launch_bounds__(256)
void tf_gemm(const float* __restrict__ A, const float* __restrict__ B,
             float* __restrict__ Cout,
             int Mrows, int Nrows, int K, int lda, int ldb, int nsplit,
             long long sA, long long sB, long long sC)
{
    extern __shared__ __align__(128) uint8_t smem[];

    const int tid  = threadIdx.x;
    const int lane = tid & 31;
    const int warp = tid >> 5;
    const int mw   = warp >> 2;
    const int nw   = warp & 3;
    const int z    = blockIdx.z;
    const int bat  = z / nsplit;
    const int sp   = z - bat * nsplit;
    const int m0   = blockIdx.y * 128;
    const int n0   = blockIdx.x * 256;

    A += (long long)bat * sA + (long long)sp * K;
    B += (long long)bat * sB + (long long)sp * K;

    const uint32_t sbase = smem_u32(smem);
    const int KI = K >> 5;

    auto load_tile = [&](int it) {
        const int k0 = it << 5;
        const uint32_t st = sbase + (uint32_t)(it % 3) * 49152;
#pragma unroll
        for (int i = 0; i < 12; ++i) {
            int idx = tid + i * 256;
            if (idx < 1024) {
                int r = idx >> 3, c = idx & 7;
                int grow = m0 + r;
                int ok = (grow < Mrows);
                const float* src = A + (long long)(ok ? grow : 0) * lda + k0 + c * 4;
                uint32_t dst = st + r * 128 + ((c ^ (r & 7)) << 4);
                CP_ASYNC16(dst, src, ok ? 16 : 0);
            } else {
                int bi = idx - 1024;
                int r = bi >> 3, c = bi & 7;
                int grow = n0 + r;
                int ok = (grow < Nrows);
                const float* src = B + (long long)(ok ? grow : 0) * ldb + k0 + c * 4;
                uint32_t dst = st + 16384 + r * 128 + ((c ^ (r & 7)) << 4);
                CP_ASYNC16(dst, src, ok ? 16 : 0);
            }
        }
    };

    float acc[4][8][4];
#pragma unroll
    for (int i = 0; i < 4; ++i)
#pragma unroll
        for (int j = 0; j < 8; ++j)
#pragma unroll
            for (int r = 0; r < 4; ++r) acc[i][j][r] = 0.f;

    load_tile(0); CP_COMMIT();
    if (KI > 1) { load_tile(1); CP_COMMIT(); }

    const int g  = lane >> 2;
    const int tq = lane & 3;

    for (int it = 0; it < KI; ++it) {
        if (it + 1 < KI) CP_WAIT(1); else CP_WAIT(0);
        __syncthreads();
        if (it + 2 < KI) { load_tile(it + 2); CP_COMMIT(); }

        const uint8_t* aP = smem + (it % 3) * 49152;
        const uint8_t* bP = aP + 16384;
        auto LDF = [&](const uint8_t* base, int r, int k) -> uint32_t {
            int off = r * 128 + (((k >> 2) ^ (r & 7)) << 4) + (k & 3) * 4;
            return *(const uint32_t*)(base + off);
        };

#pragma unroll
        for (int ks = 0; ks < 4; ++ks) {
            const int kb = ks * 8;
            uint32_t a[4][4];
#pragma unroll
            for (int mi = 0; mi < 4; ++mi) {
                int r0 = mw * 64 + mi * 16 + g;
                a[mi][0] = LDF(aP, r0,     kb + tq);
                a[mi][1] = LDF(aP, r0 + 8, kb + tq);
                a[mi][2] = LDF(aP, r0,     kb + tq + 4);
                a[mi][3] = LDF(aP, r0 + 8, kb + tq + 4);
            }
            uint32_t b[8][2];
#pragma unroll
            for (int ni = 0; ni < 8; ++ni) {
                int rn = nw * 64 + ni * 8 + g;
                b[ni][0] = LDF(bP, rn, kb + tq);
                b[ni][1] = LDF(bP, rn, kb + tq + 4);
            }
#pragma unroll
            for (int mi = 0; mi < 4; ++mi)
#pragma unroll
                for (int ni = 0; ni < 8; ++ni)
                    MMA1688(acc[mi][ni], a[mi], b[ni]);
        }
    }

    float* C = Cout + (long long)z * sC;
#pragma unroll
    for (int mi = 0; mi < 4; ++mi) {
#pragma unroll
        for (int half = 0; half < 2; ++half) {
            int m = m0 + mw * 64 + mi * 16 + g + half * 8;
            if (m >= Mrows) continue;
#pragma unroll
            for (int ni = 0; ni < 8; ++ni) {
                int n = n0 + nw * 64 + ni * 8 + tq * 2;
                if (n + 1 < Nrows)
                    *(float2*)&C[(long long)m * Nrows + n] =
                        make_float2(acc[mi][ni][half * 2], acc[mi][ni][half * 2 + 1]);
                else if (n < Nrows)
                    C[(long long)m * Nrows + n] = acc[mi][ni][half * 2];
            }
        }
    }
}

// ---------------------------------------------------------------------------
// bf16 GEMM, BM128 x BN256 x BK64, 512 threads (16 warps, 4x4, 32x64 warp
// tile), ldmatrix + m16n8k16, 3-stage pipeline (48 KB/stage).
// OM: 0=f32 row-major, 3=combine epilogue, 4=bf16 row-major,
//     5=bf16 transposed (C[n*M+m]), 6=fp16 row-major
// ---------------------------------------------------------------------------
template <int OM, bool HAS_BIAS>
__global__ __launch_bounds__(512)
void bf_gemm(const bf16* __restrict__ A, const bf16* __restrict__ B,
             void* __restrict__ Cout, const float* __restrict__ bias,
             int Mrows, int Nrows, int K, int lda, int ldb,
             long long sA, long long sB, long long sC,
             const float* __restrict__ P, const float* __restrict__ X,
             long long sPX,
             const float* __restrict__ s_alpha, const float* __restrict__ s_beta,
             const float* __restrict__ s_gp, const float* __restrict__ s_gc)
{
    extern __shared__ __align__(128) uint8_t smem[];   // 3 * 48 KB

    const int tid  = threadIdx.x;
    const int lane = tid & 31;
    const int warp = tid >> 5;      // 0..15
    const int mw   = warp >> 2;     // 0..3 (32-row strips)
    const int nw   = warp & 3;      // 0..3 (64-col strips)
    const int z    = blockIdx.z;
    const int m0   = blockIdx.y * 128;
    const int n0   = blockIdx.x * 256;

    A += (long long)z * sA;
    B += (long long)z * sB;

    const uint32_t sbase = smem_u32(smem);
    const int KI = K >> 6;          // K / 64

    // A: 128 rows x 128B = 1024 chunks; B: 256 rows x 128B = 2048 chunks.
    // 3072 chunks over 512 threads = 6 each.
    auto load_tile = [&](int it) {
        const int k0 = it << 6;
        const uint32_t st = sbase + (uint32_t)(it % 3) * 49152;
#pragma unroll
        for (int i = 0; i < 6; ++i) {
            int idx = tid + i * 512;
            if (idx < 1024) {
                int r = idx >> 3, c = idx & 7;
                int grow = m0 + r;
                int ok = (grow < Mrows);
                const bf16* src = A + (long long)(ok ? grow : 0) * lda + k0 + c * 8;
                uint32_t dst = st + r * 128 + ((c ^ (r & 7)) << 4);
                CP_ASYNC16(dst, src, ok ? 16 : 0);
            } else {
                int bi = idx - 1024;
                int r = bi >> 3, c = bi & 7;
                int grow = n0 + r;
                int ok = (grow < Nrows);
                const bf16* src = B + (long long)(ok ? grow : 0) * ldb + k0 + c * 8;
                uint32_t dst = st + 16384 + r * 128 + ((c ^ (r & 7)) << 4);
                CP_ASYNC16(dst, src, ok ? 16 : 0);
            }
        }
    };

    float acc[2][8][4];
#pragma unroll
    for (int i = 0; i < 2; ++i)
#pragma unroll
        for (int j = 0; j < 8; ++j)
#pragma unroll
            for (int r = 0; r < 4; ++r) acc[i][j][r] = 0.f;

    load_tile(0); CP_COMMIT();
    if (KI > 1) { load_tile(1); CP_COMMIT(); }

    const int sub  = lane >> 3;
    const int lrow = lane & 7;

    for (int it = 0; it < KI; ++it) {
        if (it + 1 < KI) CP_WAIT(1); else CP_WAIT(0);
        __syncthreads();
        if (it + 2 < KI) { load_tile(it + 2); CP_COMMIT(); }

        const uint32_t aB = sbase + (uint32_t)(it % 3) * 49152;
        const uint32_t bB = aB + 16384;

#pragma unroll
        for (int ks = 0; ks < 4; ++ks) {        // four k16 steps per BK=64
            uint32_t a[2][4];
#pragma unroll
            for (int mi = 0; mi < 2; ++mi) {
                int row = mw * 32 + mi * 16 + (sub & 1) * 8 + lrow;
                int kc  = ks * 2 + (sub >> 1);
                uint32_t addr = aB + row * 128 + ((kc ^ (row & 7)) << 4);
                LDSM4(a[mi], addr);
            }
            uint32_t b[8][2];
#pragma unroll
            for (int p = 0; p < 4; ++p) {
                int row = nw * 64 + p * 16 + (sub >> 1) * 8 + lrow;
                int kc  = ks * 2 + (sub & 1);
                uint32_t addr = bB + row * 128 + ((kc ^ (row & 7)) << 4);
                uint32_t t[4];
                LDSM4(t, addr);
                b[2 * p][0]     = t[0];
                b[2 * p][1]     = t[1];
                b[2 * p + 1][0] = t[2];
                b[2 * p + 1][1] = t[3];
            }
#pragma unroll
            for (int mi = 0; mi < 2; ++mi)
#pragma unroll
                for (int ni = 0; ni < 8; ++ni)
                    MMA16816(acc[mi][ni], a[mi], b[ni]);
        }
    }

    float c1 = 0.f, c2 = 1.f, c3 = 0.f;
    if (OM == 3) {
        float al = *s_alpha, be = *s_beta;
        c1 = al * (*s_gp);
        c2 = be * (*s_gc);
        c3 = al + be + 1.f;
        P += (long long)z * sPX;
        X += (long long)z * sPX;
    }
    float*  Cf = (float*)Cout + (long long)z * sC;
    bf16*   Cb = (bf16*)Cout + (long long)z * sC;
    __half* Ch = (__half*)Cout + (long long)z * sC;

    const int g  = lane >> 2;
    const int tq = lane & 3;

#pragma unroll
    for (int mi = 0; mi < 2; ++mi) {
#pragma unroll
        for (int half = 0; half < 2; ++half) {
            int m = m0 + mw * 32 + mi * 16 + g + half * 8;
            if (m >= Mrows) continue;
            float bv = HAS_BIAS ? bias[m] : 0.f;
#pragma unroll
            for (int ni = 0; ni < 8; ++ni) {
                int n = n0 + nw * 64 + ni * 8 + tq * 2;
                float v0 = acc[mi][ni][half * 2 + 0] + bv;
                float v1 = acc[mi][ni][half * 2 + 1] + bv;
                if (OM == 5) {
                    if (n < Nrows)     Cb[(long long)n * Mrows + m]       = __float2bfloat16(v0);
                    if (n + 1 < Nrows) Cb[(long long)(n + 1) * Mrows + m] = __float2bfloat16(v1);
                } else if (n + 1 < Nrows) {
                    long long idx = (long long)m * Nrows + n;
                    if (OM == 0) {
                        *(float2*)&Cf[idx] = make_float2(v0, v1);
                    } else if (OM == 3) {
                        Cf[idx]     = c1 * P[idx]     + c2 * v0 + c3 * X[idx];
                        Cf[idx + 1] = c1 * P[idx + 1] + c2 * v1 + c3 * X[idx + 1];
                    } else if (OM == 4) {
                        uint32_t pk = ((uint32_t)__bfloat16_as_ushort(__float2bfloat16(v1)) << 16)
                                    | (uint32_t)__bfloat16_as_ushort(__float2bfloat16(v0));
                        *(uint32_t*)&Cb[idx] = pk;
                    } else { // OM == 6
                        __half2 h = __floats2half2_rn(v0, v1);
                        *(__half2*)&Ch[idx] = h;
                    }
                } else if (n < Nrows) {
                    long long idx = (long long)m * Nrows + n;
                    if (OM == 0)      Cf[idx] = v0;
                    else if (OM == 3) Cf[idx] = c1 * P[idx] + c2 * v0 + c3 * X[idx];
                    else if (OM == 4) Cb[idx] = __float2bfloat16(v0);
                    else              Ch[idx] = __float2half_rn(v0);
                }
            }
        }
    }
}

// ---------------------------------------------------------------------------
// x (b,c,n) fp32 -> tf32 xb (c-major, for gram) and bf16 xbt_b (n-major)
// ---------------------------------------------------------------------------
__global__ __launch_bounds__(256)
void convert_x_k(const float* __restrict__ x, float* __restrict__ xb,
                 bf16* __restrict__ xbt_b)
{
    __shared__ float t[32][33];
    const int z = blockIdx.z;
    const float* xp = x + (size_t)z * CH * NN;
    float* xbp = xb + (size_t)z * CH * NN;
    bf16*  xtb = xbt_b + (size_t)z * NN * CH;
    const int n0 = blockIdx.x * 32, c0 = blockIdx.y * 32;
    const int tx = threadIdx.x, ty = threadIdx.y;
#pragma unroll
    for (int k = 0; k < 4; ++k) {
        int c = ty + k * 8;
        float raw = xp[(size_t)(c0 + c) * NN + n0 + tx];
        t[c][tx] = raw;
        xbp[(size_t)(c0 + c) * NN + n0 + tx] = tf32r(raw);
    }
    __syncthreads();
#pragma unroll
    for (int k = 0; k < 4; ++k) {
        int n = ty + k * 8;
        xtb[(size_t)(n0 + n) * CH + c0 + tx] = __float2bfloat16(t[tx][n]);
    }
}

__global__ __launch_bounds__(256)
void prep_weights_k(const float* __restrict__ wq, const float* __restrict__ wk,
                    const float* __restrict__ bq, const float* __restrict__ bk,
                    const float* __restrict__ wv,
                    bf16* __restrict__ wqk, float* __restrict__ bqk,
                    bf16* __restrict__ wvr)
{
    int i = blockIdx.x * 256 + threadIdx.x;
    if (i < 128 * CH) {
        int row = i >> 9;
        float v = (row < 64) ? wq[i] : wk[i - 64 * CH];
        wqk[i] = __float2bfloat16(v);
    }
    if (i < 128) bqk[i] = (i < 64) ? bq[i] : bk[i - 64];
    if (i < CH * CH) wvr[i] = __float2bfloat16(wv[i]);
}

// ---------------------------------------------------------------------------
// Row softmax: fp16 in, bf16 out IN PLACE (same buffer, same addresses).
// ---------------------------------------------------------------------------
__global__ __launch_bounds__(256)
void softmax_pos(__half* __restrict__ energy)
{
    const long long row = (long long)blockIdx.y * NN + blockIdx.x;
    __half* p = energy + row * NN;
    bf16*  ob = (bf16*)p;
    const int tid = threadIdx.x;
    __shared__ float red[8];

    float v[16];
    float mx = -1e30f;
#pragma unroll
    for (int i = 0; i < 16; ++i) {
        v[i] = __half2float(p[tid + i * 256]);
        mx = fmaxf(mx, v[i]);
    }
#pragma unroll
    for (int o2 = 16; o2; o2 >>= 1) mx = fmaxf(mx, __shfl_xor_sync(~0u, mx, o2));
    if ((tid & 31) == 0) red[tid >> 5] = mx;
    __syncthreads();
    mx = red[0];
#pragma unroll
    for (int i = 1; i < 8; ++i) mx = fmaxf(mx, red[i]);

    float s = 0.f;
#pragma unroll
    for (int i = 0; i < 16; ++i) { v[i] = expf(v[i] - mx); s += v[i]; }
#pragma unroll
    for (int o2 = 16; o2; o2 >>= 1) s += __shfl_xor_sync(~0u, s, o2);
    __syncthreads();
    if ((tid & 31) == 0) red[tid >> 5] = s;
    __syncthreads();
    s = 0.f;
#pragma unroll
    for (int i = 0; i < 8; ++i) s += red[i];
    float inv = 1.f / s;
#pragma unroll
    for (int i = 0; i < 16; ++i) ob[tid + i * 256] = __float2bfloat16(v[i] * inv);
}

// ---------------------------------------------------------------------------
__global__ __launch_bounds__(128)
void softmax_chan(const float* __restrict__ gramp, bf16* __restrict__ attcb)
{
    const int bat = blockIdx.y;
    const int row = blockIdx.x;
    const float* base = gramp + ((size_t)bat * NSPLIT) * CH * CH + (size_t)row * CH;
    bf16* o = attcb + ((size_t)bat * CH + row) * CH;
    const int tid = threadIdx.x;
    __shared__ float red[4];

    float v[4];
    float mn = 1e30f;
#pragma unroll
    for (int i = 0; i < 4; ++i) {
        float s = 0.f;
#pragma unroll
        for (int sp = 0; sp < NSPLIT; ++sp)
            s += base[(size_t)sp * CH * CH + tid + i * 128];
        v[i] = s;
        mn = fminf(mn, s);
    }
#pragma unroll
    for (int o2 = 16; o2; o2 >>= 1) mn = fminf(mn, __shfl_xor_sync(~0u, mn, o2));
    if ((tid & 31) == 0) red[tid >> 5] = mn;
    __syncthreads();
    mn = fminf(fminf(red[0], red[1]), fminf(red[2], red[3]));

    float s = 0.f;
#pragma unroll
    for (int i = 0; i < 4; ++i) { v[i] = expf(mn - v[i]); s += v[i]; }
#pragma unroll
    for (int o2 = 16; o2; o2 >>= 1) s += __shfl_xor_sync(~0u, s, o2);
    __syncthreads();
    if ((tid & 31) == 0) red[tid >> 5] = s;
    __syncthreads();
    s = red[0] + red[1] + red[2] + red[3];
    float inv = 1.f / s;
#pragma unroll
    for (int i = 0; i < 4; ++i) o[tid + i * 128] = __float2bfloat16(v[i] * inv);
}

// ---------------------------------------------------------------------------
extern "C" void kernel_launch(void* const* d_in, const int* in_sizes, int n_in,
                              void* d_out, int out_size)
{
    const float* x  = (const float*)d_in[0];
    const float* wq = (const float*)d_in[1];
    const float* bq = (const float*)d_in[2];
    const float* wk = (const float*)d_in[3];
    const float* bk = (const float*)d_in[4];
    const float* wv = (const float*)d_in[5];
    const float* bv = (const float*)d_in[6];
    const float* gp = (const float*)d_in[7];
    const float* gc = (const float*)d_in[8];
    const float* al = (const float*)d_in[9];
    const float* be = (const float*)d_in[10];
    float* out = (float*)d_out;

    __half* energy;
    float *xb, *pos, *gramp, *bqk;
    bf16 *xbt_b, *vb, *qkt, *attcb, *wqk, *wvr;
    cudaGetSymbolAddress((void**)&energy, g_energy);
    cudaGetSymbolAddress((void**)&xb,    g_xb);
    cudaGetSymbolAddress((void**)&xbt_b, g_xbt_b);
    cudaGetSymbolAddress((void**)&vb,    g_vb);
    cudaGetSymbolAddress((void**)&qkt,   g_qkt);
    cudaGetSymbolAddress((void**)&pos,   g_pos);
    cudaGetSymbolAddress((void**)&gramp, g_gramp);
    cudaGetSymbolAddress((void**)&attcb, g_attcb);
    cudaGetSymbolAddress((void**)&wqk,   g_wqk);
    cudaGetSymbolAddress((void**)&bqk,   g_bqk);
    cudaGetSymbolAddress((void**)&wvr,   g_wvr);

    const long long sX   = (long long)CH * NN;
    const long long sXT  = (long long)NN * CH;
    const long long sQK  = (long long)NN * 128;
    const long long sAtt = (long long)NN * NN;
    const long long sGr  = (long long)CH * CH;

    const int SMEM_T = 3 * 49152;
    const int SMEM_B = 3 * 49152;   // bf16 kernel now BK=64: 48 KB/stage

    static bool init_done = false;
    static cudaStream_t sA, sB;
    static cudaEvent_t evFork, evV, evA, evB;
    if (!init_done) {
        cudaFuncSetAttribute(tf_gemm, cudaFuncAttributeMaxDynamicSharedMemorySize, SMEM_T);
        cudaFuncSetAttribute(bf_gemm<5, true>,  cudaFuncAttributeMaxDynamicSharedMemorySize, SMEM_B);
        cudaFuncSetAttribute(bf_gemm<4, true>,  cudaFuncAttributeMaxDynamicSharedMemorySize, SMEM_B);
        cudaFuncSetAttribute(bf_gemm<6, false>, cudaFuncAttributeMaxDynamicSharedMemorySize, SMEM_B);
        cudaFuncSetAttribute(bf_gemm<0, false>, cudaFuncAttributeMaxDynamicSharedMemorySize, SMEM_B);
        cudaFuncSetAttribute(bf_gemm<3, false>, cudaFuncAttributeMaxDynamicSharedMemorySize, SMEM_B);
        cudaStreamCreateWithFlags(&sA, cudaStreamNonBlocking);
        cudaStreamCreateWithFlags(&sB, cudaStreamNonBlocking);
        cudaEventCreateWithFlags(&evFork, cudaEventDisableTiming);
        cudaEventCreateWithFlags(&evV,    cudaEventDisableTiming);
        cudaEventCreateWithFlags(&evA,    cudaEventDisableTiming);
        cudaEventCreateWithFlags(&evB,    cudaEventDisableTiming);
        init_done = true;
    }

    // ---- prologue on the default (capture) stream ----
    convert_x_k<<<dim3(NN / 32, CH / 32, BDIM), dim3(32, 8)>>>(x, xb, xbt_b);
    prep_weights_k<<<(CH * CH + 255) / 256, 256>>>(wq, wk, bq, bk, wv, wqk, bqk, wvr);

    // ---- fork ----
    cudaEventRecord(evFork, 0);
    cudaStreamWaitEvent(sA, evFork, 0);
    cudaStreamWaitEvent(sB, evFork, 0);

    // chain A (stream sA): qk-proj -> energy -> softmax_pos
    bf_gemm<5, true><<<dim3(NN / 256, 1, BDIM), 512, SMEM_B, sA>>>(
        wqk, xbt_b, qkt, bqk, 128, NN, CH, CH, CH, 0, sXT, sQK,
        nullptr, nullptr, 0, nullptr, nullptr, nullptr, nullptr);
    bf_gemm<6, false><<<dim3(NN / 256, NN / 128, BDIM), 512, SMEM_B, sA>>>(
        qkt, qkt + 64, energy, nullptr, NN, NN, CQ, 128, 128, sQK, sQK, sAtt,
        nullptr, nullptr, 0, nullptr, nullptr, nullptr, nullptr);
    softmax_pos<<<dim3(NN, BDIM), 256, 0, sA>>>(energy);

    // chain B (stream sB): v-proj -> gram -> softmax_chan
    bf_gemm<4, true><<<dim3(NN / 256, CH / 128, BDIM), 512, SMEM_B, sB>>>(
        wvr, xbt_b, vb, bv, CH, NN, CH, CH, CH, 0, sXT, sX,
        nullptr, nullptr, 0, nullptr, nullptr, nullptr, nullptr);
    cudaEventRecord(evV, sB);
    tf_gemm<<<dim3(CH / 256, CH / 128, BDIM * NSPLIT), 256, SMEM_T, sB>>>(
        xb, xb, gramp, CH, CH, NN / NSPLIT, NN, NN, NSPLIT, sX, sX, sGr);
    softmax_chan<<<dim3(CH, BDIM), 128, 0, sB>>>(gramp, attcb);

    // pos needs chain A's att AND chain B's v
    cudaStreamWaitEvent(sA, evV, 0);
    bf_gemm<0, false><<<dim3(NN / 256, CH / 128, BDIM), 512, SMEM_B, sA>>>(
        vb, (const bf16*)energy, pos, nullptr, CH, NN, NN, NN, NN, sX, sAtt, sX,
        nullptr, nullptr, 0, nullptr, nullptr, nullptr, nullptr);

    // ---- join back to the default stream ----
    cudaEventRecord(evA, sA);
    cudaEventRecord(evB, sB);
    cudaStreamWaitEvent(0, evA, 0);
    cudaStreamWaitEvent(0, evB, 0);

    // combine on default stream
    bf_gemm<3, false><<<dim3(NN / 256, CH / 128, BDIM), 512, SMEM_B>>>(
        attcb, xbt_b, out, nullptr, CH, NN, CH, CH, CH, sGr, sXT, sX,
        pos, x, sX, al, be, gp, gc);
}